// round 9
// baseline (speedup 1.0000x reference)
#include <cuda_runtime.h>
#include <cuda_bf16.h>
#include <math.h>
#include <stdint.h>

#define N_BATCH 4
#define LQ      5448
#define LSP     5440
#define DMODEL  256
#define DFFN    1024
#define NVT     8
#define NALLVT  600
#define TTOK    (N_BATCH * LQ)   // 21792

// -------------------- scratch (planar dual-bf16: hi plane then lo plane) --------------------
__device__ uint32_t g_q_pk   [(size_t)TTOK * DMODEL];
__device__ float    g_vin    [(size_t)TTOK * DMODEL];
__device__ uint32_t g_vin_pk [(size_t)TTOK * DMODEL];
__device__ float    g_value  [(size_t)TTOK * DMODEL];
__device__ float    g_off    [(size_t)TTOK * DMODEL];
__device__ float    g_attn   [(size_t)TTOK * 128];
__device__ uint32_t g_samp_pk[(size_t)TTOK * DMODEL];
__device__ float    g_src2   [(size_t)TTOK * DMODEL];
__device__ float    g_x      [(size_t)TTOK * DMODEL];
__device__ uint32_t g_x_pk   [(size_t)TTOK * DMODEL];
__device__ uint32_t g_h_pk   [(size_t)TTOK * DFFN];
__device__ float    g_y      [(size_t)TTOK * DMODEL];
// packed weights (planar)
__device__ uint32_t g_Wv_pk [256 * 256];
__device__ uint32_t g_Woa_pk[384 * 256];
__device__ uint32_t g_Wp_pk [256 * 256];
__device__ uint32_t g_W1_pk [1024 * 256];
__device__ uint32_t g_W2_pk [256 * 1024];
__device__ float    g_bias_oa[384];

// ==================== helpers ====================
__device__ __forceinline__ uint32_t smem_u32(const void* p) {
    return (uint32_t)__cvta_generic_to_shared(p);
}
__device__ __forceinline__ void cp_async16(uint32_t dst, const void* src, int src_size) {
    asm volatile("cp.async.cg.shared.global [%0], [%1], 16, %2;\n"
                 :: "r"(dst), "l"(src), "r"(src_size));
}
__device__ __forceinline__ void cp_async_commit() {
    asm volatile("cp.async.commit_group;" ::: "memory");
}
template<int N> __device__ __forceinline__ void cp_async_wait() {
    asm volatile("cp.async.wait_group %0;" :: "n"(N) : "memory");
}
__device__ __forceinline__ void ldm_x4(uint32_t addr, uint32_t& r0, uint32_t& r1,
                                       uint32_t& r2, uint32_t& r3) {
    asm volatile("ldmatrix.sync.aligned.m8n8.x4.shared.b16 {%0,%1,%2,%3}, [%4];"
                 : "=r"(r0), "=r"(r1), "=r"(r2), "=r"(r3) : "r"(addr));
}
__device__ __forceinline__ void mma16(float* d, const uint32_t* a, const uint32_t* b) {
    asm volatile(
        "mma.sync.aligned.m16n8k16.row.col.f32.bf16.bf16.f32 "
        "{%0,%1,%2,%3}, {%4,%5,%6,%7}, {%8,%9}, {%0,%1,%2,%3};"
        : "+f"(d[0]), "+f"(d[1]), "+f"(d[2]), "+f"(d[3])
        : "r"(a[0]), "r"(a[1]), "r"(a[2]), "r"(a[3]), "r"(b[0]), "r"(b[1]));
}
// split two adjacent fp32 into (hi word, lo word), each word = 2 bf16
__device__ __forceinline__ void split2(float vx, float vy, uint32_t& hw, uint32_t& lw) {
    __nv_bfloat16 hx = __float2bfloat16(vx);
    __nv_bfloat16 lx = __float2bfloat16(vx - __bfloat162float(hx));
    __nv_bfloat16 hy = __float2bfloat16(vy);
    __nv_bfloat16 ly = __float2bfloat16(vy - __bfloat162float(hy));
    hw = (uint32_t)__bfloat16_as_ushort(hx) | ((uint32_t)__bfloat16_as_ushort(hy) << 16);
    lw = (uint32_t)__bfloat16_as_ushort(lx) | ((uint32_t)__bfloat16_as_ushort(ly) << 16);
}

// ==================== planar dual-bf16 GEMM via ldmatrix ====================
// out[T,Nout] = A[T,K] * W[Nout,K]^T + bias. KW = K/2 (words per row per plane).
// CTA 128x64, BK = 32 halves (16 words), 8 warps (4M x 2N), warp tile 32x32.
#define BM 128
#define BN 64
#define STR 20              // words per smem row (16 + 4 pad)
#define APL 2560            // A plane words (128*20)
#define BPL 1280            // B plane words (64*20)
#define BUFW 7680           // words per buffer (2*APL + 2*BPL)
#define SMEM_BYTES (2 * BUFW * 4)

__global__ void __launch_bounds__(256, 2)
gemm_pl(const uint32_t* __restrict__ A, size_t psA,
        const uint32_t* __restrict__ Wt, size_t psW,
        const float* __restrict__ bias, int T, int KW, int Nout,
        float* __restrict__ outA, int split, float* __restrict__ outB,
        uint32_t* __restrict__ outPk, size_t psOut,
        int relu, const unsigned char* __restrict__ mask)
{
    extern __shared__ __align__(16) uint32_t smem[];
    const uint32_t sm = smem_u32(smem);

    const int tid  = threadIdx.x;
    const int wid  = tid >> 5;
    const int lane = tid & 31;
    const int bm = blockIdx.x * BM;
    const int bn = blockIdx.y * BN;
    const int mbase = (wid & 3) * 32;
    const int nbase = (wid >> 2) * 32;
    const int gq = lane >> 2;
    const int tg = lane & 3;

    float acc[2][4][4];
#pragma unroll
    for (int mi = 0; mi < 2; mi++)
#pragma unroll
        for (int ni = 0; ni < 4; ni++)
#pragma unroll
            for (int r = 0; r < 4; r++) acc[mi][ni][r] = 0.f;

    auto load = [&](int kw0, int buf) {
        const uint32_t base = sm + buf * (BUFW * 4);
#pragma unroll
        for (int j = 0; j < 4; j++) {              // A: 2 planes x 128 rows x 4 chunks
            int o = tid + 256 * j;
            int plane = o >> 9;
            int oo = o & 511;
            int row = oo >> 2;
            int ch = oo & 3;
            int gr = bm + row;
            const uint32_t* srcp = A + (size_t)plane * psA
                                     + (size_t)(gr < T ? gr : 0) * KW + kw0 + ch * 4;
            cp_async16(base + (plane * APL + row * STR + ch * 4) * 4, srcp, gr < T ? 16 : 0);
        }
#pragma unroll
        for (int j = 0; j < 2; j++) {              // B: 2 planes x 64 rows x 4 chunks
            int o = tid + 256 * j;
            int plane = o >> 8;
            int oo = o & 255;
            int row = oo >> 2;
            int ch = oo & 3;
            const uint32_t* srcp = Wt + (size_t)plane * psW
                                      + (size_t)(bn + row) * KW + kw0 + ch * 4;
            cp_async16(base + (2 * APL + plane * BPL + row * STR + ch * 4) * 4, srcp, 16);
        }
        cp_async_commit();
    };

    const int nch = KW >> 4;
    load(0, 0);

    // ldmatrix per-lane address components
    const int arow = lane & 15;
    const int acol = (lane >> 4) * 4;                          // words
    const int brow = (lane & 7) + ((lane >> 4) & 1) * 8;
    const int bcol = ((lane >> 3) & 1) * 4;                    // words

    for (int i = 0; i < nch; i++) {
        cp_async_wait<0>();
        __syncthreads();
        if (i + 1 < nch) load((i + 1) << 4, (i + 1) & 1);

        const uint32_t base = sm + (i & 1) * (BUFW * 4);
        const uint32_t Ahi = base, Alo = base + APL * 4;
        const uint32_t Bhi = base + 2 * APL * 4, Blo = Bhi + BPL * 4;

#pragma unroll
        for (int k16 = 0; k16 < 2; k16++) {
            const int kw = k16 * 8;
            uint32_t ah[2][4], al[2][4];
#pragma unroll
            for (int mi = 0; mi < 2; mi++) {
                uint32_t off = ((mbase + mi * 16 + arow) * STR + kw + acol) * 4;
                ldm_x4(Ahi + off, ah[mi][0], ah[mi][1], ah[mi][2], ah[mi][3]);
                ldm_x4(Alo + off, al[mi][0], al[mi][1], al[mi][2], al[mi][3]);
            }
            uint32_t bh[4][2], bl[4][2];
#pragma unroll
            for (int hb = 0; hb < 2; hb++) {
                uint32_t off = ((nbase + hb * 16 + brow) * STR + kw + bcol) * 4;
                ldm_x4(Bhi + off, bh[hb*2][0], bh[hb*2][1], bh[hb*2+1][0], bh[hb*2+1][1]);
                ldm_x4(Blo + off, bl[hb*2][0], bl[hb*2][1], bl[hb*2+1][0], bl[hb*2+1][1]);
            }
            // term-outer ordering: 8 independent accumulators between reuses of
            // the same acc registers -> tensor pipe streams instead of stalling
            // on its own accumulator latency.
#pragma unroll
            for (int mi = 0; mi < 2; mi++)
#pragma unroll
                for (int ng = 0; ng < 4; ng++)
                    mma16(acc[mi][ng], ah[mi], bh[ng]);   // hi*hi
#pragma unroll
            for (int mi = 0; mi < 2; mi++)
#pragma unroll
                for (int ng = 0; ng < 4; ng++)
                    mma16(acc[mi][ng], ah[mi], bl[ng]);   // hi*lo
#pragma unroll
            for (int mi = 0; mi < 2; mi++)
#pragma unroll
                for (int ng = 0; ng < 4; ng++)
                    mma16(acc[mi][ng], al[mi], bh[ng]);   // lo*hi
        }
        __syncthreads();
    }

    // ---- epilogue ----
    const int wB = Nout - split;
    const int KWout = Nout >> 1;
#pragma unroll
    for (int mi = 0; mi < 2; mi++) {
#pragma unroll
        for (int half = 0; half < 2; half++) {
            int row = bm + mbase + mi * 16 + gq + half * 8;
            if (row >= T) continue;
            bool zero = (mask != nullptr) && (mask[row] != 0);
#pragma unroll
            for (int ni = 0; ni < 4; ni++) {
                int gc = bn + nbase + ni * 8 + tg * 2;
                float vx = acc[mi][ni][half * 2 + 0] + bias[gc];
                float vy = acc[mi][ni][half * 2 + 1] + bias[gc + 1];
                if (relu) { vx = fmaxf(vx, 0.f); vy = fmaxf(vy, 0.f); }
                if (zero) { vx = 0.f; vy = 0.f; }
                if (outPk) {
                    uint32_t hw, lw;
                    split2(vx, vy, hw, lw);
                    size_t wi = (size_t)row * KWout + (gc >> 1);
                    outPk[wi] = hw;
                    outPk[wi + psOut] = lw;
                }
                if (outA) {
                    if (gc < split) {
                        float2 v; v.x = vx; v.y = vy;
                        *reinterpret_cast<float2*>(outA + (size_t)row * split + gc) = v;
                    } else if (outB) {
                        float2 v; v.x = vx; v.y = vy;
                        *reinterpret_cast<float2*>(outB + (size_t)row * wB + (gc - split)) = v;
                    }
                }
            }
        }
    }
}

// -------------------- weight packing (planar) --------------------
#define WV_W  32768
#define WO_W  32768
#define WA_W  16384
#define WP_W  32768
#define W1_W  131072
#define W2_W  131072
#define TOT_W (WV_W + WO_W + WA_W + WP_W + W1_W + W2_W)   // 376832

__global__ void pack_weights(const float* __restrict__ Wv, const float* __restrict__ Wo,
                             const float* __restrict__ Wa, const float* __restrict__ Wp,
                             const float* __restrict__ W1, const float* __restrict__ W2,
                             const float* __restrict__ bo, const float* __restrict__ ba)
{
    int i = blockIdx.x * 256 + threadIdx.x;
    if (i < TOT_W) {
        const float* srcm; uint32_t* dst; int w; size_t ps;
        if (i < WV_W)                      { srcm = Wv; dst = g_Wv_pk;  w = i; ps = WV_W; }
        else if (i < WV_W + WO_W)          { srcm = Wo; dst = g_Woa_pk; w = i - WV_W; ps = WO_W + WA_W; }
        else if (i < WV_W + WO_W + WA_W)   { srcm = Wa; dst = g_Woa_pk + WO_W; w = i - WV_W - WO_W; ps = WO_W + WA_W; }
        else if (i < WV_W + WO_W + WA_W + WP_W)
                                           { srcm = Wp; dst = g_Wp_pk;  w = i - WV_W - WO_W - WA_W; ps = WP_W; }
        else if (i < TOT_W - W2_W)         { srcm = W1; dst = g_W1_pk;  w = i - (WV_W+WO_W+WA_W+WP_W); ps = W1_W; }
        else                               { srcm = W2; dst = g_W2_pk;  w = i - (TOT_W - W2_W); ps = W2_W; }
        float2 v = *reinterpret_cast<const float2*>(srcm + 2 * (size_t)w);
        uint32_t hw, lw;
        split2(v.x, v.y, hw, lw);
        dst[w] = hw;
        dst[w + ps] = lw;
    } else if (i < TOT_W + 256) {
        g_bias_oa[i - TOT_W] = bo[i - TOT_W];
    } else if (i < TOT_W + 384) {
        g_bias_oa[i - TOT_W] = ba[i - TOT_W - 256];
    }
}

// -------------------- build q / v_in (fp32 + planar packed) --------------------
__global__ void build_qv_kernel(const float* __restrict__ src, const float* __restrict__ pos,
                                const float* __restrict__ sel,
                                uint32_t* __restrict__ q_pk,
                                float* __restrict__ vin, uint32_t* __restrict__ vin_pk)
{
    size_t gid = (size_t)blockIdx.x * 256 + threadIdx.x;
    if (gid >= (size_t)TTOK * 128) return;
    int dw = (int)(gid & 127);
    size_t t = gid >> 7;
    int n = (int)(t / LQ);
    int i = (int)(t % LQ);
    float2 sv, pv;
    if (i < LSP) {
        size_t si = ((size_t)n * LSP + i) * DMODEL + dw * 2;
        sv = *reinterpret_cast<const float2*>(src + si);
        pv = *reinterpret_cast<const float2*>(pos + si);
    } else {
        size_t si = ((size_t)n * NVT + (i - LSP)) * DMODEL + dw * 2;
        sv = *reinterpret_cast<const float2*>(sel + si);
        pv.x = 0.f; pv.y = 0.f;
    }
    float qx = sv.x + pv.x, qy = sv.y + pv.y;
    const size_t PS = (size_t)TTOK * 128;
    uint32_t hw, lw;
    split2(qx, qy, hw, lw);
    q_pk[gid] = hw; q_pk[gid + PS] = lw;
    split2(sv.x, sv.y, hw, lw);
    vin_pk[gid] = hw; vin_pk[gid + PS] = lw;
    *reinterpret_cast<float2*>(vin + 2 * gid) = sv;
}

// -------------------- deformable sampling: warp per (token, head) --------------------
__global__ void msdeform_sample_kernel(const float* __restrict__ value,
                                       const float* __restrict__ logits,
                                       const float* __restrict__ off,
                                       const float* __restrict__ ref,
                                       uint32_t* __restrict__ out_pk)
{
    const int nq   = blockIdx.x;
    const int n    = nq / LQ;
    const int m    = threadIdx.x >> 5;
    const int lane = threadIdx.x & 31;

    const float* lg = logits + (size_t)nq * 128 + m * 16;
    float v = (lane < 16) ? lg[lane] : -1e30f;
    float mx = v;
#pragma unroll
    for (int o = 16; o > 0; o >>= 1) mx = fmaxf(mx, __shfl_xor_sync(0xffffffffu, mx, o));
    float e = (lane < 16) ? __expf(v - mx) : 0.f;
    float sm = e;
#pragma unroll
    for (int o = 16; o > 0; o >>= 1) sm += __shfl_xor_sync(0xffffffffu, sm, o);
    float wgt = e / sm;

    float offv = off[(size_t)nq * DMODEL + m * 32 + lane];
    float refv = (lane < 8) ? ref[(size_t)nq * 8 + lane] : 0.f;

    const float* vb = value + (size_t)n * LQ * DMODEL + m * 32 + lane;

    const int HH[4] = {64, 32, 16, 8};
    const int WW[4] = {64, 32, 16, 8};
    const int ST[4] = {0, 4096, 5120, 5376};

    float acc = 0.f;
#pragma unroll
    for (int s = 0; s < 16; s++) {
        const int l = s >> 2;
        float dx = __shfl_sync(0xffffffffu, offv, 2 * s);
        float dy = __shfl_sync(0xffffffffu, offv, 2 * s + 1);
        float rx = __shfl_sync(0xffffffffu, refv, 2 * l);
        float ry = __shfl_sync(0xffffffffu, refv, 2 * l + 1);
        float ws = __shfl_sync(0xffffffffu, wgt, s);
        const int H = HH[l], W = WW[l], st = ST[l];

        float x = rx * (float)W + dx - 0.5f;
        float y = ry * (float)H + dy - 0.5f;
        float xf = floorf(x), yf = floorf(y);
        int x0 = (int)xf, y0 = (int)yf;
        float wx = x - xf, wy = y - yf;

        float w00 = (1.f - wx) * (1.f - wy);
        float w10 = wx * (1.f - wy);
        float w01 = (1.f - wx) * wy;
        float w11 = wx * wy;

        float samp = 0.f;
        if (x0 >= 0 && x0 < W && y0 >= 0 && y0 < H)
            samp += w00 * vb[(size_t)(st + y0 * W + x0) * DMODEL];
        if (x0 + 1 >= 0 && x0 + 1 < W && y0 >= 0 && y0 < H)
            samp += w10 * vb[(size_t)(st + y0 * W + x0 + 1) * DMODEL];
        if (x0 >= 0 && x0 < W && y0 + 1 >= 0 && y0 + 1 < H)
            samp += w01 * vb[(size_t)(st + (y0 + 1) * W + x0) * DMODEL];
        if (x0 + 1 >= 0 && x0 + 1 < W && y0 + 1 >= 0 && y0 + 1 < H)
            samp += w11 * vb[(size_t)(st + (y0 + 1) * W + x0 + 1) * DMODEL];

        acc += ws * samp;
    }
    float accn = __shfl_down_sync(0xffffffffu, acc, 1);
    if ((lane & 1) == 0) {
        uint32_t hw, lw;
        split2(acc, accn, hw, lw);
        size_t wi = (size_t)nq * 128 + ((m * 32 + lane) >> 1);
        out_pk[wi] = hw;
        out_pk[wi + (size_t)TTOK * 128] = lw;
    }
}

// -------------------- add + LayerNorm --------------------
__global__ void add_ln_kernel(const float* __restrict__ a, const float* __restrict__ b,
                              const float* __restrict__ g, const float* __restrict__ beta,
                              float* __restrict__ out, uint32_t* __restrict__ out_pk, int scatter)
{
    const int t = blockIdx.x;
    const int d = threadIdx.x;
    const int lane = d & 31, wid = d >> 5;

    float v = a[(size_t)t * DMODEL + d] + b[(size_t)t * DMODEL + d];

    __shared__ float red[8];
    float s = v;
#pragma unroll
    for (int o = 16; o > 0; o >>= 1) s += __shfl_xor_sync(0xffffffffu, s, o);
    if (lane == 0) red[wid] = s;
    __syncthreads();
    float mean;
    {
        if (d == 0) {
            float tot = 0.f;
#pragma unroll
            for (int i = 0; i < 8; i++) tot += red[i];
            red[0] = tot;
        }
        __syncthreads();
        mean = red[0] * (1.f / 256.f);
    }
    __syncthreads();

    float xc = v - mean;
    s = xc * xc;
#pragma unroll
    for (int o = 16; o > 0; o >>= 1) s += __shfl_xor_sync(0xffffffffu, s, o);
    if (lane == 0) red[wid] = s;
    __syncthreads();
    float var;
    {
        if (d == 0) {
            float tot = 0.f;
#pragma unroll
            for (int i = 0; i < 8; i++) tot += red[i];
            red[0] = tot;
        }
        __syncthreads();
        var = red[0] * (1.f / 256.f);
    }

    float r = g[d] * xc * rsqrtf(var + 1e-5f) + beta[d];

    if (out_pk) {
        float rn = __shfl_down_sync(0xffffffffu, r, 1);
        if ((d & 1) == 0) {
            uint32_t hw, lw;
            split2(r, rn, hw, lw);
            size_t wi = (size_t)t * 128 + (d >> 1);
            out_pk[wi] = hw;
            out_pk[wi + (size_t)TTOK * 128] = lw;
        }
    }

    float* dst;
    if (!scatter) {
        dst = out + (size_t)t * DMODEL;
    } else {
        int n = t / LQ, i = t % LQ;
        if (i < LSP)
            dst = out + ((size_t)n * LSP + i) * DMODEL;
        else
            dst = out + ((size_t)N_BATCH * LSP + (size_t)N_BATCH * NALLVT) * DMODEL
                      + ((size_t)n * NVT + (i - LSP)) * DMODEL;
    }
    dst[d] = r;
}

// -------------------- launch --------------------
extern "C" void kernel_launch(void* const* d_in, const int* in_sizes, int n_in,
                              void* d_out, int out_size)
{
    const float* src  = (const float*)d_in[0];
    const float* pos  = (const float*)d_in[1];
    const float* ref  = (const float*)d_in[2];
    const unsigned char* mask = (const unsigned char*)d_in[5];
    const float* all_vt = (const float*)d_in[6];
    const float* sel_vt = (const float*)d_in[7];
    const float* Wv = (const float*)d_in[8];   const float* bv  = (const float*)d_in[9];
    const float* Wo = (const float*)d_in[10];  const float* bo  = (const float*)d_in[11];
    const float* Wa = (const float*)d_in[12];  const float* ba  = (const float*)d_in[13];
    const float* Wp = (const float*)d_in[14];  const float* bp  = (const float*)d_in[15];
    const float* g1 = (const float*)d_in[16];  const float* be1 = (const float*)d_in[17];
    const float* W1 = (const float*)d_in[18];  const float* bf1 = (const float*)d_in[19];
    const float* W2 = (const float*)d_in[20];  const float* bf2 = (const float*)d_in[21];
    const float* g2 = (const float*)d_in[22];  const float* be2 = (const float*)d_in[23];
    float* out = (float*)d_out;

    uint32_t *q_pk, *vin_pk, *samp_pk, *x_pk, *h_pk;
    uint32_t *Wv_pk, *Woa_pk, *Wp_pk, *W1_pk, *W2_pk;
    float *vin, *value, *off, *attn, *src2, *x, *y, *bias_oa;
    cudaGetSymbolAddress((void**)&q_pk,   g_q_pk);
    cudaGetSymbolAddress((void**)&vin,    g_vin);
    cudaGetSymbolAddress((void**)&vin_pk, g_vin_pk);
    cudaGetSymbolAddress((void**)&value,  g_value);
    cudaGetSymbolAddress((void**)&off,    g_off);
    cudaGetSymbolAddress((void**)&attn,   g_attn);
    cudaGetSymbolAddress((void**)&samp_pk,g_samp_pk);
    cudaGetSymbolAddress((void**)&src2,   g_src2);
    cudaGetSymbolAddress((void**)&x,      g_x);
    cudaGetSymbolAddress((void**)&x_pk,   g_x_pk);
    cudaGetSymbolAddress((void**)&h_pk,   g_h_pk);
    cudaGetSymbolAddress((void**)&y,      g_y);
    cudaGetSymbolAddress((void**)&Wv_pk,  g_Wv_pk);
    cudaGetSymbolAddress((void**)&Woa_pk, g_Woa_pk);
    cudaGetSymbolAddress((void**)&Wp_pk,  g_Wp_pk);
    cudaGetSymbolAddress((void**)&W1_pk,  g_W1_pk);
    cudaGetSymbolAddress((void**)&W2_pk,  g_W2_pk);
    cudaGetSymbolAddress((void**)&bias_oa,g_bias_oa);

    cudaFuncSetAttribute(gemm_pl, cudaFuncAttributeMaxDynamicSharedMemorySize, SMEM_BYTES);

    const int T = TTOK;
    const int TM = (T + BM - 1) / BM;   // 171
    const size_t psAct = (size_t)TTOK * 128;
    const size_t psH   = (size_t)TTOK * 512;

    // 0) pack weights (+ concat bias_oa)
    pack_weights<<<(TOT_W + 384 + 255) / 256, 256>>>(Wv, Wo, Wa, Wp, W1, W2, bo, ba);

    // 1) build q / v_in
    build_qv_kernel<<<(TTOK * 128 + 255) / 256, 256>>>(src, pos, sel_vt, q_pk, vin, vin_pk);

    // 2) value = vin @ Wv^T + bv (masked)
    gemm_pl<<<dim3(TM, 4), 256, SMEM_BYTES>>>(vin_pk, psAct, Wv_pk, WV_W, bv, T, 128, 256,
                                              value, 256, nullptr, nullptr, 0, 0, mask);
    // 3) [off | attn] = q @ [Wo;Wa]^T + [bo;ba]
    gemm_pl<<<dim3(TM, 6), 256, SMEM_BYTES>>>(q_pk, psAct, Woa_pk, WO_W + WA_W, bias_oa, T, 128, 384,
                                              off, 256, attn, nullptr, 0, 0, nullptr);

    // 4) deformable sampling (softmax fused) -> planar packed samp
    msdeform_sample_kernel<<<TTOK, 256>>>(value, attn, off, ref, samp_pk);

    // 5) src2 = samp @ Wp^T + bp
    gemm_pl<<<dim3(TM, 4), 256, SMEM_BYTES>>>(samp_pk, psAct, Wp_pk, WP_W, bp, T, 128, 256,
                                              src2, 256, nullptr, nullptr, 0, 0, nullptr);

    // 6) x = LN(vin + src2), also planar packed
    add_ln_kernel<<<TTOK, 256>>>(vin, src2, g1, be1, x, x_pk, 0);

    // 7) h = relu(x @ W1^T + bf1) -> planar packed only
    gemm_pl<<<dim3(TM, 16), 256, SMEM_BYTES>>>(x_pk, psAct, W1_pk, W1_W, bf1, T, 128, 1024,
                                               nullptr, 1024, nullptr, h_pk, psH, 1, nullptr);
    // 8) y = h @ W2^T + bf2
    gemm_pl<<<dim3(TM, 4), 256, SMEM_BYTES>>>(h_pk, psH, W2_pk, W2_W, bf2, T, 512, 256,
                                              y, 256, nullptr, nullptr, 0, 0, nullptr);

    // 9) out = LN(x + y) scattered into [spatial | all_vt | vt] layout
    add_ln_kernel<<<TTOK, 256>>>(x, y, g2, be2, out, nullptr, 1);

    // 10) all_vt passthrough
    cudaMemcpyAsync(out + (size_t)N_BATCH * LSP * DMODEL, all_vt,
                    (size_t)N_BATCH * NALLVT * DMODEL * sizeof(float),
                    cudaMemcpyDeviceToDevice, 0);
}

// round 10
// speedup vs baseline: 1.4724x; 1.4724x over previous
#include <cuda_runtime.h>
#include <cuda_bf16.h>
#include <math.h>
#include <stdint.h>

#define N_BATCH 4
#define LQ      5448
#define LSP     5440
#define DMODEL  256
#define DFFN    1024
#define NVT     8
#define NALLVT  600
#define TTOK    (N_BATCH * LQ)   // 21792

// -------------------- scratch (planar dual-bf16: hi plane then lo plane) --------------------
__device__ uint32_t g_q_pk   [(size_t)TTOK * DMODEL];
__device__ float    g_vin    [(size_t)TTOK * DMODEL];
__device__ uint32_t g_vin_pk [(size_t)TTOK * DMODEL];
__device__ float    g_value  [(size_t)TTOK * DMODEL];
__device__ float    g_off    [(size_t)TTOK * DMODEL];
__device__ float    g_attn   [(size_t)TTOK * 128];
__device__ uint32_t g_samp_pk[(size_t)TTOK * DMODEL];
__device__ float    g_src2   [(size_t)TTOK * DMODEL];
__device__ float    g_x      [(size_t)TTOK * DMODEL];
__device__ uint32_t g_x_pk   [(size_t)TTOK * DMODEL];
__device__ uint32_t g_h_pk   [(size_t)TTOK * DFFN];
__device__ float    g_y      [(size_t)TTOK * DMODEL];
// packed weights (planar)
__device__ uint32_t g_Wv_pk [256 * 256];
__device__ uint32_t g_Woa_pk[384 * 256];
__device__ uint32_t g_Wp_pk [256 * 256];
__device__ uint32_t g_W1_pk [1024 * 256];
__device__ uint32_t g_W2_pk [256 * 1024];
__device__ float    g_bias_oa[384];

// ==================== helpers ====================
__device__ __forceinline__ uint32_t smem_u32(const void* p) {
    return (uint32_t)__cvta_generic_to_shared(p);
}
__device__ __forceinline__ void cp_async16(uint32_t dst, const void* src, int src_size) {
    asm volatile("cp.async.cg.shared.global [%0], [%1], 16, %2;\n"
                 :: "r"(dst), "l"(src), "r"(src_size));
}
__device__ __forceinline__ void cp_async_commit() {
    asm volatile("cp.async.commit_group;" ::: "memory");
}
template<int N> __device__ __forceinline__ void cp_async_wait() {
    asm volatile("cp.async.wait_group %0;" :: "n"(N) : "memory");
}
__device__ __forceinline__ void ldm_x4(uint32_t addr, uint32_t& r0, uint32_t& r1,
                                       uint32_t& r2, uint32_t& r3) {
    asm volatile("ldmatrix.sync.aligned.m8n8.x4.shared.b16 {%0,%1,%2,%3}, [%4];"
                 : "=r"(r0), "=r"(r1), "=r"(r2), "=r"(r3) : "r"(addr));
}
__device__ __forceinline__ void mma16(float* d, const uint32_t* a, const uint32_t* b) {
    asm volatile(
        "mma.sync.aligned.m16n8k16.row.col.f32.bf16.bf16.f32 "
        "{%0,%1,%2,%3}, {%4,%5,%6,%7}, {%8,%9}, {%0,%1,%2,%3};"
        : "+f"(d[0]), "+f"(d[1]), "+f"(d[2]), "+f"(d[3])
        : "r"(a[0]), "r"(a[1]), "r"(a[2]), "r"(a[3]), "r"(b[0]), "r"(b[1]));
}
// split two adjacent fp32 into (hi word, lo word), each word = 2 bf16
__device__ __forceinline__ void split2(float vx, float vy, uint32_t& hw, uint32_t& lw) {
    __nv_bfloat16 hx = __float2bfloat16(vx);
    __nv_bfloat16 lx = __float2bfloat16(vx - __bfloat162float(hx));
    __nv_bfloat16 hy = __float2bfloat16(vy);
    __nv_bfloat16 ly = __float2bfloat16(vy - __bfloat162float(hy));
    hw = (uint32_t)__bfloat16_as_ushort(hx) | ((uint32_t)__bfloat16_as_ushort(hy) << 16);
    lw = (uint32_t)__bfloat16_as_ushort(lx) | ((uint32_t)__bfloat16_as_ushort(ly) << 16);
}

// ==================== planar dual-bf16 GEMM via ldmatrix ====================
// out[T,Nout] = A[T,K] * W[Nout,K]^T + bias. KW = K/2 (words per row per plane).
// CTA 128x64, BK = 32 halves (16 words), 16 warps (8M x 2N), warp tile 16x32.
#define BM 128
#define BN 64
#define NT 512              // threads per CTA
#define STR 20              // words per smem row (16 + 4 pad)
#define APL 2560            // A plane words (128*20)
#define BPL 1280            // B plane words (64*20)
#define BUFW 7680           // words per buffer (2*APL + 2*BPL)
#define SMEM_BYTES (2 * BUFW * 4)

__global__ void __launch_bounds__(NT, 2)
gemm_pl(const uint32_t* __restrict__ A, size_t psA,
        const uint32_t* __restrict__ Wt, size_t psW,
        const float* __restrict__ bias, int T, int KW, int Nout,
        float* __restrict__ outA, int split, float* __restrict__ outB,
        uint32_t* __restrict__ outPk, size_t psOut,
        int relu, const unsigned char* __restrict__ mask)
{
    extern __shared__ __align__(16) uint32_t smem[];
    const uint32_t sm = smem_u32(smem);

    const int tid  = threadIdx.x;
    const int wid  = tid >> 5;
    const int lane = tid & 31;
    const int bm = blockIdx.x * BM;
    const int bn = blockIdx.y * BN;
    const int mbase = (wid & 7) * 16;      // 8 M-warps x 16 rows
    const int nbase = (wid >> 3) * 32;     // 2 N-warps x 32 cols
    const int gq = lane >> 2;
    const int tg = lane & 3;

    float acc[4][4];
#pragma unroll
    for (int ni = 0; ni < 4; ni++)
#pragma unroll
        for (int r = 0; r < 4; r++) acc[ni][r] = 0.f;

    auto load = [&](int kw0, int buf) {
        const uint32_t base = sm + buf * (BUFW * 4);
#pragma unroll
        for (int j = 0; j < 2; j++) {              // A: 2 planes x 128 rows x 4 chunks = 1024
            int o = tid + NT * j;
            int plane = o >> 9;
            int oo = o & 511;
            int row = oo >> 2;
            int ch = oo & 3;
            int gr = bm + row;
            const uint32_t* srcp = A + (size_t)plane * psA
                                     + (size_t)(gr < T ? gr : 0) * KW + kw0 + ch * 4;
            cp_async16(base + (plane * APL + row * STR + ch * 4) * 4, srcp, gr < T ? 16 : 0);
        }
        {                                          // B: 2 planes x 64 rows x 4 chunks = 512
            int o = tid;
            int plane = o >> 8;
            int oo = o & 255;
            int row = oo >> 2;
            int ch = oo & 3;
            const uint32_t* srcp = Wt + (size_t)plane * psW
                                      + (size_t)(bn + row) * KW + kw0 + ch * 4;
            cp_async16(base + (2 * APL + plane * BPL + row * STR + ch * 4) * 4, srcp, 16);
        }
        cp_async_commit();
    };

    const int nch = KW >> 4;
    load(0, 0);

    // ldmatrix per-lane address components
    const int arow = lane & 15;
    const int acol = (lane >> 4) * 4;                          // words
    const int brow = (lane & 7) + ((lane >> 4) & 1) * 8;
    const int bcol = ((lane >> 3) & 1) * 4;                    // words

    for (int i = 0; i < nch; i++) {
        cp_async_wait<0>();
        __syncthreads();
        if (i + 1 < nch) load((i + 1) << 4, (i + 1) & 1);

        const uint32_t base = sm + (i & 1) * (BUFW * 4);
        const uint32_t Ahi = base, Alo = base + APL * 4;
        const uint32_t Bhi = base + 2 * APL * 4, Blo = Bhi + BPL * 4;

#pragma unroll
        for (int k16 = 0; k16 < 2; k16++) {
            const int kw = k16 * 8;
            uint32_t ah[4], al[4];
            {
                uint32_t off = ((mbase + arow) * STR + kw + acol) * 4;
                ldm_x4(Ahi + off, ah[0], ah[1], ah[2], ah[3]);
                ldm_x4(Alo + off, al[0], al[1], al[2], al[3]);
            }
            uint32_t bh[4][2], bl[4][2];
#pragma unroll
            for (int hb = 0; hb < 2; hb++) {
                uint32_t off = ((nbase + hb * 16 + brow) * STR + kw + bcol) * 4;
                ldm_x4(Bhi + off, bh[hb*2][0], bh[hb*2][1], bh[hb*2+1][0], bh[hb*2+1][1]);
                ldm_x4(Blo + off, bl[hb*2][0], bl[hb*2][1], bl[hb*2+1][0], bl[hb*2+1][1]);
            }
#pragma unroll
            for (int ng = 0; ng < 4; ng++) {
                mma16(acc[ng], ah, bh[ng]);   // hi*hi
                mma16(acc[ng], ah, bl[ng]);   // hi*lo
                mma16(acc[ng], al, bh[ng]);   // lo*hi
            }
        }
        __syncthreads();
    }

    // ---- epilogue ----
    const int wB = Nout - split;
    const int KWout = Nout >> 1;
#pragma unroll
    for (int half = 0; half < 2; half++) {
        int row = bm + mbase + gq + half * 8;
        if (row >= T) continue;
        bool zero = (mask != nullptr) && (mask[row] != 0);
#pragma unroll
        for (int ni = 0; ni < 4; ni++) {
            int gc = bn + nbase + ni * 8 + tg * 2;
            float vx = acc[ni][half * 2 + 0] + bias[gc];
            float vy = acc[ni][half * 2 + 1] + bias[gc + 1];
            if (relu) { vx = fmaxf(vx, 0.f); vy = fmaxf(vy, 0.f); }
            if (zero) { vx = 0.f; vy = 0.f; }
            if (outPk) {
                uint32_t hw, lw;
                split2(vx, vy, hw, lw);
                size_t wi = (size_t)row * KWout + (gc >> 1);
                outPk[wi] = hw;
                outPk[wi + psOut] = lw;
            }
            if (outA) {
                if (gc < split) {
                    float2 v; v.x = vx; v.y = vy;
                    *reinterpret_cast<float2*>(outA + (size_t)row * split + gc) = v;
                } else if (outB) {
                    float2 v; v.x = vx; v.y = vy;
                    *reinterpret_cast<float2*>(outB + (size_t)row * wB + (gc - split)) = v;
                }
            }
        }
    }
}

// -------------------- weight packing (planar) --------------------
#define WV_W  32768
#define WO_W  32768
#define WA_W  16384
#define WP_W  32768
#define W1_W  131072
#define W2_W  131072
#define TOT_W (WV_W + WO_W + WA_W + WP_W + W1_W + W2_W)   // 376832

__global__ void pack_weights(const float* __restrict__ Wv, const float* __restrict__ Wo,
                             const float* __restrict__ Wa, const float* __restrict__ Wp,
                             const float* __restrict__ W1, const float* __restrict__ W2,
                             const float* __restrict__ bo, const float* __restrict__ ba)
{
    int i = blockIdx.x * 256 + threadIdx.x;
    if (i < TOT_W) {
        const float* srcm; uint32_t* dst; int w; size_t ps;
        if (i < WV_W)                      { srcm = Wv; dst = g_Wv_pk;  w = i; ps = WV_W; }
        else if (i < WV_W + WO_W)          { srcm = Wo; dst = g_Woa_pk; w = i - WV_W; ps = WO_W + WA_W; }
        else if (i < WV_W + WO_W + WA_W)   { srcm = Wa; dst = g_Woa_pk + WO_W; w = i - WV_W - WO_W; ps = WO_W + WA_W; }
        else if (i < WV_W + WO_W + WA_W + WP_W)
                                           { srcm = Wp; dst = g_Wp_pk;  w = i - WV_W - WO_W - WA_W; ps = WP_W; }
        else if (i < TOT_W - W2_W)         { srcm = W1; dst = g_W1_pk;  w = i - (WV_W+WO_W+WA_W+WP_W); ps = W1_W; }
        else                               { srcm = W2; dst = g_W2_pk;  w = i - (TOT_W - W2_W); ps = W2_W; }
        float2 v = *reinterpret_cast<const float2*>(srcm + 2 * (size_t)w);
        uint32_t hw, lw;
        split2(v.x, v.y, hw, lw);
        dst[w] = hw;
        dst[w + ps] = lw;
    } else if (i < TOT_W + 256) {
        g_bias_oa[i - TOT_W] = bo[i - TOT_W];
    } else if (i < TOT_W + 384) {
        g_bias_oa[i - TOT_W] = ba[i - TOT_W - 256];
    }
}

// -------------------- build q / v_in (fp32 + planar packed) --------------------
__global__ void build_qv_kernel(const float* __restrict__ src, const float* __restrict__ pos,
                                const float* __restrict__ sel,
                                uint32_t* __restrict__ q_pk,
                                float* __restrict__ vin, uint32_t* __restrict__ vin_pk)
{
    size_t gid = (size_t)blockIdx.x * 256 + threadIdx.x;
    if (gid >= (size_t)TTOK * 128) return;
    int dw = (int)(gid & 127);
    size_t t = gid >> 7;
    int n = (int)(t / LQ);
    int i = (int)(t % LQ);
    float2 sv, pv;
    if (i < LSP) {
        size_t si = ((size_t)n * LSP + i) * DMODEL + dw * 2;
        sv = *reinterpret_cast<const float2*>(src + si);
        pv = *reinterpret_cast<const float2*>(pos + si);
    } else {
        size_t si = ((size_t)n * NVT + (i - LSP)) * DMODEL + dw * 2;
        sv = *reinterpret_cast<const float2*>(sel + si);
        pv.x = 0.f; pv.y = 0.f;
    }
    float qx = sv.x + pv.x, qy = sv.y + pv.y;
    const size_t PS = (size_t)TTOK * 128;
    uint32_t hw, lw;
    split2(qx, qy, hw, lw);
    q_pk[gid] = hw; q_pk[gid + PS] = lw;
    split2(sv.x, sv.y, hw, lw);
    vin_pk[gid] = hw; vin_pk[gid + PS] = lw;
    *reinterpret_cast<float2*>(vin + 2 * gid) = sv;
}

// -------------------- deformable sampling: warp per (token, head) --------------------
__global__ void msdeform_sample_kernel(const float* __restrict__ value,
                                       const float* __restrict__ logits,
                                       const float* __restrict__ off,
                                       const float* __restrict__ ref,
                                       uint32_t* __restrict__ out_pk)
{
    const int nq   = blockIdx.x;
    const int n    = nq / LQ;
    const int m    = threadIdx.x >> 5;
    const int lane = threadIdx.x & 31;

    const float* lg = logits + (size_t)nq * 128 + m * 16;
    float v = (lane < 16) ? lg[lane] : -1e30f;
    float mx = v;
#pragma unroll
    for (int o = 16; o > 0; o >>= 1) mx = fmaxf(mx, __shfl_xor_sync(0xffffffffu, mx, o));
    float e = (lane < 16) ? __expf(v - mx) : 0.f;
    float sm = e;
#pragma unroll
    for (int o = 16; o > 0; o >>= 1) sm += __shfl_xor_sync(0xffffffffu, sm, o);
    float wgt = e / sm;

    float offv = off[(size_t)nq * DMODEL + m * 32 + lane];
    float refv = (lane < 8) ? ref[(size_t)nq * 8 + lane] : 0.f;

    const float* vb = value + (size_t)n * LQ * DMODEL + m * 32 + lane;

    const int HH[4] = {64, 32, 16, 8};
    const int WW[4] = {64, 32, 16, 8};
    const int ST[4] = {0, 4096, 5120, 5376};

    float acc = 0.f;
#pragma unroll
    for (int s = 0; s < 16; s++) {
        const int l = s >> 2;
        float dx = __shfl_sync(0xffffffffu, offv, 2 * s);
        float dy = __shfl_sync(0xffffffffu, offv, 2 * s + 1);
        float rx = __shfl_sync(0xffffffffu, refv, 2 * l);
        float ry = __shfl_sync(0xffffffffu, refv, 2 * l + 1);
        float ws = __shfl_sync(0xffffffffu, wgt, s);
        const int H = HH[l], W = WW[l], st = ST[l];

        float x = rx * (float)W + dx - 0.5f;
        float y = ry * (float)H + dy - 0.5f;
        float xf = floorf(x), yf = floorf(y);
        int x0 = (int)xf, y0 = (int)yf;
        float wx = x - xf, wy = y - yf;

        float w00 = (1.f - wx) * (1.f - wy);
        float w10 = wx * (1.f - wy);
        float w01 = (1.f - wx) * wy;
        float w11 = wx * wy;

        float samp = 0.f;
        if (x0 >= 0 && x0 < W && y0 >= 0 && y0 < H)
            samp += w00 * vb[(size_t)(st + y0 * W + x0) * DMODEL];
        if (x0 + 1 >= 0 && x0 + 1 < W && y0 >= 0 && y0 < H)
            samp += w10 * vb[(size_t)(st + y0 * W + x0 + 1) * DMODEL];
        if (x0 >= 0 && x0 < W && y0 + 1 >= 0 && y0 + 1 < H)
            samp += w01 * vb[(size_t)(st + (y0 + 1) * W + x0) * DMODEL];
        if (x0 + 1 >= 0 && x0 + 1 < W && y0 + 1 >= 0 && y0 + 1 < H)
            samp += w11 * vb[(size_t)(st + (y0 + 1) * W + x0 + 1) * DMODEL];

        acc += ws * samp;
    }
    float accn = __shfl_down_sync(0xffffffffu, acc, 1);
    if ((lane & 1) == 0) {
        uint32_t hw, lw;
        split2(acc, accn, hw, lw);
        size_t wi = (size_t)nq * 128 + ((m * 32 + lane) >> 1);
        out_pk[wi] = hw;
        out_pk[wi + (size_t)TTOK * 128] = lw;
    }
}

// -------------------- add + LayerNorm --------------------
__global__ void add_ln_kernel(const float* __restrict__ a, const float* __restrict__ b,
                              const float* __restrict__ g, const float* __restrict__ beta,
                              float* __restrict__ out, uint32_t* __restrict__ out_pk, int scatter)
{
    const int t = blockIdx.x;
    const int d = threadIdx.x;
    const int lane = d & 31, wid = d >> 5;

    float v = a[(size_t)t * DMODEL + d] + b[(size_t)t * DMODEL + d];

    __shared__ float red[8];
    float s = v;
#pragma unroll
    for (int o = 16; o > 0; o >>= 1) s += __shfl_xor_sync(0xffffffffu, s, o);
    if (lane == 0) red[wid] = s;
    __syncthreads();
    float mean;
    {
        if (d == 0) {
            float tot = 0.f;
#pragma unroll
            for (int i = 0; i < 8; i++) tot += red[i];
            red[0] = tot;
        }
        __syncthreads();
        mean = red[0] * (1.f / 256.f);
    }
    __syncthreads();

    float xc = v - mean;
    s = xc * xc;
#pragma unroll
    for (int o = 16; o > 0; o >>= 1) s += __shfl_xor_sync(0xffffffffu, s, o);
    if (lane == 0) red[wid] = s;
    __syncthreads();
    float var;
    {
        if (d == 0) {
            float tot = 0.f;
#pragma unroll
            for (int i = 0; i < 8; i++) tot += red[i];
            red[0] = tot;
        }
        __syncthreads();
        var = red[0] * (1.f / 256.f);
    }

    float r = g[d] * xc * rsqrtf(var + 1e-5f) + beta[d];

    if (out_pk) {
        float rn = __shfl_down_sync(0xffffffffu, r, 1);
        if ((d & 1) == 0) {
            uint32_t hw, lw;
            split2(r, rn, hw, lw);
            size_t wi = (size_t)t * 128 + (d >> 1);
            out_pk[wi] = hw;
            out_pk[wi + (size_t)TTOK * 128] = lw;
        }
    }

    float* dst;
    if (!scatter) {
        dst = out + (size_t)t * DMODEL;
    } else {
        int n = t / LQ, i = t % LQ;
        if (i < LSP)
            dst = out + ((size_t)n * LSP + i) * DMODEL;
        else
            dst = out + ((size_t)N_BATCH * LSP + (size_t)N_BATCH * NALLVT) * DMODEL
                      + ((size_t)n * NVT + (i - LSP)) * DMODEL;
    }
    dst[d] = r;
}

// -------------------- launch --------------------
extern "C" void kernel_launch(void* const* d_in, const int* in_sizes, int n_in,
                              void* d_out, int out_size)
{
    const float* src  = (const float*)d_in[0];
    const float* pos  = (const float*)d_in[1];
    const float* ref  = (const float*)d_in[2];
    const unsigned char* mask = (const unsigned char*)d_in[5];
    const float* all_vt = (const float*)d_in[6];
    const float* sel_vt = (const float*)d_in[7];
    const float* Wv = (const float*)d_in[8];   const float* bv  = (const float*)d_in[9];
    const float* Wo = (const float*)d_in[10];  const float* bo  = (const float*)d_in[11];
    const float* Wa = (const float*)d_in[12];  const float* ba  = (const float*)d_in[13];
    const float* Wp = (const float*)d_in[14];  const float* bp  = (const float*)d_in[15];
    const float* g1 = (const float*)d_in[16];  const float* be1 = (const float*)d_in[17];
    const float* W1 = (const float*)d_in[18];  const float* bf1 = (const float*)d_in[19];
    const float* W2 = (const float*)d_in[20];  const float* bf2 = (const float*)d_in[21];
    const float* g2 = (const float*)d_in[22];  const float* be2 = (const float*)d_in[23];
    float* out = (float*)d_out;

    uint32_t *q_pk, *vin_pk, *samp_pk, *x_pk, *h_pk;
    uint32_t *Wv_pk, *Woa_pk, *Wp_pk, *W1_pk, *W2_pk;
    float *vin, *value, *off, *attn, *src2, *x, *y, *bias_oa;
    cudaGetSymbolAddress((void**)&q_pk,   g_q_pk);
    cudaGetSymbolAddress((void**)&vin,    g_vin);
    cudaGetSymbolAddress((void**)&vin_pk, g_vin_pk);
    cudaGetSymbolAddress((void**)&value,  g_value);
    cudaGetSymbolAddress((void**)&off,    g_off);
    cudaGetSymbolAddress((void**)&attn,   g_attn);
    cudaGetSymbolAddress((void**)&samp_pk,g_samp_pk);
    cudaGetSymbolAddress((void**)&src2,   g_src2);
    cudaGetSymbolAddress((void**)&x,      g_x);
    cudaGetSymbolAddress((void**)&x_pk,   g_x_pk);
    cudaGetSymbolAddress((void**)&h_pk,   g_h_pk);
    cudaGetSymbolAddress((void**)&y,      g_y);
    cudaGetSymbolAddress((void**)&Wv_pk,  g_Wv_pk);
    cudaGetSymbolAddress((void**)&Woa_pk, g_Woa_pk);
    cudaGetSymbolAddress((void**)&Wp_pk,  g_Wp_pk);
    cudaGetSymbolAddress((void**)&W1_pk,  g_W1_pk);
    cudaGetSymbolAddress((void**)&W2_pk,  g_W2_pk);
    cudaGetSymbolAddress((void**)&bias_oa,g_bias_oa);

    cudaFuncSetAttribute(gemm_pl, cudaFuncAttributeMaxDynamicSharedMemorySize, SMEM_BYTES);

    const int T = TTOK;
    const int TM = (T + BM - 1) / BM;   // 171
    const size_t psAct = (size_t)TTOK * 128;
    const size_t psH   = (size_t)TTOK * 512;

    // 0) pack weights (+ concat bias_oa)
    pack_weights<<<(TOT_W + 384 + 255) / 256, 256>>>(Wv, Wo, Wa, Wp, W1, W2, bo, ba);

    // 1) build q / v_in
    build_qv_kernel<<<(TTOK * 128 + 255) / 256, 256>>>(src, pos, sel_vt, q_pk, vin, vin_pk);

    // 2) value = vin @ Wv^T + bv (masked)
    gemm_pl<<<dim3(TM, 4), NT, SMEM_BYTES>>>(vin_pk, psAct, Wv_pk, WV_W, bv, T, 128, 256,
                                             value, 256, nullptr, nullptr, 0, 0, mask);
    // 3) [off | attn] = q @ [Wo;Wa]^T + [bo;ba]
    gemm_pl<<<dim3(TM, 6), NT, SMEM_BYTES>>>(q_pk, psAct, Woa_pk, WO_W + WA_W, bias_oa, T, 128, 384,
                                             off, 256, attn, nullptr, 0, 0, nullptr);

    // 4) deformable sampling (softmax fused) -> planar packed samp
    msdeform_sample_kernel<<<TTOK, 256>>>(value, attn, off, ref, samp_pk);

    // 5) src2 = samp @ Wp^T + bp
    gemm_pl<<<dim3(TM, 4), NT, SMEM_BYTES>>>(samp_pk, psAct, Wp_pk, WP_W, bp, T, 128, 256,
                                             src2, 256, nullptr, nullptr, 0, 0, nullptr);

    // 6) x = LN(vin + src2), also planar packed
    add_ln_kernel<<<TTOK, 256>>>(vin, src2, g1, be1, x, x_pk, 0);

    // 7) h = relu(x @ W1^T + bf1) -> planar packed only
    gemm_pl<<<dim3(TM, 16), NT, SMEM_BYTES>>>(x_pk, psAct, W1_pk, W1_W, bf1, T, 128, 1024,
                                              nullptr, 1024, nullptr, h_pk, psH, 1, nullptr);
    // 8) y = h @ W2^T + bf2
    gemm_pl<<<dim3(TM, 4), NT, SMEM_BYTES>>>(h_pk, psH, W2_pk, W2_W, bf2, T, 512, 256,
                                             y, 256, nullptr, nullptr, 0, 0, nullptr);

    // 9) out = LN(x + y) scattered into [spatial | all_vt | vt] layout
    add_ln_kernel<<<TTOK, 256>>>(x, y, g2, be2, out, nullptr, 1);

    // 10) all_vt passthrough
    cudaMemcpyAsync(out + (size_t)N_BATCH * LSP * DMODEL, all_vt,
                    (size_t)N_BATCH * NALLVT * DMODEL * sizeof(float),
                    cudaMemcpyDeviceToDevice, 0);
}

// round 11
// speedup vs baseline: 1.8656x; 1.2670x over previous
#include <cuda_runtime.h>
#include <cuda_fp16.h>
#include <math.h>
#include <stdint.h>

#define N_BATCH 4
#define LQ      5448
#define LSP     5440
#define DMODEL  256
#define DFFN    1024
#define NVT     8
#define NALLVT  600
#define TTOK    (N_BATCH * LQ)   // 21792

// -------------------- scratch --------------------
// activations: single-plane fp16x2 words (K/2 words per row)
__device__ uint32_t g_q_pk   [(size_t)TTOK * 128];
__device__ float    g_vin    [(size_t)TTOK * DMODEL];
__device__ uint32_t g_vin_pk [(size_t)TTOK * 128];
__device__ float    g_value  [(size_t)TTOK * DMODEL];
__device__ float    g_off    [(size_t)TTOK * DMODEL];
__device__ float    g_attn   [(size_t)TTOK * 128];
__device__ uint32_t g_samp_pk[(size_t)TTOK * 128];
__device__ float    g_src2   [(size_t)TTOK * DMODEL];
__device__ float    g_x      [(size_t)TTOK * DMODEL];
__device__ uint32_t g_x_pk   [(size_t)TTOK * 128];
__device__ uint32_t g_h_pk   [(size_t)TTOK * 512];
__device__ float    g_y      [(size_t)TTOK * DMODEL];
// packed weights: dual-fp16 planar (hi plane then lo/residual plane)
__device__ uint32_t g_Wv_pk [2 * 256 * 128];
__device__ uint32_t g_Woa_pk[2 * 384 * 128];
__device__ uint32_t g_Wp_pk [2 * 256 * 128];
__device__ uint32_t g_W1_pk [2 * 1024 * 128];
__device__ uint32_t g_W2_pk [2 * 256 * 512];
__device__ float    g_bias_oa[384];

// ==================== helpers ====================
__device__ __forceinline__ uint32_t smem_u32(const void* p) {
    return (uint32_t)__cvta_generic_to_shared(p);
}
__device__ __forceinline__ void cp_async16(uint32_t dst, const void* src, int src_size) {
    asm volatile("cp.async.cg.shared.global [%0], [%1], 16, %2;\n"
                 :: "r"(dst), "l"(src), "r"(src_size));
}
__device__ __forceinline__ void cp_async_commit() {
    asm volatile("cp.async.commit_group;" ::: "memory");
}
template<int N> __device__ __forceinline__ void cp_async_wait() {
    asm volatile("cp.async.wait_group %0;" :: "n"(N) : "memory");
}
__device__ __forceinline__ void ldm_x4(uint32_t addr, uint32_t& r0, uint32_t& r1,
                                       uint32_t& r2, uint32_t& r3) {
    asm volatile("ldmatrix.sync.aligned.m8n8.x4.shared.b16 {%0,%1,%2,%3}, [%4];"
                 : "=r"(r0), "=r"(r1), "=r"(r2), "=r"(r3) : "r"(addr));
}
__device__ __forceinline__ void mma16(float* d, const uint32_t* a, const uint32_t* b) {
    asm volatile(
        "mma.sync.aligned.m16n8k16.row.col.f32.f16.f16.f32 "
        "{%0,%1,%2,%3}, {%4,%5,%6,%7}, {%8,%9}, {%0,%1,%2,%3};"
        : "+f"(d[0]), "+f"(d[1]), "+f"(d[2]), "+f"(d[3])
        : "r"(a[0]), "r"(a[1]), "r"(a[2]), "r"(a[3]), "r"(b[0]), "r"(b[1]));
}
// pack two fp32 into one fp16x2 word
__device__ __forceinline__ uint32_t pack2h(float vx, float vy) {
    __half2 h = __floats2half2_rn(vx, vy);
    return *reinterpret_cast<uint32_t*>(&h);
}
// split two adjacent fp32 weights into (hi fp16x2, residual fp16x2)
__device__ __forceinline__ void wsplit2(float vx, float vy, uint32_t& hw, uint32_t& lw) {
    __half hx = __float2half_rn(vx);
    __half lx = __float2half_rn(vx - __half2float(hx));
    __half hy = __float2half_rn(vy);
    __half ly = __float2half_rn(vy - __half2float(hy));
    hw = (uint32_t)__half_as_ushort(hx) | ((uint32_t)__half_as_ushort(hy) << 16);
    lw = (uint32_t)__half_as_ushort(lx) | ((uint32_t)__half_as_ushort(ly) << 16);
}

// ==================== 2-term fp16 GEMM via ldmatrix ====================
// out[T,Nout] = A[T,K] * (Wh + Wl)[Nout,K]^T + bias. KW = K/2 words per row.
// A: single fp16 plane. W: hi+lo planes. CTA 128x64, BK=32, 8 warps (4Mx2N), warp 32x32.
#define BM 128
#define BN 64
#define STR 20              // words per smem row (16 + 4 pad)
#define APL 2560            // A plane words (128*20)
#define BPL 1280            // B plane words (64*20)
#define BUFW 5120           // words per buffer (APL + 2*BPL)
#define SMEM_BYTES (2 * BUFW * 4)

__global__ void __launch_bounds__(256, 2)
gemm_pl(const uint32_t* __restrict__ A,
        const uint32_t* __restrict__ Wt, size_t psW,
        const float* __restrict__ bias, int T, int KW, int Nout,
        float* __restrict__ outA, int split, float* __restrict__ outB,
        uint32_t* __restrict__ outPk,
        int relu, const unsigned char* __restrict__ mask)
{
    extern __shared__ __align__(16) uint32_t smem[];
    const uint32_t sm = smem_u32(smem);

    const int tid  = threadIdx.x;
    const int wid  = tid >> 5;
    const int lane = tid & 31;
    const int bm = blockIdx.x * BM;
    const int bn = blockIdx.y * BN;
    const int mbase = (wid & 3) * 32;
    const int nbase = (wid >> 2) * 32;
    const int gq = lane >> 2;
    const int tg = lane & 3;

    float acc[2][4][4];
#pragma unroll
    for (int mi = 0; mi < 2; mi++)
#pragma unroll
        for (int ni = 0; ni < 4; ni++)
#pragma unroll
            for (int r = 0; r < 4; r++) acc[mi][ni][r] = 0.f;

    auto load = [&](int kw0, int buf) {
        const uint32_t base = sm + buf * (BUFW * 4);
#pragma unroll
        for (int j = 0; j < 2; j++) {              // A: 128 rows x 4 chunks = 512
            int o = tid + 256 * j;
            int row = o >> 2;
            int ch = o & 3;
            int gr = bm + row;
            const uint32_t* srcp = A + (size_t)(gr < T ? gr : 0) * KW + kw0 + ch * 4;
            cp_async16(base + (row * STR + ch * 4) * 4, srcp, gr < T ? 16 : 0);
        }
#pragma unroll
        for (int j = 0; j < 2; j++) {              // B: 2 planes x 64 rows x 4 chunks = 512
            int o = tid + 256 * j;
            int plane = o >> 8;
            int oo = o & 255;
            int row = oo >> 2;
            int ch = oo & 3;
            const uint32_t* srcp = Wt + (size_t)plane * psW
                                      + (size_t)(bn + row) * KW + kw0 + ch * 4;
            cp_async16(base + (APL + plane * BPL + row * STR + ch * 4) * 4, srcp, 16);
        }
        cp_async_commit();
    };

    const int nch = KW >> 4;
    load(0, 0);

    // ldmatrix per-lane address components
    const int arow = lane & 15;
    const int acol = (lane >> 4) * 4;                          // words
    const int brow = (lane & 7) + ((lane >> 4) & 1) * 8;
    const int bcol = ((lane >> 3) & 1) * 4;                    // words

    for (int i = 0; i < nch; i++) {
        cp_async_wait<0>();
        __syncthreads();
        if (i + 1 < nch) load((i + 1) << 4, (i + 1) & 1);

        const uint32_t base = sm + (i & 1) * (BUFW * 4);
        const uint32_t Aw = base;
        const uint32_t Bhi = base + APL * 4, Blo = Bhi + BPL * 4;

#pragma unroll
        for (int k16 = 0; k16 < 2; k16++) {
            const int kw = k16 * 8;
            uint32_t ah[2][4];
#pragma unroll
            for (int mi = 0; mi < 2; mi++) {
                uint32_t off = ((mbase + mi * 16 + arow) * STR + kw + acol) * 4;
                ldm_x4(Aw + off, ah[mi][0], ah[mi][1], ah[mi][2], ah[mi][3]);
            }
            uint32_t bh[4][2], bl[4][2];
#pragma unroll
            for (int hb = 0; hb < 2; hb++) {
                uint32_t off = ((nbase + hb * 16 + brow) * STR + kw + bcol) * 4;
                ldm_x4(Bhi + off, bh[hb*2][0], bh[hb*2][1], bh[hb*2+1][0], bh[hb*2+1][1]);
                ldm_x4(Blo + off, bl[hb*2][0], bl[hb*2][1], bl[hb*2+1][0], bl[hb*2+1][1]);
            }
#pragma unroll
            for (int mi = 0; mi < 2; mi++)
#pragma unroll
                for (int ng = 0; ng < 4; ng++) {
                    mma16(acc[mi][ng], ah[mi], bh[ng]);   // a * w_hi
                    mma16(acc[mi][ng], ah[mi], bl[ng]);   // a * w_lo
                }
        }
        __syncthreads();
    }

    // ---- epilogue ----
    const int wB = Nout - split;
    const int KWout = Nout >> 1;
#pragma unroll
    for (int mi = 0; mi < 2; mi++) {
#pragma unroll
        for (int half = 0; half < 2; half++) {
            int row = bm + mbase + mi * 16 + gq + half * 8;
            if (row >= T) continue;
            bool zero = (mask != nullptr) && (mask[row] != 0);
#pragma unroll
            for (int ni = 0; ni < 4; ni++) {
                int gc = bn + nbase + ni * 8 + tg * 2;
                float vx = acc[mi][ni][half * 2 + 0] + bias[gc];
                float vy = acc[mi][ni][half * 2 + 1] + bias[gc + 1];
                if (relu) { vx = fmaxf(vx, 0.f); vy = fmaxf(vy, 0.f); }
                if (zero) { vx = 0.f; vy = 0.f; }
                if (outPk)
                    outPk[(size_t)row * KWout + (gc >> 1)] = pack2h(vx, vy);
                if (outA) {
                    if (gc < split) {
                        float2 v; v.x = vx; v.y = vy;
                        *reinterpret_cast<float2*>(outA + (size_t)row * split + gc) = v;
                    } else if (outB) {
                        float2 v; v.x = vx; v.y = vy;
                        *reinterpret_cast<float2*>(outB + (size_t)row * wB + (gc - split)) = v;
                    }
                }
            }
        }
    }
}

// -------------------- weight packing (dual-fp16 planar) --------------------
#define WV_W  32768
#define WO_W  32768
#define WA_W  16384
#define WP_W  32768
#define W1_W  131072
#define W2_W  131072
#define TOT_W (WV_W + WO_W + WA_W + WP_W + W1_W + W2_W)   // 376832

__global__ void pack_weights(const float* __restrict__ Wv, const float* __restrict__ Wo,
                             const float* __restrict__ Wa, const float* __restrict__ Wp,
                             const float* __restrict__ W1, const float* __restrict__ W2,
                             const float* __restrict__ bo, const float* __restrict__ ba)
{
    int i = blockIdx.x * 256 + threadIdx.x;
    if (i < TOT_W) {
        const float* srcm; uint32_t* dst; int w; size_t ps;
        if (i < WV_W)                      { srcm = Wv; dst = g_Wv_pk;  w = i; ps = WV_W; }
        else if (i < WV_W + WO_W)          { srcm = Wo; dst = g_Woa_pk; w = i - WV_W; ps = WO_W + WA_W; }
        else if (i < WV_W + WO_W + WA_W)   { srcm = Wa; dst = g_Woa_pk + WO_W; w = i - WV_W - WO_W; ps = WO_W + WA_W; }
        else if (i < WV_W + WO_W + WA_W + WP_W)
                                           { srcm = Wp; dst = g_Wp_pk;  w = i - WV_W - WO_W - WA_W; ps = WP_W; }
        else if (i < TOT_W - W2_W)         { srcm = W1; dst = g_W1_pk;  w = i - (WV_W+WO_W+WA_W+WP_W); ps = W1_W; }
        else                               { srcm = W2; dst = g_W2_pk;  w = i - (TOT_W - W2_W); ps = W2_W; }
        float2 v = *reinterpret_cast<const float2*>(srcm + 2 * (size_t)w);
        uint32_t hw, lw;
        wsplit2(v.x, v.y, hw, lw);
        dst[w] = hw;
        dst[w + ps] = lw;
    } else if (i < TOT_W + 256) {
        g_bias_oa[i - TOT_W] = bo[i - TOT_W];
    } else if (i < TOT_W + 384) {
        g_bias_oa[i - TOT_W] = ba[i - TOT_W - 256];
    }
}

// -------------------- build q / v_in (fp32 + fp16 packed) --------------------
__global__ void build_qv_kernel(const float* __restrict__ src, const float* __restrict__ pos,
                                const float* __restrict__ sel,
                                uint32_t* __restrict__ q_pk,
                                float* __restrict__ vin, uint32_t* __restrict__ vin_pk)
{
    size_t gid = (size_t)blockIdx.x * 256 + threadIdx.x;
    if (gid >= (size_t)TTOK * 128) return;
    int dw = (int)(gid & 127);
    size_t t = gid >> 7;
    int n = (int)(t / LQ);
    int i = (int)(t % LQ);
    float2 sv, pv;
    if (i < LSP) {
        size_t si = ((size_t)n * LSP + i) * DMODEL + dw * 2;
        sv = *reinterpret_cast<const float2*>(src + si);
        pv = *reinterpret_cast<const float2*>(pos + si);
    } else {
        size_t si = ((size_t)n * NVT + (i - LSP)) * DMODEL + dw * 2;
        sv = *reinterpret_cast<const float2*>(sel + si);
        pv.x = 0.f; pv.y = 0.f;
    }
    q_pk[gid]   = pack2h(sv.x + pv.x, sv.y + pv.y);
    vin_pk[gid] = pack2h(sv.x, sv.y);
    *reinterpret_cast<float2*>(vin + 2 * gid) = sv;
}

// -------------------- deformable sampling: warp per (token, head) --------------------
__global__ void msdeform_sample_kernel(const float* __restrict__ value,
                                       const float* __restrict__ logits,
                                       const float* __restrict__ off,
                                       const float* __restrict__ ref,
                                       uint32_t* __restrict__ out_pk)
{
    const int nq   = blockIdx.x;
    const int n    = nq / LQ;
    const int m    = threadIdx.x >> 5;
    const int lane = threadIdx.x & 31;

    const float* lg = logits + (size_t)nq * 128 + m * 16;
    float v = (lane < 16) ? lg[lane] : -1e30f;
    float mx = v;
#pragma unroll
    for (int o = 16; o > 0; o >>= 1) mx = fmaxf(mx, __shfl_xor_sync(0xffffffffu, mx, o));
    float e = (lane < 16) ? __expf(v - mx) : 0.f;
    float sm = e;
#pragma unroll
    for (int o = 16; o > 0; o >>= 1) sm += __shfl_xor_sync(0xffffffffu, sm, o);
    float wgt = e / sm;

    float offv = off[(size_t)nq * DMODEL + m * 32 + lane];
    float refv = (lane < 8) ? ref[(size_t)nq * 8 + lane] : 0.f;

    const float* vb = value + (size_t)n * LQ * DMODEL + m * 32 + lane;

    const int HH[4] = {64, 32, 16, 8};
    const int WW[4] = {64, 32, 16, 8};
    const int ST[4] = {0, 4096, 5120, 5376};

    float acc = 0.f;
#pragma unroll
    for (int s = 0; s < 16; s++) {
        const int l = s >> 2;
        float dx = __shfl_sync(0xffffffffu, offv, 2 * s);
        float dy = __shfl_sync(0xffffffffu, offv, 2 * s + 1);
        float rx = __shfl_sync(0xffffffffu, refv, 2 * l);
        float ry = __shfl_sync(0xffffffffu, refv, 2 * l + 1);
        float ws = __shfl_sync(0xffffffffu, wgt, s);
        const int H = HH[l], W = WW[l], st = ST[l];

        float x = rx * (float)W + dx - 0.5f;
        float y = ry * (float)H + dy - 0.5f;
        float xf = floorf(x), yf = floorf(y);
        int x0 = (int)xf, y0 = (int)yf;
        float wx = x - xf, wy = y - yf;

        float w00 = (1.f - wx) * (1.f - wy);
        float w10 = wx * (1.f - wy);
        float w01 = (1.f - wx) * wy;
        float w11 = wx * wy;

        float samp = 0.f;
        if (x0 >= 0 && x0 < W && y0 >= 0 && y0 < H)
            samp += w00 * vb[(size_t)(st + y0 * W + x0) * DMODEL];
        if (x0 + 1 >= 0 && x0 + 1 < W && y0 >= 0 && y0 < H)
            samp += w10 * vb[(size_t)(st + y0 * W + x0 + 1) * DMODEL];
        if (x0 >= 0 && x0 < W && y0 + 1 >= 0 && y0 + 1 < H)
            samp += w01 * vb[(size_t)(st + (y0 + 1) * W + x0) * DMODEL];
        if (x0 + 1 >= 0 && x0 + 1 < W && y0 + 1 >= 0 && y0 + 1 < H)
            samp += w11 * vb[(size_t)(st + (y0 + 1) * W + x0 + 1) * DMODEL];

        acc += ws * samp;
    }
    float accn = __shfl_down_sync(0xffffffffu, acc, 1);
    if ((lane & 1) == 0)
        out_pk[(size_t)nq * 128 + ((m * 32 + lane) >> 1)] = pack2h(acc, accn);
}

// -------------------- add + LayerNorm --------------------
__global__ void add_ln_kernel(const float* __restrict__ a, const float* __restrict__ b,
                              const float* __restrict__ g, const float* __restrict__ beta,
                              float* __restrict__ out, uint32_t* __restrict__ out_pk, int scatter)
{
    const int t = blockIdx.x;
    const int d = threadIdx.x;
    const int lane = d & 31, wid = d >> 5;

    float v = a[(size_t)t * DMODEL + d] + b[(size_t)t * DMODEL + d];

    __shared__ float red[8];
    float s = v;
#pragma unroll
    for (int o = 16; o > 0; o >>= 1) s += __shfl_xor_sync(0xffffffffu, s, o);
    if (lane == 0) red[wid] = s;
    __syncthreads();
    float mean;
    {
        if (d == 0) {
            float tot = 0.f;
#pragma unroll
            for (int i = 0; i < 8; i++) tot += red[i];
            red[0] = tot;
        }
        __syncthreads();
        mean = red[0] * (1.f / 256.f);
    }
    __syncthreads();

    float xc = v - mean;
    s = xc * xc;
#pragma unroll
    for (int o = 16; o > 0; o >>= 1) s += __shfl_xor_sync(0xffffffffu, s, o);
    if (lane == 0) red[wid] = s;
    __syncthreads();
    float var;
    {
        if (d == 0) {
            float tot = 0.f;
#pragma unroll
            for (int i = 0; i < 8; i++) tot += red[i];
            red[0] = tot;
        }
        __syncthreads();
        var = red[0] * (1.f / 256.f);
    }

    float r = g[d] * xc * rsqrtf(var + 1e-5f) + beta[d];

    if (out_pk) {
        float rn = __shfl_down_sync(0xffffffffu, r, 1);
        if ((d & 1) == 0)
            out_pk[(size_t)t * 128 + (d >> 1)] = pack2h(r, rn);
    }

    float* dst;
    if (!scatter) {
        dst = out + (size_t)t * DMODEL;
    } else {
        int n = t / LQ, i = t % LQ;
        if (i < LSP)
            dst = out + ((size_t)n * LSP + i) * DMODEL;
        else
            dst = out + ((size_t)N_BATCH * LSP + (size_t)N_BATCH * NALLVT) * DMODEL
                      + ((size_t)n * NVT + (i - LSP)) * DMODEL;
    }
    dst[d] = r;
}

// -------------------- launch --------------------
extern "C" void kernel_launch(void* const* d_in, const int* in_sizes, int n_in,
                              void* d_out, int out_size)
{
    const float* src  = (const float*)d_in[0];
    const float* pos  = (const float*)d_in[1];
    const float* ref  = (const float*)d_in[2];
    const unsigned char* mask = (const unsigned char*)d_in[5];
    const float* all_vt = (const float*)d_in[6];
    const float* sel_vt = (const float*)d_in[7];
    const float* Wv = (const float*)d_in[8];   const float* bv  = (const float*)d_in[9];
    const float* Wo = (const float*)d_in[10];  const float* bo  = (const float*)d_in[11];
    const float* Wa = (const float*)d_in[12];  const float* ba  = (const float*)d_in[13];
    const float* Wp = (const float*)d_in[14];  const float* bp  = (const float*)d_in[15];
    const float* g1 = (const float*)d_in[16];  const float* be1 = (const float*)d_in[17];
    const float* W1 = (const float*)d_in[18];  const float* bf1 = (const float*)d_in[19];
    const float* W2 = (const float*)d_in[20];  const float* bf2 = (const float*)d_in[21];
    const float* g2 = (const float*)d_in[22];  const float* be2 = (const float*)d_in[23];
    float* out = (float*)d_out;

    uint32_t *q_pk, *vin_pk, *samp_pk, *x_pk, *h_pk;
    uint32_t *Wv_pk, *Woa_pk, *Wp_pk, *W1_pk, *W2_pk;
    float *vin, *value, *off, *attn, *src2, *x, *y, *bias_oa;
    cudaGetSymbolAddress((void**)&q_pk,   g_q_pk);
    cudaGetSymbolAddress((void**)&vin,    g_vin);
    cudaGetSymbolAddress((void**)&vin_pk, g_vin_pk);
    cudaGetSymbolAddress((void**)&value,  g_value);
    cudaGetSymbolAddress((void**)&off,    g_off);
    cudaGetSymbolAddress((void**)&attn,   g_attn);
    cudaGetSymbolAddress((void**)&samp_pk,g_samp_pk);
    cudaGetSymbolAddress((void**)&src2,   g_src2);
    cudaGetSymbolAddress((void**)&x,      g_x);
    cudaGetSymbolAddress((void**)&x_pk,   g_x_pk);
    cudaGetSymbolAddress((void**)&h_pk,   g_h_pk);
    cudaGetSymbolAddress((void**)&y,      g_y);
    cudaGetSymbolAddress((void**)&Wv_pk,  g_Wv_pk);
    cudaGetSymbolAddress((void**)&Woa_pk, g_Woa_pk);
    cudaGetSymbolAddress((void**)&Wp_pk,  g_Wp_pk);
    cudaGetSymbolAddress((void**)&W1_pk,  g_W1_pk);
    cudaGetSymbolAddress((void**)&W2_pk,  g_W2_pk);
    cudaGetSymbolAddress((void**)&bias_oa,g_bias_oa);

    cudaFuncSetAttribute(gemm_pl, cudaFuncAttributeMaxDynamicSharedMemorySize, SMEM_BYTES);

    const int T = TTOK;
    const int TM = (T + BM - 1) / BM;   // 171

    // 0) pack weights (+ concat bias_oa)
    pack_weights<<<(TOT_W + 384 + 255) / 256, 256>>>(Wv, Wo, Wa, Wp, W1, W2, bo, ba);

    // 1) build q / v_in
    build_qv_kernel<<<(TTOK * 128 + 255) / 256, 256>>>(src, pos, sel_vt, q_pk, vin, vin_pk);

    // 2) value = vin @ Wv^T + bv (masked)
    gemm_pl<<<dim3(TM, 4), 256, SMEM_BYTES>>>(vin_pk, Wv_pk, WV_W, bv, T, 128, 256,
                                              value, 256, nullptr, nullptr, 0, mask);
    // 3) [off | attn] = q @ [Wo;Wa]^T + [bo;ba]
    gemm_pl<<<dim3(TM, 6), 256, SMEM_BYTES>>>(q_pk, Woa_pk, WO_W + WA_W, bias_oa, T, 128, 384,
                                              off, 256, attn, nullptr, 0, nullptr);

    // 4) deformable sampling (softmax fused) -> fp16 packed samp
    msdeform_sample_kernel<<<TTOK, 256>>>(value, attn, off, ref, samp_pk);

    // 5) src2 = samp @ Wp^T + bp
    gemm_pl<<<dim3(TM, 4), 256, SMEM_BYTES>>>(samp_pk, Wp_pk, WP_W, bp, T, 128, 256,
                                              src2, 256, nullptr, nullptr, 0, nullptr);

    // 6) x = LN(vin + src2), also fp16 packed
    add_ln_kernel<<<TTOK, 256>>>(vin, src2, g1, be1, x, x_pk, 0);

    // 7) h = relu(x @ W1^T + bf1) -> fp16 packed only
    gemm_pl<<<dim3(TM, 16), 256, SMEM_BYTES>>>(x_pk, W1_pk, W1_W, bf1, T, 128, 1024,
                                               nullptr, 1024, nullptr, h_pk, 1, nullptr);
    // 8) y = h @ W2^T + bf2
    gemm_pl<<<dim3(TM, 4), 256, SMEM_BYTES>>>(h_pk, W2_pk, W2_W, bf2, T, 512, 256,
                                              y, 256, nullptr, nullptr, 0, nullptr);

    // 9) out = LN(x + y) scattered into [spatial | all_vt | vt] layout
    add_ln_kernel<<<TTOK, 256>>>(x, y, g2, be2, out, nullptr, 1);

    // 10) all_vt passthrough
    cudaMemcpyAsync(out + (size_t)N_BATCH * LSP * DMODEL, all_vt,
                    (size_t)N_BATCH * NALLVT * DMODEL * sizeof(float),
                    cudaMemcpyDeviceToDevice, 0);
}

// round 12
// speedup vs baseline: 2.1010x; 1.1262x over previous
#include <cuda_runtime.h>
#include <cuda_fp16.h>
#include <math.h>
#include <stdint.h>

#define N_BATCH 4
#define LQ      5448
#define LSP     5440
#define DMODEL  256
#define DFFN    1024
#define NVT     8
#define NALLVT  600
#define TTOK    (N_BATCH * LQ)   // 21792

// -------------------- scratch --------------------
__device__ uint32_t g_q_pk    [(size_t)TTOK * 128];
__device__ float    g_vin     [(size_t)TTOK * DMODEL];
__device__ uint32_t g_vin_pk  [(size_t)TTOK * 128];
__device__ uint32_t g_value_pk[(size_t)TTOK * 128];
__device__ float    g_off     [(size_t)TTOK * DMODEL];
__device__ float    g_attn    [(size_t)TTOK * 128];
__device__ uint32_t g_samp_pk [(size_t)TTOK * 128];
__device__ float    g_src2    [(size_t)TTOK * DMODEL];
__device__ float    g_x       [(size_t)TTOK * DMODEL];
__device__ uint32_t g_x_pk    [(size_t)TTOK * 128];
__device__ uint32_t g_h_pk    [(size_t)TTOK * 512];
__device__ float    g_y       [(size_t)TTOK * DMODEL];
// packed weights: dual-fp16 planar (hi plane then residual plane)
__device__ uint32_t g_Wv_pk [2 * 256 * 128];
__device__ uint32_t g_Woa_pk[2 * 384 * 128];
__device__ uint32_t g_Wp_pk [2 * 256 * 128];
__device__ uint32_t g_W1_pk [2 * 1024 * 128];
__device__ uint32_t g_W2_pk [2 * 256 * 512];
__device__ float    g_bias_oa[384];

// ==================== helpers ====================
__device__ __forceinline__ uint32_t smem_u32(const void* p) {
    return (uint32_t)__cvta_generic_to_shared(p);
}
__device__ __forceinline__ void cp_async16(uint32_t dst, const void* src, int src_size) {
    asm volatile("cp.async.cg.shared.global [%0], [%1], 16, %2;\n"
                 :: "r"(dst), "l"(src), "r"(src_size));
}
__device__ __forceinline__ void cp_async_commit() {
    asm volatile("cp.async.commit_group;" ::: "memory");
}
template<int N> __device__ __forceinline__ void cp_async_wait() {
    asm volatile("cp.async.wait_group %0;" :: "n"(N) : "memory");
}
__device__ __forceinline__ void ldm_x4(uint32_t addr, uint32_t& r0, uint32_t& r1,
                                       uint32_t& r2, uint32_t& r3) {
    asm volatile("ldmatrix.sync.aligned.m8n8.x4.shared.b16 {%0,%1,%2,%3}, [%4];"
                 : "=r"(r0), "=r"(r1), "=r"(r2), "=r"(r3) : "r"(addr));
}
__device__ __forceinline__ void mma16(float* d, const uint32_t* a, const uint32_t* b) {
    asm volatile(
        "mma.sync.aligned.m16n8k16.row.col.f32.f16.f16.f32 "
        "{%0,%1,%2,%3}, {%4,%5,%6,%7}, {%8,%9}, {%0,%1,%2,%3};"
        : "+f"(d[0]), "+f"(d[1]), "+f"(d[2]), "+f"(d[3])
        : "r"(a[0]), "r"(a[1]), "r"(a[2]), "r"(a[3]), "r"(b[0]), "r"(b[1]));
}
__device__ __forceinline__ uint32_t pack2h(float vx, float vy) {
    __half2 h = __floats2half2_rn(vx, vy);
    return *reinterpret_cast<uint32_t*>(&h);
}
__device__ __forceinline__ void wsplit2(float vx, float vy, uint32_t& hw, uint32_t& lw) {
    __half hx = __float2half_rn(vx);
    __half lx = __float2half_rn(vx - __half2float(hx));
    __half hy = __float2half_rn(vy);
    __half ly = __float2half_rn(vy - __half2float(hy));
    hw = (uint32_t)__half_as_ushort(hx) | ((uint32_t)__half_as_ushort(hy) << 16);
    lw = (uint32_t)__half_as_ushort(lx) | ((uint32_t)__half_as_ushort(ly) << 16);
}

// ==================== 2-term fp16 GEMM, 4-stage cp.async pipeline ====================
// out[T,Nout] = A[T,K] * (Wh + Wl)[Nout,K]^T + bias. KW = K/2 words per row.
#define BM 128
#define BN 64
#define STR 20
#define APL 2560
#define BPL 1280
#define BUFW 5120
#define STAGES 4
#define SMEM_BYTES (STAGES * BUFW * 4)

__global__ void __launch_bounds__(256, 2)
gemm_pl(const uint32_t* __restrict__ A,
        const uint32_t* __restrict__ Wt, size_t psW,
        const float* __restrict__ bias, int T, int KW, int Nout,
        float* __restrict__ outA, int split, float* __restrict__ outB,
        uint32_t* __restrict__ outPk,
        int relu, const unsigned char* __restrict__ mask)
{
    extern __shared__ __align__(16) uint32_t smem[];
    const uint32_t sm = smem_u32(smem);

    const int tid  = threadIdx.x;
    const int wid  = tid >> 5;
    const int lane = tid & 31;
    const int bm = blockIdx.x * BM;
    const int bn = blockIdx.y * BN;
    const int mbase = (wid & 3) * 32;
    const int nbase = (wid >> 2) * 32;
    const int gq = lane >> 2;
    const int tg = lane & 3;

    float acc[2][4][4];
#pragma unroll
    for (int mi = 0; mi < 2; mi++)
#pragma unroll
        for (int ni = 0; ni < 4; ni++)
#pragma unroll
            for (int r = 0; r < 4; r++) acc[mi][ni][r] = 0.f;

    auto load = [&](int kw0, int buf) {
        const uint32_t base = sm + buf * (BUFW * 4);
#pragma unroll
        for (int j = 0; j < 2; j++) {              // A: 128 rows x 4 chunks
            int o = tid + 256 * j;
            int row = o >> 2;
            int ch = o & 3;
            int gr = bm + row;
            const uint32_t* srcp = A + (size_t)(gr < T ? gr : 0) * KW + kw0 + ch * 4;
            cp_async16(base + (row * STR + ch * 4) * 4, srcp, gr < T ? 16 : 0);
        }
#pragma unroll
        for (int j = 0; j < 2; j++) {              // B: 2 planes x 64 rows x 4 chunks
            int o = tid + 256 * j;
            int plane = o >> 8;
            int oo = o & 255;
            int row = oo >> 2;
            int ch = oo & 3;
            const uint32_t* srcp = Wt + (size_t)plane * psW
                                      + (size_t)(bn + row) * KW + kw0 + ch * 4;
            cp_async16(base + (APL + plane * BPL + row * STR + ch * 4) * 4, srcp, 16);
        }
    };

    const int nch = KW >> 4;    // >= 8 always
    load(0, 0);  cp_async_commit();
    load(16, 1); cp_async_commit();
    load(32, 2); cp_async_commit();

    const int arow = lane & 15;
    const int acol = (lane >> 4) * 4;
    const int brow = (lane & 7) + ((lane >> 4) & 1) * 8;
    const int bcol = ((lane >> 3) & 1) * 4;

    for (int i = 0; i < nch; i++) {
        cp_async_wait<2>();
        __syncthreads();
        if (i + 3 < nch) load((i + 3) << 4, (i + 3) & 3);
        cp_async_commit();                      // empty groups keep numbering at tail

        const uint32_t base = sm + (i & 3) * (BUFW * 4);
        const uint32_t Aw = base;
        const uint32_t Bhi = base + APL * 4, Blo = Bhi + BPL * 4;

#pragma unroll
        for (int k16 = 0; k16 < 2; k16++) {
            const int kw = k16 * 8;
            uint32_t ah[2][4];
#pragma unroll
            for (int mi = 0; mi < 2; mi++) {
                uint32_t off = ((mbase + mi * 16 + arow) * STR + kw + acol) * 4;
                ldm_x4(Aw + off, ah[mi][0], ah[mi][1], ah[mi][2], ah[mi][3]);
            }
            uint32_t bh[4][2], bl[4][2];
#pragma unroll
            for (int hb = 0; hb < 2; hb++) {
                uint32_t off = ((nbase + hb * 16 + brow) * STR + kw + bcol) * 4;
                ldm_x4(Bhi + off, bh[hb*2][0], bh[hb*2][1], bh[hb*2+1][0], bh[hb*2+1][1]);
                ldm_x4(Blo + off, bl[hb*2][0], bl[hb*2][1], bl[hb*2+1][0], bl[hb*2+1][1]);
            }
#pragma unroll
            for (int mi = 0; mi < 2; mi++)
#pragma unroll
                for (int ng = 0; ng < 4; ng++) {
                    mma16(acc[mi][ng], ah[mi], bh[ng]);   // a * w_hi
                    mma16(acc[mi][ng], ah[mi], bl[ng]);   // a * w_lo
                }
        }
        __syncthreads();
    }

    // ---- epilogue ----
    const int wB = Nout - split;
    const int KWout = Nout >> 1;
#pragma unroll
    for (int mi = 0; mi < 2; mi++) {
#pragma unroll
        for (int half = 0; half < 2; half++) {
            int row = bm + mbase + mi * 16 + gq + half * 8;
            if (row >= T) continue;
            bool zero = (mask != nullptr) && (mask[row] != 0);
#pragma unroll
            for (int ni = 0; ni < 4; ni++) {
                int gc = bn + nbase + ni * 8 + tg * 2;
                float vx = acc[mi][ni][half * 2 + 0] + bias[gc];
                float vy = acc[mi][ni][half * 2 + 1] + bias[gc + 1];
                if (relu) { vx = fmaxf(vx, 0.f); vy = fmaxf(vy, 0.f); }
                if (zero) { vx = 0.f; vy = 0.f; }
                if (outPk)
                    outPk[(size_t)row * KWout + (gc >> 1)] = pack2h(vx, vy);
                if (outA) {
                    if (gc < split) {
                        float2 v; v.x = vx; v.y = vy;
                        *reinterpret_cast<float2*>(outA + (size_t)row * split + gc) = v;
                    } else if (outB) {
                        float2 v; v.x = vx; v.y = vy;
                        *reinterpret_cast<float2*>(outB + (size_t)row * wB + (gc - split)) = v;
                    }
                }
            }
        }
    }
}

// -------------------- weight packing --------------------
#define WV_W  32768
#define WO_W  32768
#define WA_W  16384
#define WP_W  32768
#define W1_W  131072
#define W2_W  131072
#define TOT_W (WV_W + WO_W + WA_W + WP_W + W1_W + W2_W)

__global__ void pack_weights(const float* __restrict__ Wv, const float* __restrict__ Wo,
                             const float* __restrict__ Wa, const float* __restrict__ Wp,
                             const float* __restrict__ W1, const float* __restrict__ W2,
                             const float* __restrict__ bo, const float* __restrict__ ba)
{
    int i = blockIdx.x * 256 + threadIdx.x;
    if (i < TOT_W) {
        const float* srcm; uint32_t* dst; int w; size_t ps;
        if (i < WV_W)                      { srcm = Wv; dst = g_Wv_pk;  w = i; ps = WV_W; }
        else if (i < WV_W + WO_W)          { srcm = Wo; dst = g_Woa_pk; w = i - WV_W; ps = WO_W + WA_W; }
        else if (i < WV_W + WO_W + WA_W)   { srcm = Wa; dst = g_Woa_pk + WO_W; w = i - WV_W - WO_W; ps = WO_W + WA_W; }
        else if (i < WV_W + WO_W + WA_W + WP_W)
                                           { srcm = Wp; dst = g_Wp_pk;  w = i - WV_W - WO_W - WA_W; ps = WP_W; }
        else if (i < TOT_W - W2_W)         { srcm = W1; dst = g_W1_pk;  w = i - (WV_W+WO_W+WA_W+WP_W); ps = W1_W; }
        else                               { srcm = W2; dst = g_W2_pk;  w = i - (TOT_W - W2_W); ps = W2_W; }
        float2 v = *reinterpret_cast<const float2*>(srcm + 2 * (size_t)w);
        uint32_t hw, lw;
        wsplit2(v.x, v.y, hw, lw);
        dst[w] = hw;
        dst[w + ps] = lw;
    } else if (i < TOT_W + 256) {
        g_bias_oa[i - TOT_W] = bo[i - TOT_W];
    } else if (i < TOT_W + 384) {
        g_bias_oa[i - TOT_W] = ba[i - TOT_W - 256];
    }
}

// -------------------- build q / v_in --------------------
__global__ void build_qv_kernel(const float* __restrict__ src, const float* __restrict__ pos,
                                const float* __restrict__ sel,
                                uint32_t* __restrict__ q_pk,
                                float* __restrict__ vin, uint32_t* __restrict__ vin_pk)
{
    size_t gid = (size_t)blockIdx.x * 256 + threadIdx.x;
    if (gid >= (size_t)TTOK * 128) return;
    int dw = (int)(gid & 127);
    size_t t = gid >> 7;
    int n = (int)(t / LQ);
    int i = (int)(t % LQ);
    float2 sv, pv;
    if (i < LSP) {
        size_t si = ((size_t)n * LSP + i) * DMODEL + dw * 2;
        sv = *reinterpret_cast<const float2*>(src + si);
        pv = *reinterpret_cast<const float2*>(pos + si);
    } else {
        size_t si = ((size_t)n * NVT + (i - LSP)) * DMODEL + dw * 2;
        sv = *reinterpret_cast<const float2*>(sel + si);
        pv.x = 0.f; pv.y = 0.f;
    }
    q_pk[gid]   = pack2h(sv.x + pv.x, sv.y + pv.y);
    vin_pk[gid] = pack2h(sv.x, sv.y);
    *reinterpret_cast<float2*>(vin + 2 * gid) = sv;
}

// -------------------- deformable sampling: warp per (token, head), fp16 value --------------------
// half-warp h handles sample 2*it+h; 16 lanes x half2 = 32 channels per head.
__global__ void msdeform_sample_kernel(const uint32_t* __restrict__ value_pk,
                                       const float* __restrict__ logits,
                                       const float* __restrict__ off,
                                       const float* __restrict__ ref,
                                       uint32_t* __restrict__ out_pk)
{
    const int nq   = blockIdx.x;
    const int n    = nq / LQ;
    const int m    = threadIdx.x >> 5;
    const int lane = threadIdx.x & 31;
    const int hl   = lane & 15;
    const int hf   = lane >> 4;

    const float* lg = logits + (size_t)nq * 128 + m * 16;
    float v = (lane < 16) ? lg[lane] : -1e30f;
    float mx = v;
#pragma unroll
    for (int o = 16; o > 0; o >>= 1) mx = fmaxf(mx, __shfl_xor_sync(0xffffffffu, mx, o));
    float e = (lane < 16) ? __expf(v - mx) : 0.f;
    float sm = e;
#pragma unroll
    for (int o = 16; o > 0; o >>= 1) sm += __shfl_xor_sync(0xffffffffu, sm, o);
    float wgt = e / sm;

    float offv = off[(size_t)nq * DMODEL + m * 32 + lane];
    float refv = (lane < 8) ? ref[(size_t)nq * 8 + lane] : 0.f;

    const uint32_t* vb = value_pk + (size_t)n * LQ * 128 + m * 16 + hl;

    const int HH[4] = {64, 32, 16, 8};
    const int WW[4] = {64, 32, 16, 8};
    const int ST[4] = {0, 4096, 5120, 5376};

    float accx = 0.f, accy = 0.f;
#pragma unroll
    for (int it = 0; it < 8; it++) {
        const int s = 2 * it + hf;
        const int l = s >> 2;
        float dx = __shfl_sync(0xffffffffu, offv, 2 * s);
        float dy = __shfl_sync(0xffffffffu, offv, 2 * s + 1);
        float rx = __shfl_sync(0xffffffffu, refv, 2 * l);
        float ry = __shfl_sync(0xffffffffu, refv, 2 * l + 1);
        float ws = __shfl_sync(0xffffffffu, wgt, s);
        const int H = HH[l], W = WW[l], st = ST[l];

        float x = rx * (float)W + dx - 0.5f;
        float y = ry * (float)H + dy - 0.5f;
        float xf = floorf(x), yf = floorf(y);
        int x0 = (int)xf, y0 = (int)yf;
        float wx = x - xf, wy = y - yf;

        float w00 = (1.f - wx) * (1.f - wy);
        float w10 = wx * (1.f - wy);
        float w01 = (1.f - wx) * wy;
        float w11 = wx * wy;

        float sx = 0.f, sy = 0.f;
        if (x0 >= 0 && x0 < W && y0 >= 0 && y0 < H) {
            float2 f = __half22float2(*reinterpret_cast<const __half2*>(
                vb + (size_t)(st + y0 * W + x0) * 128));
            sx += w00 * f.x; sy += w00 * f.y;
        }
        if (x0 + 1 >= 0 && x0 + 1 < W && y0 >= 0 && y0 < H) {
            float2 f = __half22float2(*reinterpret_cast<const __half2*>(
                vb + (size_t)(st + y0 * W + x0 + 1) * 128));
            sx += w10 * f.x; sy += w10 * f.y;
        }
        if (x0 >= 0 && x0 < W && y0 + 1 >= 0 && y0 + 1 < H) {
            float2 f = __half22float2(*reinterpret_cast<const __half2*>(
                vb + (size_t)(st + (y0 + 1) * W + x0) * 128));
            sx += w01 * f.x; sy += w01 * f.y;
        }
        if (x0 + 1 >= 0 && x0 + 1 < W && y0 + 1 >= 0 && y0 + 1 < H) {
            float2 f = __half22float2(*reinterpret_cast<const __half2*>(
                vb + (size_t)(st + (y0 + 1) * W + x0 + 1) * 128));
            sx += w11 * f.x; sy += w11 * f.y;
        }
        accx += ws * sx;
        accy += ws * sy;
    }
    accx += __shfl_xor_sync(0xffffffffu, accx, 16);
    accy += __shfl_xor_sync(0xffffffffu, accy, 16);
    if (lane < 16)
        out_pk[(size_t)nq * 128 + m * 16 + hl] = pack2h(accx, accy);
}

// -------------------- add + LayerNorm --------------------
__global__ void add_ln_kernel(const float* __restrict__ a, const float* __restrict__ b,
                              const float* __restrict__ g, const float* __restrict__ beta,
                              float* __restrict__ out, uint32_t* __restrict__ out_pk, int scatter)
{
    const int t = blockIdx.x;
    const int d = threadIdx.x;
    const int lane = d & 31, wid = d >> 5;

    float v = a[(size_t)t * DMODEL + d] + b[(size_t)t * DMODEL + d];

    __shared__ float red[8];
    float s = v;
#pragma unroll
    for (int o = 16; o > 0; o >>= 1) s += __shfl_xor_sync(0xffffffffu, s, o);
    if (lane == 0) red[wid] = s;
    __syncthreads();
    float mean;
    {
        if (d == 0) {
            float tot = 0.f;
#pragma unroll
            for (int i = 0; i < 8; i++) tot += red[i];
            red[0] = tot;
        }
        __syncthreads();
        mean = red[0] * (1.f / 256.f);
    }
    __syncthreads();

    float xc = v - mean;
    s = xc * xc;
#pragma unroll
    for (int o = 16; o > 0; o >>= 1) s += __shfl_xor_sync(0xffffffffu, s, o);
    if (lane == 0) red[wid] = s;
    __syncthreads();
    float var;
    {
        if (d == 0) {
            float tot = 0.f;
#pragma unroll
            for (int i = 0; i < 8; i++) tot += red[i];
            red[0] = tot;
        }
        __syncthreads();
        var = red[0] * (1.f / 256.f);
    }

    float r = g[d] * xc * rsqrtf(var + 1e-5f) + beta[d];

    if (out_pk) {
        float rn = __shfl_down_sync(0xffffffffu, r, 1);
        if ((d & 1) == 0)
            out_pk[(size_t)t * 128 + (d >> 1)] = pack2h(r, rn);
    }

    float* dst;
    if (!scatter) {
        dst = out + (size_t)t * DMODEL;
    } else {
        int n = t / LQ, i = t % LQ;
        if (i < LSP)
            dst = out + ((size_t)n * LSP + i) * DMODEL;
        else
            dst = out + ((size_t)N_BATCH * LSP + (size_t)N_BATCH * NALLVT) * DMODEL
                      + ((size_t)n * NVT + (i - LSP)) * DMODEL;
    }
    dst[d] = r;
}

// -------------------- launch --------------------
extern "C" void kernel_launch(void* const* d_in, const int* in_sizes, int n_in,
                              void* d_out, int out_size)
{
    const float* src  = (const float*)d_in[0];
    const float* pos  = (const float*)d_in[1];
    const float* ref  = (const float*)d_in[2];
    const unsigned char* mask = (const unsigned char*)d_in[5];
    const float* all_vt = (const float*)d_in[6];
    const float* sel_vt = (const float*)d_in[7];
    const float* Wv = (const float*)d_in[8];   const float* bv  = (const float*)d_in[9];
    const float* Wo = (const float*)d_in[10];  const float* bo  = (const float*)d_in[11];
    const float* Wa = (const float*)d_in[12];  const float* ba  = (const float*)d_in[13];
    const float* Wp = (const float*)d_in[14];  const float* bp  = (const float*)d_in[15];
    const float* g1 = (const float*)d_in[16];  const float* be1 = (const float*)d_in[17];
    const float* W1 = (const float*)d_in[18];  const float* bf1 = (const float*)d_in[19];
    const float* W2 = (const float*)d_in[20];  const float* bf2 = (const float*)d_in[21];
    const float* g2 = (const float*)d_in[22];  const float* be2 = (const float*)d_in[23];
    float* out = (float*)d_out;

    uint32_t *q_pk, *vin_pk, *value_pk, *samp_pk, *x_pk, *h_pk;
    uint32_t *Wv_pk, *Woa_pk, *Wp_pk, *W1_pk, *W2_pk;
    float *vin, *off, *attn, *src2, *x, *y, *bias_oa;
    cudaGetSymbolAddress((void**)&q_pk,    g_q_pk);
    cudaGetSymbolAddress((void**)&vin,     g_vin);
    cudaGetSymbolAddress((void**)&vin_pk,  g_vin_pk);
    cudaGetSymbolAddress((void**)&value_pk,g_value_pk);
    cudaGetSymbolAddress((void**)&off,     g_off);
    cudaGetSymbolAddress((void**)&attn,    g_attn);
    cudaGetSymbolAddress((void**)&samp_pk, g_samp_pk);
    cudaGetSymbolAddress((void**)&src2,    g_src2);
    cudaGetSymbolAddress((void**)&x,       g_x);
    cudaGetSymbolAddress((void**)&x_pk,    g_x_pk);
    cudaGetSymbolAddress((void**)&h_pk,    g_h_pk);
    cudaGetSymbolAddress((void**)&y,       g_y);
    cudaGetSymbolAddress((void**)&Wv_pk,   g_Wv_pk);
    cudaGetSymbolAddress((void**)&Woa_pk,  g_Woa_pk);
    cudaGetSymbolAddress((void**)&Wp_pk,   g_Wp_pk);
    cudaGetSymbolAddress((void**)&W1_pk,   g_W1_pk);
    cudaGetSymbolAddress((void**)&W2_pk,   g_W2_pk);
    cudaGetSymbolAddress((void**)&bias_oa, g_bias_oa);

    cudaFuncSetAttribute(gemm_pl, cudaFuncAttributeMaxDynamicSharedMemorySize, SMEM_BYTES);

    const int T = TTOK;
    const int TM = (T + BM - 1) / BM;   // 171

    // 0) pack weights (+ concat bias_oa)
    pack_weights<<<(TOT_W + 384 + 255) / 256, 256>>>(Wv, Wo, Wa, Wp, W1, W2, bo, ba);

    // 1) build q / v_in
    build_qv_kernel<<<(TTOK * 128 + 255) / 256, 256>>>(src, pos, sel_vt, q_pk, vin, vin_pk);

    // 2) value = vin @ Wv^T + bv (masked) -> fp16 packed only
    gemm_pl<<<dim3(TM, 4), 256, SMEM_BYTES>>>(vin_pk, Wv_pk, WV_W, bv, T, 128, 256,
                                              nullptr, 256, nullptr, value_pk, 0, mask);
    // 3) [off | attn] = q @ [Wo;Wa]^T + [bo;ba]
    gemm_pl<<<dim3(TM, 6), 256, SMEM_BYTES>>>(q_pk, Woa_pk, WO_W + WA_W, bias_oa, T, 128, 384,
                                              off, 256, attn, nullptr, 0, nullptr);

    // 4) deformable sampling (softmax fused) -> fp16 packed samp
    msdeform_sample_kernel<<<TTOK, 256>>>(value_pk, attn, off, ref, samp_pk);

    // 5) src2 = samp @ Wp^T + bp
    gemm_pl<<<dim3(TM, 4), 256, SMEM_BYTES>>>(samp_pk, Wp_pk, WP_W, bp, T, 128, 256,
                                              src2, 256, nullptr, nullptr, 0, nullptr);

    // 6) x = LN(vin + src2), also fp16 packed
    add_ln_kernel<<<TTOK, 256>>>(vin, src2, g1, be1, x, x_pk, 0);

    // 7) h = relu(x @ W1^T + bf1) -> fp16 packed only
    gemm_pl<<<dim3(TM, 16), 256, SMEM_BYTES>>>(x_pk, W1_pk, W1_W, bf1, T, 128, 1024,
                                               nullptr, 1024, nullptr, h_pk, 1, nullptr);
    // 8) y = h @ W2^T + bf2
    gemm_pl<<<dim3(TM, 4), 256, SMEM_BYTES>>>(h_pk, W2_pk, W2_W, bf2, T, 512, 256,
                                              y, 256, nullptr, nullptr, 0, nullptr);

    // 9) out = LN(x + y) scattered into [spatial | all_vt | vt] layout
    add_ln_kernel<<<TTOK, 256>>>(x, y, g2, be2, out, nullptr, 1);

    // 10) all_vt passthrough
    cudaMemcpyAsync(out + (size_t)N_BATCH * LSP * DMODEL, all_vt,
                    (size_t)N_BATCH * NALLVT * DMODEL * sizeof(float),
                    cudaMemcpyDeviceToDevice, 0);
}

// round 14
// speedup vs baseline: 2.4648x; 1.1732x over previous
#include <cuda_runtime.h>
#include <cuda_fp16.h>
#include <math.h>
#include <stdint.h>

#define N_BATCH 4
#define LQ      5448
#define LSP     5440
#define DMODEL  256
#define DFFN    1024
#define NVT     8
#define NALLVT  600
#define TTOK    (N_BATCH * LQ)   // 21792

// -------------------- scratch --------------------
__device__ uint32_t g_q_pk    [(size_t)TTOK * 128];
__device__ float    g_vin     [(size_t)TTOK * DMODEL];
__device__ uint32_t g_vin_pk  [(size_t)TTOK * 128];
__device__ uint32_t g_value_pk[(size_t)TTOK * 128];
__device__ float    g_off     [(size_t)TTOK * DMODEL];
__device__ float    g_attn    [(size_t)TTOK * 128];
__device__ uint32_t g_samp_pk [(size_t)TTOK * 128];
__device__ float    g_src2    [(size_t)TTOK * DMODEL];
__device__ float    g_x       [(size_t)TTOK * DMODEL];
__device__ uint32_t g_x_pk    [(size_t)TTOK * 128];
__device__ uint32_t g_h_pk    [(size_t)TTOK * 512];
__device__ float    g_y       [(size_t)TTOK * DMODEL];
// packed weights: single fp16 plane
__device__ uint32_t g_Wv_pk [256 * 128];
__device__ uint32_t g_Woa_pk[384 * 128];
__device__ uint32_t g_Wp_pk [256 * 128];
__device__ uint32_t g_W1_pk [1024 * 128];
__device__ uint32_t g_W2_pk [256 * 512];
__device__ float    g_bias_oa[384];

// ==================== helpers ====================
__device__ __forceinline__ uint32_t smem_u32(const void* p) {
    return (uint32_t)__cvta_generic_to_shared(p);
}
__device__ __forceinline__ void cp_async16(uint32_t dst, const void* src, int src_size) {
    asm volatile("cp.async.cg.shared.global [%0], [%1], 16, %2;\n"
                 :: "r"(dst), "l"(src), "r"(src_size));
}
__device__ __forceinline__ void cp_async_commit() {
    asm volatile("cp.async.commit_group;" ::: "memory");
}
template<int N> __device__ __forceinline__ void cp_async_wait() {
    asm volatile("cp.async.wait_group %0;" :: "n"(N) : "memory");
}
__device__ __forceinline__ void ldm_x4(uint32_t addr, uint32_t& r0, uint32_t& r1,
                                       uint32_t& r2, uint32_t& r3) {
    asm volatile("ldmatrix.sync.aligned.m8n8.x4.shared.b16 {%0,%1,%2,%3}, [%4];"
                 : "=r"(r0), "=r"(r1), "=r"(r2), "=r"(r3) : "r"(addr));
}
__device__ __forceinline__ void mma16(float* d, const uint32_t* a, const uint32_t* b) {
    asm volatile(
        "mma.sync.aligned.m16n8k16.row.col.f32.f16.f16.f32 "
        "{%0,%1,%2,%3}, {%4,%5,%6,%7}, {%8,%9}, {%0,%1,%2,%3};"
        : "+f"(d[0]), "+f"(d[1]), "+f"(d[2]), "+f"(d[3])
        : "r"(a[0]), "r"(a[1]), "r"(a[2]), "r"(a[3]), "r"(b[0]), "r"(b[1]));
}
__device__ __forceinline__ uint32_t pack2h(float vx, float vy) {
    __half2 h = __floats2half2_rn(vx, vy);
    return *reinterpret_cast<uint32_t*>(&h);
}

// ==================== fp16 GEMM, 4-stage cp.async pipeline ====================
// out[T,Nout] = A[T,K] * W[Nout,K]^T + bias. KW = K/2 words per row. fp32 accum.
#define BM 128
#define BN 64
#define STR 20
#define APL 2560            // A words per stage (128*20)
#define BPL 1280            // B words per stage (64*20)
#define BUFW 3840           // words per stage
#define STAGES 4
#define SMEM_BYTES (STAGES * BUFW * 4)

__global__ void __launch_bounds__(256, 2)
gemm_pl(const uint32_t* __restrict__ A,
        const uint32_t* __restrict__ Wt,
        const float* __restrict__ bias, int T, int KW, int Nout,
        float* __restrict__ outA, int split, float* __restrict__ outB,
        uint32_t* __restrict__ outPk,
        int relu, const unsigned char* __restrict__ mask)
{
    extern __shared__ __align__(16) uint32_t smem[];
    const uint32_t sm = smem_u32(smem);

    const int tid  = threadIdx.x;
    const int wid  = tid >> 5;
    const int lane = tid & 31;
    const int bm = blockIdx.x * BM;
    const int bn = blockIdx.y * BN;
    const int mbase = (wid & 3) * 32;
    const int nbase = (wid >> 2) * 32;
    const int gq = lane >> 2;
    const int tg = lane & 3;

    float acc[2][4][4];
#pragma unroll
    for (int mi = 0; mi < 2; mi++)
#pragma unroll
        for (int ni = 0; ni < 4; ni++)
#pragma unroll
            for (int r = 0; r < 4; r++) acc[mi][ni][r] = 0.f;

    auto load = [&](int kw0, int buf) {
        const uint32_t base = sm + buf * (BUFW * 4);
#pragma unroll
        for (int j = 0; j < 2; j++) {              // A: 128 rows x 4 chunks = 512
            int o = tid + 256 * j;
            int row = o >> 2;
            int ch = o & 3;
            int gr = bm + row;
            const uint32_t* srcp = A + (size_t)(gr < T ? gr : 0) * KW + kw0 + ch * 4;
            cp_async16(base + (row * STR + ch * 4) * 4, srcp, gr < T ? 16 : 0);
        }
        {                                          // B: 64 rows x 4 chunks = 256
            int row = tid >> 2;
            int ch = tid & 3;
            const uint32_t* srcp = Wt + (size_t)(bn + row) * KW + kw0 + ch * 4;
            cp_async16(base + (APL + row * STR + ch * 4) * 4, srcp, 16);
        }
        cp_async_commit();
    };

    const int nch = KW >> 4;    // >= 8 always
    load(0, 0);
    load(16, 1);
    load(32, 2);

    const int arow = lane & 15;
    const int acol = (lane >> 4) * 4;
    const int brow = (lane & 7) + ((lane >> 4) & 1) * 8;
    const int bcol = ((lane >> 3) & 1) * 4;

    for (int i = 0; i < nch; i++) {
        cp_async_wait<2>();
        __syncthreads();
        if (i + 3 < nch) load((i + 3) << 4, (i + 3) & 3);
        else cp_async_commit();                 // keep group numbering at tail

        const uint32_t base = sm + (i & 3) * (BUFW * 4);
        const uint32_t Aw = base;
        const uint32_t Bw = base + APL * 4;

#pragma unroll
        for (int k16 = 0; k16 < 2; k16++) {
            const int kw = k16 * 8;
            uint32_t ah[2][4];
#pragma unroll
            for (int mi = 0; mi < 2; mi++) {
                uint32_t off = ((mbase + mi * 16 + arow) * STR + kw + acol) * 4;
                ldm_x4(Aw + off, ah[mi][0], ah[mi][1], ah[mi][2], ah[mi][3]);
            }
            uint32_t bh[4][2];
#pragma unroll
            for (int hb = 0; hb < 2; hb++) {
                uint32_t off = ((nbase + hb * 16 + brow) * STR + kw + bcol) * 4;
                ldm_x4(Bw + off, bh[hb*2][0], bh[hb*2][1], bh[hb*2+1][0], bh[hb*2+1][1]);
            }
#pragma unroll
            for (int mi = 0; mi < 2; mi++)
#pragma unroll
                for (int ng = 0; ng < 4; ng++)
                    mma16(acc[mi][ng], ah[mi], bh[ng]);
        }
        __syncthreads();
    }

    // ---- epilogue ----
    const int wB = Nout - split;
    const int KWout = Nout >> 1;
#pragma unroll
    for (int mi = 0; mi < 2; mi++) {
#pragma unroll
        for (int half = 0; half < 2; half++) {
            int row = bm + mbase + mi * 16 + gq + half * 8;
            if (row >= T) continue;
            bool zero = (mask != nullptr) && (mask[row] != 0);
#pragma unroll
            for (int ni = 0; ni < 4; ni++) {
                int gc = bn + nbase + ni * 8 + tg * 2;
                float vx = acc[mi][ni][half * 2 + 0] + bias[gc];
                float vy = acc[mi][ni][half * 2 + 1] + bias[gc + 1];
                if (relu) { vx = fmaxf(vx, 0.f); vy = fmaxf(vy, 0.f); }
                if (zero) { vx = 0.f; vy = 0.f; }
                if (outPk)
                    outPk[(size_t)row * KWout + (gc >> 1)] = pack2h(vx, vy);
                if (outA) {
                    if (gc < split) {
                        float2 v; v.x = vx; v.y = vy;
                        *reinterpret_cast<float2*>(outA + (size_t)row * split + gc) = v;
                    } else if (outB) {
                        float2 v; v.x = vx; v.y = vy;
                        *reinterpret_cast<float2*>(outB + (size_t)row * wB + (gc - split)) = v;
                    }
                }
            }
        }
    }
}

// -------------------- weight packing (single fp16 plane) --------------------
#define WV_W  32768
#define WO_W  32768
#define WA_W  16384
#define WP_W  32768
#define W1_W  131072
#define W2_W  131072
#define TOT_W (WV_W + WO_W + WA_W + WP_W + W1_W + W2_W)

__global__ void pack_weights(const float* __restrict__ Wv, const float* __restrict__ Wo,
                             const float* __restrict__ Wa, const float* __restrict__ Wp,
                             const float* __restrict__ W1, const float* __restrict__ W2,
                             const float* __restrict__ bo, const float* __restrict__ ba)
{
    int i = blockIdx.x * 256 + threadIdx.x;
    if (i < TOT_W) {
        const float* srcm; uint32_t* dst; int w;
        if (i < WV_W)                      { srcm = Wv; dst = g_Wv_pk;  w = i; }
        else if (i < WV_W + WO_W)          { srcm = Wo; dst = g_Woa_pk; w = i - WV_W; }
        else if (i < WV_W + WO_W + WA_W)   { srcm = Wa; dst = g_Woa_pk + WO_W; w = i - WV_W - WO_W; }
        else if (i < WV_W + WO_W + WA_W + WP_W)
                                           { srcm = Wp; dst = g_Wp_pk;  w = i - WV_W - WO_W - WA_W; }
        else if (i < TOT_W - W2_W)         { srcm = W1; dst = g_W1_pk;  w = i - (WV_W+WO_W+WA_W+WP_W); }
        else                               { srcm = W2; dst = g_W2_pk;  w = i - (TOT_W - W2_W); }
        float2 v = *reinterpret_cast<const float2*>(srcm + 2 * (size_t)w);
        dst[w] = pack2h(v.x, v.y);
    } else if (i < TOT_W + 256) {
        g_bias_oa[i - TOT_W] = bo[i - TOT_W];
    } else if (i < TOT_W + 384) {
        g_bias_oa[i - TOT_W] = ba[i - TOT_W - 256];
    }
}

// -------------------- build q / v_in --------------------
__global__ void build_qv_kernel(const float* __restrict__ src, const float* __restrict__ pos,
                                const float* __restrict__ sel,
                                uint32_t* __restrict__ q_pk,
                                float* __restrict__ vin, uint32_t* __restrict__ vin_pk)
{
    size_t gid = (size_t)blockIdx.x * 256 + threadIdx.x;
    if (gid >= (size_t)TTOK * 128) return;
    int dw = (int)(gid & 127);
    size_t t = gid >> 7;
    int n = (int)(t / LQ);
    int i = (int)(t % LQ);
    float2 sv, pv;
    if (i < LSP) {
        size_t si = ((size_t)n * LSP + i) * DMODEL + dw * 2;
        sv = *reinterpret_cast<const float2*>(src + si);
        pv = *reinterpret_cast<const float2*>(pos + si);
    } else {
        size_t si = ((size_t)n * NVT + (i - LSP)) * DMODEL + dw * 2;
        sv = *reinterpret_cast<const float2*>(sel + si);
        pv.x = 0.f; pv.y = 0.f;
    }
    q_pk[gid]   = pack2h(sv.x + pv.x, sv.y + pv.y);
    vin_pk[gid] = pack2h(sv.x, sv.y);
    *reinterpret_cast<float2*>(vin + 2 * gid) = sv;
}

// -------------------- deformable sampling: warp per (token, head), fp16 value --------------------
__global__ void msdeform_sample_kernel(const uint32_t* __restrict__ value_pk,
                                       const float* __restrict__ logits,
                                       const float* __restrict__ off,
                                       const float* __restrict__ ref,
                                       uint32_t* __restrict__ out_pk)
{
    const int nq   = blockIdx.x;
    const int n    = nq / LQ;
    const int m    = threadIdx.x >> 5;
    const int lane = threadIdx.x & 31;
    const int hl   = lane & 15;
    const int hf   = lane >> 4;

    const float* lg = logits + (size_t)nq * 128 + m * 16;
    float v = (lane < 16) ? lg[lane] : -1e30f;
    float mx = v;
#pragma unroll
    for (int o = 16; o > 0; o >>= 1) mx = fmaxf(mx, __shfl_xor_sync(0xffffffffu, mx, o));
    float e = (lane < 16) ? __expf(v - mx) : 0.f;
    float sm = e;
#pragma unroll
    for (int o = 16; o > 0; o >>= 1) sm += __shfl_xor_sync(0xffffffffu, sm, o);
    float wgt = e / sm;

    float offv = off[(size_t)nq * DMODEL + m * 32 + lane];
    float refv = (lane < 8) ? ref[(size_t)nq * 8 + lane] : 0.f;

    const uint32_t* vb = value_pk + (size_t)n * LQ * 128 + m * 16 + hl;

    const int HH[4] = {64, 32, 16, 8};
    const int WW[4] = {64, 32, 16, 8};
    const int ST[4] = {0, 4096, 5120, 5376};

    float accx = 0.f, accy = 0.f;
#pragma unroll
    for (int it = 0; it < 8; it++) {
        const int s = 2 * it + hf;
        const int l = s >> 2;
        float dx = __shfl_sync(0xffffffffu, offv, 2 * s);
        float dy = __shfl_sync(0xffffffffu, offv, 2 * s + 1);
        float rx = __shfl_sync(0xffffffffu, refv, 2 * l);
        float ry = __shfl_sync(0xffffffffu, refv, 2 * l + 1);
        float ws = __shfl_sync(0xffffffffu, wgt, s);
        const int H = HH[l], W = WW[l], st = ST[l];

        float x = rx * (float)W + dx - 0.5f;
        float y = ry * (float)H + dy - 0.5f;
        float xf = floorf(x), yf = floorf(y);
        int x0 = (int)xf, y0 = (int)yf;
        float wx = x - xf, wy = y - yf;

        float w00 = (1.f - wx) * (1.f - wy);
        float w10 = wx * (1.f - wy);
        float w01 = (1.f - wx) * wy;
        float w11 = wx * wy;

        float sx = 0.f, sy = 0.f;
        if (x0 >= 0 && x0 < W && y0 >= 0 && y0 < H) {
            float2 f = __half22float2(*reinterpret_cast<const __half2*>(
                vb + (size_t)(st + y0 * W + x0) * 128));
            sx += w00 * f.x; sy += w00 * f.y;
        }
        if (x0 + 1 >= 0 && x0 + 1 < W && y0 >= 0 && y0 < H) {
            float2 f = __half22float2(*reinterpret_cast<const __half2*>(
                vb + (size_t)(st + y0 * W + x0 + 1) * 128));
            sx += w10 * f.x; sy += w10 * f.y;
        }
        if (x0 >= 0 && x0 < W && y0 + 1 >= 0 && y0 + 1 < H) {
            float2 f = __half22float2(*reinterpret_cast<const __half2*>(
                vb + (size_t)(st + (y0 + 1) * W + x0) * 128));
            sx += w01 * f.x; sy += w01 * f.y;
        }
        if (x0 + 1 >= 0 && x0 + 1 < W && y0 + 1 >= 0 && y0 + 1 < H) {
            float2 f = __half22float2(*reinterpret_cast<const __half2*>(
                vb + (size_t)(st + (y0 + 1) * W + x0 + 1) * 128));
            sx += w11 * f.x; sy += w11 * f.y;
        }
        accx += ws * sx;
        accy += ws * sy;
    }
    accx += __shfl_xor_sync(0xffffffffu, accx, 16);
    accy += __shfl_xor_sync(0xffffffffu, accy, 16);
    if (lane < 16)
        out_pk[(size_t)nq * 128 + m * 16 + hl] = pack2h(accx, accy);
}

// -------------------- add + LayerNorm --------------------
__global__ void add_ln_kernel(const float* __restrict__ a, const float* __restrict__ b,
                              const float* __restrict__ g, const float* __restrict__ beta,
                              float* __restrict__ out, uint32_t* __restrict__ out_pk, int scatter)
{
    const int t = blockIdx.x;
    const int d = threadIdx.x;
    const int lane = d & 31, wid = d >> 5;

    float v = a[(size_t)t * DMODEL + d] + b[(size_t)t * DMODEL + d];

    __shared__ float red[8];
    float s = v;
#pragma unroll
    for (int o = 16; o > 0; o >>= 1) s += __shfl_xor_sync(0xffffffffu, s, o);
    if (lane == 0) red[wid] = s;
    __syncthreads();
    float mean;
    {
        if (d == 0) {
            float tot = 0.f;
#pragma unroll
            for (int i = 0; i < 8; i++) tot += red[i];
            red[0] = tot;
        }
        __syncthreads();
        mean = red[0] * (1.f / 256.f);
    }
    __syncthreads();

    float xc = v - mean;
    s = xc * xc;
#pragma unroll
    for (int o = 16; o > 0; o >>= 1) s += __shfl_xor_sync(0xffffffffu, s, o);
    if (lane == 0) red[wid] = s;
    __syncthreads();
    float var;
    {
        if (d == 0) {
            float tot = 0.f;
#pragma unroll
            for (int i = 0; i < 8; i++) tot += red[i];
            red[0] = tot;
        }
        __syncthreads();
        var = red[0] * (1.f / 256.f);
    }

    float r = g[d] * xc * rsqrtf(var + 1e-5f) + beta[d];

    if (out_pk) {
        float rn = __shfl_down_sync(0xffffffffu, r, 1);
        if ((d & 1) == 0)
            out_pk[(size_t)t * 128 + (d >> 1)] = pack2h(r, rn);
    }

    float* dst;
    if (!scatter) {
        dst = out + (size_t)t * DMODEL;
    } else {
        int n = t / LQ, i = t % LQ;
        if (i < LSP)
            dst = out + ((size_t)n * LSP + i) * DMODEL;
        else
            dst = out + ((size_t)N_BATCH * LSP + (size_t)N_BATCH * NALLVT) * DMODEL
                      + ((size_t)n * NVT + (i - LSP)) * DMODEL;
    }
    dst[d] = r;
}

// -------------------- launch --------------------
extern "C" void kernel_launch(void* const* d_in, const int* in_sizes, int n_in,
                              void* d_out, int out_size)
{
    const float* src  = (const float*)d_in[0];
    const float* pos  = (const float*)d_in[1];
    const float* ref  = (const float*)d_in[2];
    const unsigned char* mask = (const unsigned char*)d_in[5];
    const float* all_vt = (const float*)d_in[6];
    const float* sel_vt = (const float*)d_in[7];
    const float* Wv = (const float*)d_in[8];   const float* bv  = (const float*)d_in[9];
    const float* Wo = (const float*)d_in[10];  const float* bo  = (const float*)d_in[11];
    const float* Wa = (const float*)d_in[12];  const float* ba  = (const float*)d_in[13];
    const float* Wp = (const float*)d_in[14];  const float* bp  = (const float*)d_in[15];
    const float* g1 = (const float*)d_in[16];  const float* be1 = (const float*)d_in[17];
    const float* W1 = (const float*)d_in[18];  const float* bf1 = (const float*)d_in[19];
    const float* W2 = (const float*)d_in[20];  const float* bf2 = (const float*)d_in[21];
    const float* g2 = (const float*)d_in[22];  const float* be2 = (const float*)d_in[23];
    float* out = (float*)d_out;

    uint32_t *q_pk, *vin_pk, *value_pk, *samp_pk, *x_pk, *h_pk;
    uint32_t *Wv_pk, *Woa_pk, *Wp_pk, *W1_pk, *W2_pk;
    float *vin, *off, *attn, *src2, *x, *y, *bias_oa;
    cudaGetSymbolAddress((void**)&q_pk,    g_q_pk);
    cudaGetSymbolAddress((void**)&vin,     g_vin);
    cudaGetSymbolAddress((void**)&vin_pk,  g_vin_pk);
    cudaGetSymbolAddress((void**)&value_pk,g_value_pk);
    cudaGetSymbolAddress((void**)&off,     g_off);
    cudaGetSymbolAddress((void**)&attn,    g_attn);
    cudaGetSymbolAddress((void**)&samp_pk, g_samp_pk);
    cudaGetSymbolAddress((void**)&src2,    g_src2);
    cudaGetSymbolAddress((void**)&x,       g_x);
    cudaGetSymbolAddress((void**)&x_pk,    g_x_pk);
    cudaGetSymbolAddress((void**)&h_pk,    g_h_pk);
    cudaGetSymbolAddress((void**)&y,       g_y);
    cudaGetSymbolAddress((void**)&Wv_pk,   g_Wv_pk);
    cudaGetSymbolAddress((void**)&Woa_pk,  g_Woa_pk);
    cudaGetSymbolAddress((void**)&Wp_pk,   g_Wp_pk);
    cudaGetSymbolAddress((void**)&W1_pk,   g_W1_pk);
    cudaGetSymbolAddress((void**)&W2_pk,   g_W2_pk);
    cudaGetSymbolAddress((void**)&bias_oa, g_bias_oa);

    cudaFuncSetAttribute(gemm_pl, cudaFuncAttributeMaxDynamicSharedMemorySize, SMEM_BYTES);

    const int T = TTOK;
    const int TM = (T + BM - 1) / BM;   // 171

    // 0) pack weights (+ concat bias_oa)
    pack_weights<<<(TOT_W + 384 + 255) / 256, 256>>>(Wv, Wo, Wa, Wp, W1, W2, bo, ba);

    // 1) build q / v_in
    build_qv_kernel<<<(TTOK * 128 + 255) / 256, 256>>>(src, pos, sel_vt, q_pk, vin, vin_pk);

    // 2) value = vin @ Wv^T + bv (masked) -> fp16 packed only
    gemm_pl<<<dim3(TM, 4), 256, SMEM_BYTES>>>(vin_pk, Wv_pk, bv, T, 128, 256,
                                              nullptr, 256, nullptr, value_pk, 0, mask);
    // 3) [off | attn] = q @ [Wo;Wa]^T + [bo;ba]
    gemm_pl<<<dim3(TM, 6), 256, SMEM_BYTES>>>(q_pk, Woa_pk, bias_oa, T, 128, 384,
                                              off, 256, attn, nullptr, 0, nullptr);

    // 4) deformable sampling (softmax fused) -> fp16 packed samp
    msdeform_sample_kernel<<<TTOK, 256>>>(value_pk, attn, off, ref, samp_pk);

    // 5) src2 = samp @ Wp^T + bp
    gemm_pl<<<dim3(TM, 4), 256, SMEM_BYTES>>>(samp_pk, Wp_pk, bp, T, 128, 256,
                                              src2, 256, nullptr, nullptr, 0, nullptr);

    // 6) x = LN(vin + src2), also fp16 packed
    add_ln_kernel<<<TTOK, 256>>>(vin, src2, g1, be1, x, x_pk, 0);

    // 7) h = relu(x @ W1^T + bf1) -> fp16 packed only
    gemm_pl<<<dim3(TM, 16), 256, SMEM_BYTES>>>(x_pk, W1_pk, bf1, T, 128, 1024,
                                               nullptr, 1024, nullptr, h_pk, 1, nullptr);
    // 8) y = h @ W2^T + bf2
    gemm_pl<<<dim3(TM, 4), 256, SMEM_BYTES>>>(h_pk, W2_pk, bf2, T, 512, 256,
                                              y, 256, nullptr, nullptr, 0, nullptr);

    // 9) out = LN(x + y) scattered into [spatial | all_vt | vt] layout
    add_ln_kernel<<<TTOK, 256>>>(x, y, g2, be2, out, nullptr, 1);

    // 10) all_vt passthrough
    cudaMemcpyAsync(out + (size_t)N_BATCH * LSP * DMODEL, all_vt,
                    (size_t)N_BATCH * NALLVT * DMODEL * sizeof(float),
                    cudaMemcpyDeviceToDevice, 0);
}

// round 15
// speedup vs baseline: 2.8097x; 1.1399x over previous
#include <cuda_runtime.h>
#include <cuda_fp16.h>
#include <math.h>
#include <stdint.h>

#define N_BATCH 4
#define LQ      5448
#define LSP     5440
#define DMODEL  256
#define DFFN    1024
#define NVT     8
#define NALLVT  600
#define TTOK    (N_BATCH * LQ)   // 21792

// -------------------- scratch --------------------
__device__ uint32_t g_q_pk    [(size_t)TTOK * 128];
__device__ float    g_vin     [(size_t)TTOK * DMODEL];
__device__ uint32_t g_vin_pk  [(size_t)TTOK * 128];
__device__ uint32_t g_value_pk[(size_t)TTOK * 128];
__device__ float    g_off     [(size_t)TTOK * DMODEL];
__device__ float    g_attn    [(size_t)TTOK * 128];
__device__ uint32_t g_samp_pk [(size_t)TTOK * 128];
__device__ float    g_src2    [(size_t)TTOK * DMODEL];
__device__ float    g_x       [(size_t)TTOK * DMODEL];
__device__ uint32_t g_x_pk    [(size_t)TTOK * 128];
__device__ uint32_t g_h_pk    [(size_t)TTOK * 512];
__device__ float    g_y       [(size_t)TTOK * DMODEL];
// packed weights: single fp16 plane
__device__ uint32_t g_Wv_pk [256 * 128];
__device__ uint32_t g_Woa_pk[384 * 128];
__device__ uint32_t g_Wp_pk [256 * 128];
__device__ uint32_t g_W1_pk [1024 * 128];
__device__ uint32_t g_W2_pk [256 * 512];
__device__ float    g_bias_oa[384];

// ==================== helpers ====================
__device__ __forceinline__ uint32_t smem_u32(const void* p) {
    return (uint32_t)__cvta_generic_to_shared(p);
}
__device__ __forceinline__ void cp_async16(uint32_t dst, const void* src, int src_size) {
    asm volatile("cp.async.cg.shared.global [%0], [%1], 16, %2;\n"
                 :: "r"(dst), "l"(src), "r"(src_size));
}
__device__ __forceinline__ void cp_async_commit() {
    asm volatile("cp.async.commit_group;" ::: "memory");
}
template<int N> __device__ __forceinline__ void cp_async_wait() {
    asm volatile("cp.async.wait_group %0;" :: "n"(N) : "memory");
}
__device__ __forceinline__ void ldm_x4(uint32_t addr, uint32_t& r0, uint32_t& r1,
                                       uint32_t& r2, uint32_t& r3) {
    asm volatile("ldmatrix.sync.aligned.m8n8.x4.shared.b16 {%0,%1,%2,%3}, [%4];"
                 : "=r"(r0), "=r"(r1), "=r"(r2), "=r"(r3) : "r"(addr));
}
__device__ __forceinline__ void mma16(float* d, const uint32_t* a, const uint32_t* b) {
    asm volatile(
        "mma.sync.aligned.m16n8k16.row.col.f32.f16.f16.f32 "
        "{%0,%1,%2,%3}, {%4,%5,%6,%7}, {%8,%9}, {%0,%1,%2,%3};"
        : "+f"(d[0]), "+f"(d[1]), "+f"(d[2]), "+f"(d[3])
        : "r"(a[0]), "r"(a[1]), "r"(a[2]), "r"(a[3]), "r"(b[0]), "r"(b[1]));
}
__device__ __forceinline__ uint32_t pack2h(float vx, float vy) {
    __half2 h = __floats2half2_rn(vx, vy);
    return *reinterpret_cast<uint32_t*>(&h);
}

// ==================== fp16 GEMM body: CTA 128x128, 8 warps, warp 32x64 ====================
#define BM 128
#define BN 128
#define STR 20
#define APL 2560            // A words per stage (128*20)
#define BUFW 5120           // words per stage (A + B)
#define STAGES 4
#define SMEM_BYTES (STAGES * BUFW * 4)

__device__ __forceinline__ void gemm_body(
    const uint32_t* __restrict__ A, const uint32_t* __restrict__ Wt,
    const float* __restrict__ bias, int T, int KW, int Nout, int bm, int bn,
    float* __restrict__ outA, int split, float* __restrict__ outB,
    uint32_t* __restrict__ outPk, int relu, const unsigned char* __restrict__ mask,
    uint32_t sm)
{
    const int tid  = threadIdx.x;
    const int wid  = tid >> 5;
    const int lane = tid & 31;
    const int mbase = (wid & 3) * 32;
    const int nbase = (wid >> 2) * 64;
    const int gq = lane >> 2;
    const int tg = lane & 3;

    float acc[2][8][4];
#pragma unroll
    for (int mi = 0; mi < 2; mi++)
#pragma unroll
        for (int ni = 0; ni < 8; ni++)
#pragma unroll
            for (int r = 0; r < 4; r++) acc[mi][ni][r] = 0.f;

    auto load = [&](int kw0, int buf) {
        const uint32_t base = sm + buf * (BUFW * 4);
#pragma unroll
        for (int j = 0; j < 4; j++) {          // 1024 chunks: 512 A + 512 B
            int o = tid + 256 * j;
            if (o < 512) {
                int row = o >> 2, ch = o & 3;
                int gr = bm + row;
                const uint32_t* srcp = A + (size_t)(gr < T ? gr : 0) * KW + kw0 + ch * 4;
                cp_async16(base + (row * STR + ch * 4) * 4, srcp, gr < T ? 16 : 0);
            } else {
                int oo = o - 512;
                int row = oo >> 2, ch = oo & 3;
                const uint32_t* srcp = Wt + (size_t)(bn + row) * KW + kw0 + ch * 4;
                cp_async16(base + (APL + row * STR + ch * 4) * 4, srcp, 16);
            }
        }
        cp_async_commit();
    };

    const int nch = KW >> 4;
    load(0, 0);
    load(16, 1);
    load(32, 2);

    const int arow = lane & 15;
    const int acol = (lane >> 4) * 4;
    const int brow = (lane & 7) + ((lane >> 4) & 1) * 8;
    const int bcol = ((lane >> 3) & 1) * 4;

    for (int i = 0; i < nch; i++) {
        cp_async_wait<2>();
        __syncthreads();
        if (i + 3 < nch) load((i + 3) << 4, (i + 3) & 3);
        else cp_async_commit();

        const uint32_t base = sm + (i & 3) * (BUFW * 4);
        const uint32_t Aw = base;
        const uint32_t Bw = base + APL * 4;

#pragma unroll
        for (int k16 = 0; k16 < 2; k16++) {
            const int kw = k16 * 8;
            uint32_t ah[2][4];
#pragma unroll
            for (int mi = 0; mi < 2; mi++) {
                uint32_t off = ((mbase + mi * 16 + arow) * STR + kw + acol) * 4;
                ldm_x4(Aw + off, ah[mi][0], ah[mi][1], ah[mi][2], ah[mi][3]);
            }
            uint32_t bh[8][2];
#pragma unroll
            for (int hb = 0; hb < 4; hb++) {
                uint32_t off = ((nbase + hb * 16 + brow) * STR + kw + bcol) * 4;
                ldm_x4(Bw + off, bh[hb*2][0], bh[hb*2][1], bh[hb*2+1][0], bh[hb*2+1][1]);
            }
#pragma unroll
            for (int mi = 0; mi < 2; mi++)
#pragma unroll
                for (int ng = 0; ng < 8; ng++)
                    mma16(acc[mi][ng], ah[mi], bh[ng]);
        }
        __syncthreads();
    }

    // ---- epilogue ----
    const int wB = Nout - split;
    const int KWout = Nout >> 1;
#pragma unroll
    for (int mi = 0; mi < 2; mi++) {
#pragma unroll
        for (int half = 0; half < 2; half++) {
            int row = bm + mbase + mi * 16 + gq + half * 8;
            if (row >= T) continue;
            bool zero = (mask != nullptr) && (mask[row] != 0);
#pragma unroll
            for (int ni = 0; ni < 8; ni++) {
                int gc = bn + nbase + ni * 8 + tg * 2;
                float vx = acc[mi][ni][half * 2 + 0] + bias[gc];
                float vy = acc[mi][ni][half * 2 + 1] + bias[gc + 1];
                if (relu) { vx = fmaxf(vx, 0.f); vy = fmaxf(vy, 0.f); }
                if (zero) { vx = 0.f; vy = 0.f; }
                if (outPk)
                    outPk[(size_t)row * KWout + (gc >> 1)] = pack2h(vx, vy);
                if (outA) {
                    if (gc < split) {
                        float2 v; v.x = vx; v.y = vy;
                        *reinterpret_cast<float2*>(outA + (size_t)row * split + gc) = v;
                    } else if (outB) {
                        float2 v; v.x = vx; v.y = vy;
                        *reinterpret_cast<float2*>(outB + (size_t)row * wB + (gc - split)) = v;
                    }
                }
            }
        }
    }
}

// generic single-GEMM wrapper
__global__ void __launch_bounds__(256, 2)
gemm_pl(const uint32_t* __restrict__ A, const uint32_t* __restrict__ Wt,
        const float* __restrict__ bias, int T, int KW, int Nout,
        float* __restrict__ outA, int split, float* __restrict__ outB,
        uint32_t* __restrict__ outPk, int relu, const unsigned char* __restrict__ mask)
{
    extern __shared__ __align__(16) uint32_t smem[];
    gemm_body(A, Wt, bias, T, KW, Nout, blockIdx.x * BM, blockIdx.y * BN,
              outA, split, outB, outPk, relu, mask, smem_u32(smem));
}

// fused value (y<2) + off|attn (y>=2) wrapper
__global__ void __launch_bounds__(256, 2)
gemm_voa(const uint32_t* __restrict__ vin_pk, const uint32_t* __restrict__ Wv,
         const float* __restrict__ bv, uint32_t* __restrict__ value_pk,
         const unsigned char* __restrict__ mask,
         const uint32_t* __restrict__ q_pk, const uint32_t* __restrict__ Woa,
         const float* __restrict__ bias_oa, float* __restrict__ off,
         float* __restrict__ attn, int T)
{
    extern __shared__ __align__(16) uint32_t smem[];
    const int y = blockIdx.y;
    const bool isv = (y < 2);
    gemm_body(isv ? vin_pk : q_pk,
              isv ? Wv : Woa,
              isv ? bv : bias_oa,
              T, 128,
              isv ? 256 : 384,
              blockIdx.x * BM,
              (isv ? y : (y - 2)) * BN,
              isv ? nullptr : off, 256,
              isv ? nullptr : attn,
              isv ? value_pk : nullptr,
              0,
              isv ? mask : nullptr,
              smem_u32(smem));
}

// -------------------- weight packing --------------------
#define WV_W  32768
#define WO_W  32768
#define WA_W  16384
#define WP_W  32768
#define W1_W  131072
#define W2_W  131072
#define TOT_W (WV_W + WO_W + WA_W + WP_W + W1_W + W2_W)

__global__ void pack_weights(const float* __restrict__ Wv, const float* __restrict__ Wo,
                             const float* __restrict__ Wa, const float* __restrict__ Wp,
                             const float* __restrict__ W1, const float* __restrict__ W2,
                             const float* __restrict__ bo, const float* __restrict__ ba)
{
    int i = blockIdx.x * 256 + threadIdx.x;
    if (i < TOT_W) {
        const float* srcm; uint32_t* dst; int w;
        if (i < WV_W)                      { srcm = Wv; dst = g_Wv_pk;  w = i; }
        else if (i < WV_W + WO_W)          { srcm = Wo; dst = g_Woa_pk; w = i - WV_W; }
        else if (i < WV_W + WO_W + WA_W)   { srcm = Wa; dst = g_Woa_pk + WO_W; w = i - WV_W - WO_W; }
        else if (i < WV_W + WO_W + WA_W + WP_W)
                                           { srcm = Wp; dst = g_Wp_pk;  w = i - WV_W - WO_W - WA_W; }
        else if (i < TOT_W - W2_W)         { srcm = W1; dst = g_W1_pk;  w = i - (WV_W+WO_W+WA_W+WP_W); }
        else                               { srcm = W2; dst = g_W2_pk;  w = i - (TOT_W - W2_W); }
        float2 v = *reinterpret_cast<const float2*>(srcm + 2 * (size_t)w);
        dst[w] = pack2h(v.x, v.y);
    } else if (i < TOT_W + 256) {
        g_bias_oa[i - TOT_W] = bo[i - TOT_W];
    } else if (i < TOT_W + 384) {
        g_bias_oa[i - TOT_W] = ba[i - TOT_W - 256];
    }
}

// -------------------- build q / v_in --------------------
__global__ void build_qv_kernel(const float* __restrict__ src, const float* __restrict__ pos,
                                const float* __restrict__ sel,
                                uint32_t* __restrict__ q_pk,
                                float* __restrict__ vin, uint32_t* __restrict__ vin_pk)
{
    size_t gid = (size_t)blockIdx.x * 256 + threadIdx.x;
    if (gid >= (size_t)TTOK * 128) return;
    int dw = (int)(gid & 127);
    size_t t = gid >> 7;
    int n = (int)(t / LQ);
    int i = (int)(t % LQ);
    float2 sv, pv;
    if (i < LSP) {
        size_t si = ((size_t)n * LSP + i) * DMODEL + dw * 2;
        sv = *reinterpret_cast<const float2*>(src + si);
        pv = *reinterpret_cast<const float2*>(pos + si);
    } else {
        size_t si = ((size_t)n * NVT + (i - LSP)) * DMODEL + dw * 2;
        sv = *reinterpret_cast<const float2*>(sel + si);
        pv.x = 0.f; pv.y = 0.f;
    }
    q_pk[gid]   = pack2h(sv.x + pv.x, sv.y + pv.y);
    vin_pk[gid] = pack2h(sv.x, sv.y);
    *reinterpret_cast<float2*>(vin + 2 * gid) = sv;
}

// -------------------- deformable sampling --------------------
__global__ void msdeform_sample_kernel(const uint32_t* __restrict__ value_pk,
                                       const float* __restrict__ logits,
                                       const float* __restrict__ off,
                                       const float* __restrict__ ref,
                                       uint32_t* __restrict__ out_pk)
{
    const int nq   = blockIdx.x;
    const int n    = nq / LQ;
    const int m    = threadIdx.x >> 5;
    const int lane = threadIdx.x & 31;
    const int hl   = lane & 15;
    const int hf   = lane >> 4;

    const float* lg = logits + (size_t)nq * 128 + m * 16;
    float v = (lane < 16) ? lg[lane] : -1e30f;
    float mx = v;
#pragma unroll
    for (int o = 16; o > 0; o >>= 1) mx = fmaxf(mx, __shfl_xor_sync(0xffffffffu, mx, o));
    float e = (lane < 16) ? __expf(v - mx) : 0.f;
    float sm = e;
#pragma unroll
    for (int o = 16; o > 0; o >>= 1) sm += __shfl_xor_sync(0xffffffffu, sm, o);
    float wgt = e / sm;

    float offv = off[(size_t)nq * DMODEL + m * 32 + lane];
    float refv = (lane < 8) ? ref[(size_t)nq * 8 + lane] : 0.f;

    const uint32_t* vb = value_pk + (size_t)n * LQ * 128 + m * 16 + hl;

    const int HH[4] = {64, 32, 16, 8};
    const int WW[4] = {64, 32, 16, 8};
    const int ST[4] = {0, 4096, 5120, 5376};

    float accx = 0.f, accy = 0.f;
#pragma unroll
    for (int it = 0; it < 8; it++) {
        const int s = 2 * it + hf;
        const int l = s >> 2;
        float dx = __shfl_sync(0xffffffffu, offv, 2 * s);
        float dy = __shfl_sync(0xffffffffu, offv, 2 * s + 1);
        float rx = __shfl_sync(0xffffffffu, refv, 2 * l);
        float ry = __shfl_sync(0xffffffffu, refv, 2 * l + 1);
        float ws = __shfl_sync(0xffffffffu, wgt, s);
        const int H = HH[l], W = WW[l], st = ST[l];

        float x = rx * (float)W + dx - 0.5f;
        float y = ry * (float)H + dy - 0.5f;
        float xf = floorf(x), yf = floorf(y);
        int x0 = (int)xf, y0 = (int)yf;
        float wx = x - xf, wy = y - yf;

        float w00 = (1.f - wx) * (1.f - wy);
        float w10 = wx * (1.f - wy);
        float w01 = (1.f - wx) * wy;
        float w11 = wx * wy;

        float sx = 0.f, sy = 0.f;
        if (x0 >= 0 && x0 < W && y0 >= 0 && y0 < H) {
            float2 f = __half22float2(*reinterpret_cast<const __half2*>(
                vb + (size_t)(st + y0 * W + x0) * 128));
            sx += w00 * f.x; sy += w00 * f.y;
        }
        if (x0 + 1 >= 0 && x0 + 1 < W && y0 >= 0 && y0 < H) {
            float2 f = __half22float2(*reinterpret_cast<const __half2*>(
                vb + (size_t)(st + y0 * W + x0 + 1) * 128));
            sx += w10 * f.x; sy += w10 * f.y;
        }
        if (x0 >= 0 && x0 < W && y0 + 1 >= 0 && y0 + 1 < H) {
            float2 f = __half22float2(*reinterpret_cast<const __half2*>(
                vb + (size_t)(st + (y0 + 1) * W + x0) * 128));
            sx += w01 * f.x; sy += w01 * f.y;
        }
        if (x0 + 1 >= 0 && x0 + 1 < W && y0 + 1 >= 0 && y0 + 1 < H) {
            float2 f = __half22float2(*reinterpret_cast<const __half2*>(
                vb + (size_t)(st + (y0 + 1) * W + x0 + 1) * 128));
            sx += w11 * f.x; sy += w11 * f.y;
        }
        accx += ws * sx;
        accy += ws * sy;
    }
    accx += __shfl_xor_sync(0xffffffffu, accx, 16);
    accy += __shfl_xor_sync(0xffffffffu, accy, 16);
    if (lane < 16)
        out_pk[(size_t)nq * 128 + m * 16 + hl] = pack2h(accx, accy);
}

// -------------------- add + LayerNorm: warp per token, 8 tokens/block --------------------
__global__ void add_ln_kernel(const float* __restrict__ a, const float* __restrict__ b,
                              const float* __restrict__ g, const float* __restrict__ beta,
                              float* __restrict__ out, uint32_t* __restrict__ out_pk, int scatter)
{
    const int wid  = threadIdx.x >> 5;
    const int lane = threadIdx.x & 31;
    const int t = blockIdx.x * 8 + wid;

    const float4* ap = reinterpret_cast<const float4*>(a + (size_t)t * DMODEL);
    const float4* bp = reinterpret_cast<const float4*>(b + (size_t)t * DMODEL);
    float4 v0, v1;
    {
        float4 x0 = ap[lane * 2],     y0 = bp[lane * 2];
        float4 x1 = ap[lane * 2 + 1], y1 = bp[lane * 2 + 1];
        v0.x = x0.x + y0.x; v0.y = x0.y + y0.y; v0.z = x0.z + y0.z; v0.w = x0.w + y0.w;
        v1.x = x1.x + y1.x; v1.y = x1.y + y1.y; v1.z = x1.z + y1.z; v1.w = x1.w + y1.w;
    }

    float s = v0.x + v0.y + v0.z + v0.w + v1.x + v1.y + v1.z + v1.w;
#pragma unroll
    for (int o = 16; o > 0; o >>= 1) s += __shfl_xor_sync(0xffffffffu, s, o);
    const float mean = s * (1.f / 256.f);

    float c0x = v0.x - mean, c0y = v0.y - mean, c0z = v0.z - mean, c0w = v0.w - mean;
    float c1x = v1.x - mean, c1y = v1.y - mean, c1z = v1.z - mean, c1w = v1.w - mean;
    float q = c0x*c0x + c0y*c0y + c0z*c0z + c0w*c0w + c1x*c1x + c1y*c1y + c1z*c1z + c1w*c1w;
#pragma unroll
    for (int o = 16; o > 0; o >>= 1) q += __shfl_xor_sync(0xffffffffu, q, o);
    const float rstd = rsqrtf(q * (1.f / 256.f) + 1e-5f);

    const float4* gp = reinterpret_cast<const float4*>(g);
    const float4* ep = reinterpret_cast<const float4*>(beta);
    float4 g0 = gp[lane * 2], g1 = gp[lane * 2 + 1];
    float4 e0 = ep[lane * 2], e1 = ep[lane * 2 + 1];

    float4 r0, r1;
    r0.x = g0.x * c0x * rstd + e0.x; r0.y = g0.y * c0y * rstd + e0.y;
    r0.z = g0.z * c0z * rstd + e0.z; r0.w = g0.w * c0w * rstd + e0.w;
    r1.x = g1.x * c1x * rstd + e1.x; r1.y = g1.y * c1y * rstd + e1.y;
    r1.z = g1.z * c1z * rstd + e1.z; r1.w = g1.w * c1w * rstd + e1.w;

    if (out_pk) {
        uint4 p;
        p.x = pack2h(r0.x, r0.y); p.y = pack2h(r0.z, r0.w);
        p.z = pack2h(r1.x, r1.y); p.w = pack2h(r1.z, r1.w);
        *reinterpret_cast<uint4*>(out_pk + (size_t)t * 128 + lane * 4) = p;
    }

    float* dst;
    if (!scatter) {
        dst = out + (size_t)t * DMODEL;
    } else {
        int n = t / LQ, i = t % LQ;
        if (i < LSP)
            dst = out + ((size_t)n * LSP + i) * DMODEL;
        else
            dst = out + ((size_t)N_BATCH * LSP + (size_t)N_BATCH * NALLVT) * DMODEL
                      + ((size_t)n * NVT + (i - LSP)) * DMODEL;
    }
    float4* dp = reinterpret_cast<float4*>(dst);
    dp[lane * 2]     = r0;
    dp[lane * 2 + 1] = r1;
}

// -------------------- launch --------------------
extern "C" void kernel_launch(void* const* d_in, const int* in_sizes, int n_in,
                              void* d_out, int out_size)
{
    const float* src  = (const float*)d_in[0];
    const float* pos  = (const float*)d_in[1];
    const float* ref  = (const float*)d_in[2];
    const unsigned char* mask = (const unsigned char*)d_in[5];
    const float* all_vt = (const float*)d_in[6];
    const float* sel_vt = (const float*)d_in[7];
    const float* Wv = (const float*)d_in[8];   const float* bv  = (const float*)d_in[9];
    const float* Wo = (const float*)d_in[10];  const float* bo  = (const float*)d_in[11];
    const float* Wa = (const float*)d_in[12];  const float* ba  = (const float*)d_in[13];
    const float* Wp = (const float*)d_in[14];  const float* bp  = (const float*)d_in[15];
    const float* g1 = (const float*)d_in[16];  const float* be1 = (const float*)d_in[17];
    const float* W1 = (const float*)d_in[18];  const float* bf1 = (const float*)d_in[19];
    const float* W2 = (const float*)d_in[20];  const float* bf2 = (const float*)d_in[21];
    const float* g2 = (const float*)d_in[22];  const float* be2 = (const float*)d_in[23];
    float* out = (float*)d_out;

    uint32_t *q_pk, *vin_pk, *value_pk, *samp_pk, *x_pk, *h_pk;
    uint32_t *Wv_pk, *Woa_pk, *Wp_pk, *W1_pk, *W2_pk;
    float *vin, *off, *attn, *src2, *x, *y, *bias_oa;
    cudaGetSymbolAddress((void**)&q_pk,    g_q_pk);
    cudaGetSymbolAddress((void**)&vin,     g_vin);
    cudaGetSymbolAddress((void**)&vin_pk,  g_vin_pk);
    cudaGetSymbolAddress((void**)&value_pk,g_value_pk);
    cudaGetSymbolAddress((void**)&off,     g_off);
    cudaGetSymbolAddress((void**)&attn,    g_attn);
    cudaGetSymbolAddress((void**)&samp_pk, g_samp_pk);
    cudaGetSymbolAddress((void**)&src2,    g_src2);
    cudaGetSymbolAddress((void**)&x,       g_x);
    cudaGetSymbolAddress((void**)&x_pk,    g_x_pk);
    cudaGetSymbolAddress((void**)&h_pk,    g_h_pk);
    cudaGetSymbolAddress((void**)&y,       g_y);
    cudaGetSymbolAddress((void**)&Wv_pk,   g_Wv_pk);
    cudaGetSymbolAddress((void**)&Woa_pk,  g_Woa_pk);
    cudaGetSymbolAddress((void**)&Wp_pk,   g_Wp_pk);
    cudaGetSymbolAddress((void**)&W1_pk,   g_W1_pk);
    cudaGetSymbolAddress((void**)&W2_pk,   g_W2_pk);
    cudaGetSymbolAddress((void**)&bias_oa, g_bias_oa);

    cudaFuncSetAttribute(gemm_pl,  cudaFuncAttributeMaxDynamicSharedMemorySize, SMEM_BYTES);
    cudaFuncSetAttribute(gemm_voa, cudaFuncAttributeMaxDynamicSharedMemorySize, SMEM_BYTES);

    const int T = TTOK;
    const int TM = (T + BM - 1) / BM;   // 171

    // 0) pack weights (+ concat bias_oa)
    pack_weights<<<(TOT_W + 384 + 255) / 256, 256>>>(Wv, Wo, Wa, Wp, W1, W2, bo, ba);

    // 1) build q / v_in
    build_qv_kernel<<<(TTOK * 128 + 255) / 256, 256>>>(src, pos, sel_vt, q_pk, vin, vin_pk);

    // 2+3) fused: value = vin@Wv^T+bv (masked, fp16) ; [off|attn] = q@[Wo;Wa]^T+[bo;ba]
    gemm_voa<<<dim3(TM, 5), 256, SMEM_BYTES>>>(vin_pk, Wv_pk, bv, value_pk, mask,
                                               q_pk, Woa_pk, bias_oa, off, attn, T);

    // 4) deformable sampling (softmax fused) -> fp16 packed samp
    msdeform_sample_kernel<<<TTOK, 256>>>(value_pk, attn, off, ref, samp_pk);

    // 5) src2 = samp @ Wp^T + bp
    gemm_pl<<<dim3(TM, 2), 256, SMEM_BYTES>>>(samp_pk, Wp_pk, bp, T, 128, 256,
                                              src2, 256, nullptr, nullptr, 0, nullptr);

    // 6) x = LN(vin + src2), also fp16 packed
    add_ln_kernel<<<TTOK / 8, 256>>>(vin, src2, g1, be1, x, x_pk, 0);

    // 7) h = relu(x @ W1^T + bf1) -> fp16 packed only
    gemm_pl<<<dim3(TM, 8), 256, SMEM_BYTES>>>(x_pk, W1_pk, bf1, T, 128, 1024,
                                              nullptr, 1024, nullptr, h_pk, 1, nullptr);
    // 8) y = h @ W2^T + bf2
    gemm_pl<<<dim3(TM, 2), 256, SMEM_BYTES>>>(h_pk, W2_pk, bf2, T, 512, 256,
                                              y, 256, nullptr, nullptr, 0, nullptr);

    // 9) out = LN(x + y) scattered into [spatial | all_vt | vt] layout
    add_ln_kernel<<<TTOK / 8, 256>>>(x, y, g2, be2, out, nullptr, 1);

    // 10) all_vt passthrough
    cudaMemcpyAsync(out + (size_t)N_BATCH * LSP * DMODEL, all_vt,
                    (size_t)N_BATCH * NALLVT * DMODEL * sizeof(float),
                    cudaMemcpyDeviceToDevice, 0);
}

// round 16
// speedup vs baseline: 3.0739x; 1.0940x over previous
#include <cuda_runtime.h>
#include <cuda_fp16.h>
#include <math.h>
#include <stdint.h>

#define N_BATCH 4
#define LQ      5448
#define LSP     5440
#define DMODEL  256
#define DFFN    1024
#define NVT     8
#define NALLVT  600
#define TTOK    (N_BATCH * LQ)   // 21792

// -------------------- scratch --------------------
__device__ uint32_t g_q_pk    [(size_t)TTOK * 128];
__device__ float    g_vin     [(size_t)TTOK * DMODEL];
__device__ uint32_t g_vin_pk  [(size_t)TTOK * 128];
__device__ uint32_t g_value_pk[(size_t)TTOK * 128];
__device__ float    g_off     [(size_t)TTOK * DMODEL];
__device__ float    g_attn    [(size_t)TTOK * 128];
__device__ uint32_t g_samp_pk [(size_t)TTOK * 128];
__device__ float    g_src2    [(size_t)TTOK * DMODEL];
__device__ float    g_x       [(size_t)TTOK * DMODEL];
__device__ uint32_t g_x_pk    [(size_t)TTOK * 128];
__device__ uint32_t g_h_pk    [(size_t)TTOK * 512];
__device__ float    g_y       [(size_t)TTOK * DMODEL];
// packed weights: single fp16 plane
__device__ uint32_t g_Wv_pk [256 * 128];
__device__ uint32_t g_Woa_pk[384 * 128];
__device__ uint32_t g_Wp_pk [256 * 128];
__device__ uint32_t g_W1_pk [1024 * 128];
__device__ uint32_t g_W2_pk [256 * 512];
__device__ float    g_bias_oa[384];

// ==================== helpers ====================
__device__ __forceinline__ uint32_t smem_u32(const void* p) {
    return (uint32_t)__cvta_generic_to_shared(p);
}
__device__ __forceinline__ void cp_async16(uint32_t dst, const void* src, int src_size) {
    asm volatile("cp.async.cg.shared.global [%0], [%1], 16, %2;\n"
                 :: "r"(dst), "l"(src), "r"(src_size));
}
__device__ __forceinline__ void cp_async_commit() {
    asm volatile("cp.async.commit_group;" ::: "memory");
}
template<int N> __device__ __forceinline__ void cp_async_wait() {
    asm volatile("cp.async.wait_group %0;" :: "n"(N) : "memory");
}
__device__ __forceinline__ void ldm_x4(uint32_t addr, uint32_t& r0, uint32_t& r1,
                                       uint32_t& r2, uint32_t& r3) {
    asm volatile("ldmatrix.sync.aligned.m8n8.x4.shared.b16 {%0,%1,%2,%3}, [%4];"
                 : "=r"(r0), "=r"(r1), "=r"(r2), "=r"(r3) : "r"(addr));
}
__device__ __forceinline__ void mma16(float* d, const uint32_t* a, const uint32_t* b) {
    asm volatile(
        "mma.sync.aligned.m16n8k16.row.col.f32.f16.f16.f32 "
        "{%0,%1,%2,%3}, {%4,%5,%6,%7}, {%8,%9}, {%0,%1,%2,%3};"
        : "+f"(d[0]), "+f"(d[1]), "+f"(d[2]), "+f"(d[3])
        : "r"(a[0]), "r"(a[1]), "r"(a[2]), "r"(a[3]), "r"(b[0]), "r"(b[1]));
}
__device__ __forceinline__ uint32_t pack2h(float vx, float vy) {
    __half2 h = __floats2half2_rn(vx, vy);
    return *reinterpret_cast<uint32_t*>(&h);
}

// ==================== fp16 GEMM body: CTA 128x128, 8 warps, warp 32x64 ====================
#define BM 128
#define BN 128
#define STR 20
#define APL 2560
#define BUFW 5120
#define STAGES 4
#define SMEM_BYTES (STAGES * BUFW * 4)

__device__ __forceinline__ void gemm_body(
    const uint32_t* __restrict__ A, const uint32_t* __restrict__ Wt,
    const float* __restrict__ bias, int T, int KW, int Nout, int bm, int bn,
    float* __restrict__ outA, int split, float* __restrict__ outB,
    uint32_t* __restrict__ outPk, int relu, const unsigned char* __restrict__ mask,
    uint32_t sm)
{
    const int tid  = threadIdx.x;
    const int wid  = tid >> 5;
    const int lane = tid & 31;
    const int mbase = (wid & 3) * 32;
    const int nbase = (wid >> 2) * 64;
    const int gq = lane >> 2;
    const int tg = lane & 3;

    float acc[2][8][4];
#pragma unroll
    for (int mi = 0; mi < 2; mi++)
#pragma unroll
        for (int ni = 0; ni < 8; ni++)
#pragma unroll
            for (int r = 0; r < 4; r++) acc[mi][ni][r] = 0.f;

    auto load = [&](int kw0, int buf) {
        const uint32_t base = sm + buf * (BUFW * 4);
#pragma unroll
        for (int j = 0; j < 4; j++) {
            int o = tid + 256 * j;
            if (o < 512) {
                int row = o >> 2, ch = o & 3;
                int gr = bm + row;
                const uint32_t* srcp = A + (size_t)(gr < T ? gr : 0) * KW + kw0 + ch * 4;
                cp_async16(base + (row * STR + ch * 4) * 4, srcp, gr < T ? 16 : 0);
            } else {
                int oo = o - 512;
                int row = oo >> 2, ch = oo & 3;
                const uint32_t* srcp = Wt + (size_t)(bn + row) * KW + kw0 + ch * 4;
                cp_async16(base + (APL + row * STR + ch * 4) * 4, srcp, 16);
            }
        }
        cp_async_commit();
    };

    const int nch = KW >> 4;
    load(0, 0);
    load(16, 1);
    load(32, 2);

    const int arow = lane & 15;
    const int acol = (lane >> 4) * 4;
    const int brow = (lane & 7) + ((lane >> 4) & 1) * 8;
    const int bcol = ((lane >> 3) & 1) * 4;

    for (int i = 0; i < nch; i++) {
        cp_async_wait<2>();
        __syncthreads();
        if (i + 3 < nch) load((i + 3) << 4, (i + 3) & 3);
        else cp_async_commit();

        const uint32_t base = sm + (i & 3) * (BUFW * 4);
        const uint32_t Aw = base;
        const uint32_t Bw = base + APL * 4;

#pragma unroll
        for (int k16 = 0; k16 < 2; k16++) {
            const int kw = k16 * 8;
            uint32_t ah[2][4];
#pragma unroll
            for (int mi = 0; mi < 2; mi++) {
                uint32_t off = ((mbase + mi * 16 + arow) * STR + kw + acol) * 4;
                ldm_x4(Aw + off, ah[mi][0], ah[mi][1], ah[mi][2], ah[mi][3]);
            }
            uint32_t bh[8][2];
#pragma unroll
            for (int hb = 0; hb < 4; hb++) {
                uint32_t off = ((nbase + hb * 16 + brow) * STR + kw + bcol) * 4;
                ldm_x4(Bw + off, bh[hb*2][0], bh[hb*2][1], bh[hb*2+1][0], bh[hb*2+1][1]);
            }
#pragma unroll
            for (int mi = 0; mi < 2; mi++)
#pragma unroll
                for (int ng = 0; ng < 8; ng++)
                    mma16(acc[mi][ng], ah[mi], bh[ng]);
        }
        __syncthreads();
    }

    const int wB = Nout - split;
    const int KWout = Nout >> 1;
#pragma unroll
    for (int mi = 0; mi < 2; mi++) {
#pragma unroll
        for (int half = 0; half < 2; half++) {
            int row = bm + mbase + mi * 16 + gq + half * 8;
            if (row >= T) continue;
            bool zero = (mask != nullptr) && (mask[row] != 0);
#pragma unroll
            for (int ni = 0; ni < 8; ni++) {
                int gc = bn + nbase + ni * 8 + tg * 2;
                float vx = acc[mi][ni][half * 2 + 0] + bias[gc];
                float vy = acc[mi][ni][half * 2 + 1] + bias[gc + 1];
                if (relu) { vx = fmaxf(vx, 0.f); vy = fmaxf(vy, 0.f); }
                if (zero) { vx = 0.f; vy = 0.f; }
                if (outPk)
                    outPk[(size_t)row * KWout + (gc >> 1)] = pack2h(vx, vy);
                if (outA) {
                    if (gc < split) {
                        float2 v; v.x = vx; v.y = vy;
                        *reinterpret_cast<float2*>(outA + (size_t)row * split + gc) = v;
                    } else if (outB) {
                        float2 v; v.x = vx; v.y = vy;
                        *reinterpret_cast<float2*>(outB + (size_t)row * wB + (gc - split)) = v;
                    }
                }
            }
        }
    }
}

__global__ void __launch_bounds__(256, 2)
gemm_pl(const uint32_t* __restrict__ A, const uint32_t* __restrict__ Wt,
        const float* __restrict__ bias, int T, int KW, int Nout,
        float* __restrict__ outA, int split, float* __restrict__ outB,
        uint32_t* __restrict__ outPk, int relu, const unsigned char* __restrict__ mask)
{
    extern __shared__ __align__(16) uint32_t smem[];
    gemm_body(A, Wt, bias, T, KW, Nout, blockIdx.x * BM, blockIdx.y * BN,
              outA, split, outB, outPk, relu, mask, smem_u32(smem));
}

__global__ void __launch_bounds__(256, 2)
gemm_voa(const uint32_t* __restrict__ vin_pk, const uint32_t* __restrict__ Wv,
         const float* __restrict__ bv, uint32_t* __restrict__ value_pk,
         const unsigned char* __restrict__ mask,
         const uint32_t* __restrict__ q_pk, const uint32_t* __restrict__ Woa,
         const float* __restrict__ bias_oa, float* __restrict__ off,
         float* __restrict__ attn, int T)
{
    extern __shared__ __align__(16) uint32_t smem[];
    const int y = blockIdx.y;
    const bool isv = (y < 2);
    gemm_body(isv ? vin_pk : q_pk,
              isv ? Wv : Woa,
              isv ? bv : bias_oa,
              T, 128,
              isv ? 256 : 384,
              blockIdx.x * BM,
              (isv ? y : (y - 2)) * BN,
              isv ? nullptr : off, 256,
              isv ? nullptr : attn,
              isv ? value_pk : nullptr,
              0,
              isv ? mask : nullptr,
              smem_u32(smem));
}

// -------------------- weight packing --------------------
#define WV_W  32768
#define WO_W  32768
#define WA_W  16384
#define WP_W  32768
#define W1_W  131072
#define W2_W  131072
#define TOT_W (WV_W + WO_W + WA_W + WP_W + W1_W + W2_W)

__global__ void pack_weights(const float* __restrict__ Wv, const float* __restrict__ Wo,
                             const float* __restrict__ Wa, const float* __restrict__ Wp,
                             const float* __restrict__ W1, const float* __restrict__ W2,
                             const float* __restrict__ bo, const float* __restrict__ ba)
{
    int i = blockIdx.x * 256 + threadIdx.x;
    if (i < TOT_W) {
        const float* srcm; uint32_t* dst; int w;
        if (i < WV_W)                      { srcm = Wv; dst = g_Wv_pk;  w = i; }
        else if (i < WV_W + WO_W)          { srcm = Wo; dst = g_Woa_pk; w = i - WV_W; }
        else if (i < WV_W + WO_W + WA_W)   { srcm = Wa; dst = g_Woa_pk + WO_W; w = i - WV_W - WO_W; }
        else if (i < WV_W + WO_W + WA_W + WP_W)
                                           { srcm = Wp; dst = g_Wp_pk;  w = i - WV_W - WO_W - WA_W; }
        else if (i < TOT_W - W2_W)         { srcm = W1; dst = g_W1_pk;  w = i - (WV_W+WO_W+WA_W+WP_W); }
        else                               { srcm = W2; dst = g_W2_pk;  w = i - (TOT_W - W2_W); }
        float2 v = *reinterpret_cast<const float2*>(srcm + 2 * (size_t)w);
        dst[w] = pack2h(v.x, v.y);
    } else if (i < TOT_W + 256) {
        g_bias_oa[i - TOT_W] = bo[i - TOT_W];
    } else if (i < TOT_W + 384) {
        g_bias_oa[i - TOT_W] = ba[i - TOT_W - 256];
    }
}

// -------------------- build q / v_in --------------------
__global__ void build_qv_kernel(const float* __restrict__ src, const float* __restrict__ pos,
                                const float* __restrict__ sel,
                                uint32_t* __restrict__ q_pk,
                                float* __restrict__ vin, uint32_t* __restrict__ vin_pk)
{
    size_t gid = (size_t)blockIdx.x * 256 + threadIdx.x;
    if (gid >= (size_t)TTOK * 128) return;
    int dw = (int)(gid & 127);
    size_t t = gid >> 7;
    int n = (int)(t / LQ);
    int i = (int)(t % LQ);
    float2 sv, pv;
    if (i < LSP) {
        size_t si = ((size_t)n * LSP + i) * DMODEL + dw * 2;
        sv = *reinterpret_cast<const float2*>(src + si);
        pv = *reinterpret_cast<const float2*>(pos + si);
    } else {
        size_t si = ((size_t)n * NVT + (i - LSP)) * DMODEL + dw * 2;
        sv = *reinterpret_cast<const float2*>(sel + si);
        pv.x = 0.f; pv.y = 0.f;
    }
    q_pk[gid]   = pack2h(sv.x + pv.x, sv.y + pv.y);
    vin_pk[gid] = pack2h(sv.x, sv.y);
    *reinterpret_cast<float2*>(vin + 2 * gid) = sv;
}

// -------------------- deformable sampling: 2-phase, precomputed idx+weights --------------------
__global__ void msdeform_sample_kernel(const uint32_t* __restrict__ value_pk,
                                       const float* __restrict__ logits,
                                       const float* __restrict__ off,
                                       const float* __restrict__ ref,
                                       uint32_t* __restrict__ out_pk)
{
    const int nq   = blockIdx.x;
    const int n    = nq / LQ;
    const int m    = threadIdx.x >> 5;
    const int lane = threadIdx.x & 31;
    const int hl   = lane & 15;
    const int hf   = lane >> 4;

    // softmax over 16 logits (lane s < 16 holds weight for sample s)
    const float* lg = logits + (size_t)nq * 128 + m * 16;
    float v = (lane < 16) ? lg[lane] : -1e30f;
    float mx = v;
#pragma unroll
    for (int o = 16; o > 0; o >>= 1) mx = fmaxf(mx, __shfl_xor_sync(0xffffffffu, mx, o));
    float e = (lane < 16) ? __expf(v - mx) : 0.f;
    float sm = e;
#pragma unroll
    for (int o = 16; o > 0; o >>= 1) sm += __shfl_xor_sync(0xffffffffu, sm, o);
    float wgt = e / sm;

    float offv = off[(size_t)nq * DMODEL + m * 32 + lane];
    float refv = (lane < 8) ? ref[(size_t)nq * 8 + lane] : 0.f;

    const int HH[4] = {64, 32, 16, 8};
    const int ST[4] = {0, 4096, 5120, 5376};

    // ---- phase 1: lane s computes indices + ws-premultiplied weights for sample s ----
    const int l_  = (lane >> 2) & 3;
    float dx = __shfl_sync(0xffffffffu, offv, (2 * lane) & 31);
    float dy = __shfl_sync(0xffffffffu, offv, (2 * lane + 1) & 31);
    float rx = __shfl_sync(0xffffffffu, refv, 2 * l_);
    float ry = __shfl_sync(0xffffffffu, refv, 2 * l_ + 1);
    const int Wd = HH[l_], st_ = ST[l_];

    float x = rx * (float)Wd + dx - 0.5f;
    float y = ry * (float)Wd + dy - 0.5f;
    float xf = floorf(x), yf = floorf(y);
    int x0 = (int)xf, y0 = (int)yf;
    float wx = x - xf, wy = y - yf;

    bool vx0 = (x0 >= 0) && (x0 < Wd);
    bool vx1 = (x0 + 1 >= 0) && (x0 + 1 < Wd);
    bool vy0 = (y0 >= 0) && (y0 < Wd);
    bool vy1 = (y0 + 1 >= 0) && (y0 + 1 < Wd);

    float w00 = (vx0 && vy0) ? wgt * (1.f - wx) * (1.f - wy) : 0.f;
    float w10 = (vx1 && vy0) ? wgt * wx * (1.f - wy) : 0.f;
    float w01 = (vx0 && vy1) ? wgt * (1.f - wx) * wy : 0.f;
    float w11 = (vx1 && vy1) ? wgt * wx * wy : 0.f;

    int base = st_ + y0 * Wd + x0;
    uint32_t c00 = (vx0 && vy0) ? (uint32_t)base : 0u;
    uint32_t c10 = (vx1 && vy0) ? (uint32_t)(base + 1) : 0u;
    uint32_t c01 = (vx0 && vy1) ? (uint32_t)(base + Wd) : 0u;
    uint32_t c11 = (vx1 && vy1) ? (uint32_t)(base + Wd + 1) : 0u;

    uint32_t idxA = c00 | (c10 << 16);
    uint32_t idxB = c01 | (c11 << 16);
    uint32_t wpkA = pack2h(w00, w10);
    uint32_t wpkB = pack2h(w01, w11);

    // ---- phase 2: gather + accumulate (half-warp hf handles sample 2*it+hf) ----
    const uint32_t* vb = value_pk + (size_t)n * LQ * 128 + m * 16 + hl;

    float accx = 0.f, accy = 0.f;
#pragma unroll
    for (int it = 0; it < 8; it++) {
        int srcl = 2 * it + hf;
        uint32_t uA = __shfl_sync(0xffffffffu, idxA, srcl);
        uint32_t uB = __shfl_sync(0xffffffffu, idxB, srcl);
        uint32_t pA = __shfl_sync(0xffffffffu, wpkA, srcl);
        uint32_t pB = __shfl_sync(0xffffffffu, wpkB, srcl);
        float2 wA = __half22float2(*reinterpret_cast<__half2*>(&pA));
        float2 wB = __half22float2(*reinterpret_cast<__half2*>(&pB));
        float2 f;
        f = __half22float2(*reinterpret_cast<const __half2*>(vb + (size_t)(uA & 0xffffu) * 128));
        accx += wA.x * f.x; accy += wA.x * f.y;
        f = __half22float2(*reinterpret_cast<const __half2*>(vb + (size_t)(uA >> 16) * 128));
        accx += wA.y * f.x; accy += wA.y * f.y;
        f = __half22float2(*reinterpret_cast<const __half2*>(vb + (size_t)(uB & 0xffffu) * 128));
        accx += wB.x * f.x; accy += wB.x * f.y;
        f = __half22float2(*reinterpret_cast<const __half2*>(vb + (size_t)(uB >> 16) * 128));
        accx += wB.y * f.x; accy += wB.y * f.y;
    }
    accx += __shfl_xor_sync(0xffffffffu, accx, 16);
    accy += __shfl_xor_sync(0xffffffffu, accy, 16);
    if (lane < 16)
        out_pk[(size_t)nq * 128 + m * 16 + hl] = pack2h(accx, accy);
}

// -------------------- add + LayerNorm: warp per token --------------------
__global__ void add_ln_kernel(const float* __restrict__ a, const float* __restrict__ b,
                              const float* __restrict__ g, const float* __restrict__ beta,
                              float* __restrict__ out, uint32_t* __restrict__ out_pk, int scatter)
{
    const int wid  = threadIdx.x >> 5;
    const int lane = threadIdx.x & 31;
    const int t = blockIdx.x * 8 + wid;

    const float4* ap = reinterpret_cast<const float4*>(a + (size_t)t * DMODEL);
    const float4* bp = reinterpret_cast<const float4*>(b + (size_t)t * DMODEL);
    float4 v0, v1;
    {
        float4 x0 = ap[lane * 2],     y0 = bp[lane * 2];
        float4 x1 = ap[lane * 2 + 1], y1 = bp[lane * 2 + 1];
        v0.x = x0.x + y0.x; v0.y = x0.y + y0.y; v0.z = x0.z + y0.z; v0.w = x0.w + y0.w;
        v1.x = x1.x + y1.x; v1.y = x1.y + y1.y; v1.z = x1.z + y1.z; v1.w = x1.w + y1.w;
    }

    float s = v0.x + v0.y + v0.z + v0.w + v1.x + v1.y + v1.z + v1.w;
#pragma unroll
    for (int o = 16; o > 0; o >>= 1) s += __shfl_xor_sync(0xffffffffu, s, o);
    const float mean = s * (1.f / 256.f);

    float c0x = v0.x - mean, c0y = v0.y - mean, c0z = v0.z - mean, c0w = v0.w - mean;
    float c1x = v1.x - mean, c1y = v1.y - mean, c1z = v1.z - mean, c1w = v1.w - mean;
    float q = c0x*c0x + c0y*c0y + c0z*c0z + c0w*c0w + c1x*c1x + c1y*c1y + c1z*c1z + c1w*c1w;
#pragma unroll
    for (int o = 16; o > 0; o >>= 1) q += __shfl_xor_sync(0xffffffffu, q, o);
    const float rstd = rsqrtf(q * (1.f / 256.f) + 1e-5f);

    const float4* gp = reinterpret_cast<const float4*>(g);
    const float4* ep = reinterpret_cast<const float4*>(beta);
    float4 g0 = gp[lane * 2], g1 = gp[lane * 2 + 1];
    float4 e0 = ep[lane * 2], e1 = ep[lane * 2 + 1];

    float4 r0, r1;
    r0.x = g0.x * c0x * rstd + e0.x; r0.y = g0.y * c0y * rstd + e0.y;
    r0.z = g0.z * c0z * rstd + e0.z; r0.w = g0.w * c0w * rstd + e0.w;
    r1.x = g1.x * c1x * rstd + e1.x; r1.y = g1.y * c1y * rstd + e1.y;
    r1.z = g1.z * c1z * rstd + e1.z; r1.w = g1.w * c1w * rstd + e1.w;

    if (out_pk) {
        uint4 p;
        p.x = pack2h(r0.x, r0.y); p.y = pack2h(r0.z, r0.w);
        p.z = pack2h(r1.x, r1.y); p.w = pack2h(r1.z, r1.w);
        *reinterpret_cast<uint4*>(out_pk + (size_t)t * 128 + lane * 4) = p;
    }

    float* dst;
    if (!scatter) {
        dst = out + (size_t)t * DMODEL;
    } else {
        int n = t / LQ, i = t % LQ;
        if (i < LSP)
            dst = out + ((size_t)n * LSP + i) * DMODEL;
        else
            dst = out + ((size_t)N_BATCH * LSP + (size_t)N_BATCH * NALLVT) * DMODEL
                      + ((size_t)n * NVT + (i - LSP)) * DMODEL;
    }
    float4* dp = reinterpret_cast<float4*>(dst);
    dp[lane * 2]     = r0;
    dp[lane * 2 + 1] = r1;
}

// -------------------- launch --------------------
extern "C" void kernel_launch(void* const* d_in, const int* in_sizes, int n_in,
                              void* d_out, int out_size)
{
    const float* src  = (const float*)d_in[0];
    const float* pos  = (const float*)d_in[1];
    const float* ref  = (const float*)d_in[2];
    const unsigned char* mask = (const unsigned char*)d_in[5];
    const float* all_vt = (const float*)d_in[6];
    const float* sel_vt = (const float*)d_in[7];
    const float* Wv = (const float*)d_in[8];   const float* bv  = (const float*)d_in[9];
    const float* Wo = (const float*)d_in[10];  const float* bo  = (const float*)d_in[11];
    const float* Wa = (const float*)d_in[12];  const float* ba  = (const float*)d_in[13];
    const float* Wp = (const float*)d_in[14];  const float* bp  = (const float*)d_in[15];
    const float* g1 = (const float*)d_in[16];  const float* be1 = (const float*)d_in[17];
    const float* W1 = (const float*)d_in[18];  const float* bf1 = (const float*)d_in[19];
    const float* W2 = (const float*)d_in[20];  const float* bf2 = (const float*)d_in[21];
    const float* g2 = (const float*)d_in[22];  const float* be2 = (const float*)d_in[23];
    float* out = (float*)d_out;

    uint32_t *q_pk, *vin_pk, *value_pk, *samp_pk, *x_pk, *h_pk;
    uint32_t *Wv_pk, *Woa_pk, *Wp_pk, *W1_pk, *W2_pk;
    float *vin, *off, *attn, *src2, *x, *y, *bias_oa;
    cudaGetSymbolAddress((void**)&q_pk,    g_q_pk);
    cudaGetSymbolAddress((void**)&vin,     g_vin);
    cudaGetSymbolAddress((void**)&vin_pk,  g_vin_pk);
    cudaGetSymbolAddress((void**)&value_pk,g_value_pk);
    cudaGetSymbolAddress((void**)&off,     g_off);
    cudaGetSymbolAddress((void**)&attn,    g_attn);
    cudaGetSymbolAddress((void**)&samp_pk, g_samp_pk);
    cudaGetSymbolAddress((void**)&src2,    g_src2);
    cudaGetSymbolAddress((void**)&x,       g_x);
    cudaGetSymbolAddress((void**)&x_pk,    g_x_pk);
    cudaGetSymbolAddress((void**)&h_pk,    g_h_pk);
    cudaGetSymbolAddress((void**)&y,       g_y);
    cudaGetSymbolAddress((void**)&Wv_pk,   g_Wv_pk);
    cudaGetSymbolAddress((void**)&Woa_pk,  g_Woa_pk);
    cudaGetSymbolAddress((void**)&Wp_pk,   g_Wp_pk);
    cudaGetSymbolAddress((void**)&W1_pk,   g_W1_pk);
    cudaGetSymbolAddress((void**)&W2_pk,   g_W2_pk);
    cudaGetSymbolAddress((void**)&bias_oa, g_bias_oa);

    cudaFuncSetAttribute(gemm_pl,  cudaFuncAttributeMaxDynamicSharedMemorySize, SMEM_BYTES);
    cudaFuncSetAttribute(gemm_voa, cudaFuncAttributeMaxDynamicSharedMemorySize, SMEM_BYTES);

    const int T = TTOK;
    const int TM = (T + BM - 1) / BM;   // 171

    // 0) pack weights (+ concat bias_oa)
    pack_weights<<<(TOT_W + 384 + 255) / 256, 256>>>(Wv, Wo, Wa, Wp, W1, W2, bo, ba);

    // 1) build q / v_in
    build_qv_kernel<<<(TTOK * 128 + 255) / 256, 256>>>(src, pos, sel_vt, q_pk, vin, vin_pk);

    // 2+3) fused: value = vin@Wv^T+bv (masked, fp16) ; [off|attn] = q@[Wo;Wa]^T+[bo;ba]
    gemm_voa<<<dim3(TM, 5), 256, SMEM_BYTES>>>(vin_pk, Wv_pk, bv, value_pk, mask,
                                               q_pk, Woa_pk, bias_oa, off, attn, T);

    // 4) deformable sampling (softmax fused) -> fp16 packed samp
    msdeform_sample_kernel<<<TTOK, 256>>>(value_pk, attn, off, ref, samp_pk);

    // 5) src2 = samp @ Wp^T + bp
    gemm_pl<<<dim3(TM, 2), 256, SMEM_BYTES>>>(samp_pk, Wp_pk, bp, T, 128, 256,
                                              src2, 256, nullptr, nullptr, 0, nullptr);

    // 6) x = LN(vin + src2), also fp16 packed
    add_ln_kernel<<<TTOK / 8, 256>>>(vin, src2, g1, be1, x, x_pk, 0);

    // 7) h = relu(x @ W1^T + bf1) -> fp16 packed only
    gemm_pl<<<dim3(TM, 8), 256, SMEM_BYTES>>>(x_pk, W1_pk, bf1, T, 128, 1024,
                                              nullptr, 1024, nullptr, h_pk, 1, nullptr);
    // 8) y = h @ W2^T + bf2
    gemm_pl<<<dim3(TM, 2), 256, SMEM_BYTES>>>(h_pk, W2_pk, bf2, T, 512, 256,
                                              y, 256, nullptr, nullptr, 0, nullptr);

    // 9) out = LN(x + y) scattered into [spatial | all_vt | vt] layout
    add_ln_kernel<<<TTOK / 8, 256>>>(x, y, g2, be2, out, nullptr, 1);

    // 10) all_vt passthrough
    cudaMemcpyAsync(out + (size_t)N_BATCH * LSP * DMODEL, all_vt,
                    (size_t)N_BATCH * NALLVT * DMODEL * sizeof(float),
                    cudaMemcpyDeviceToDevice, 0);
}

// round 17
// speedup vs baseline: 3.2258x; 1.0494x over previous
#include <cuda_runtime.h>
#include <cuda_fp16.h>
#include <math.h>
#include <stdint.h>

#define N_BATCH 4
#define LQ      5448
#define LSP     5440
#define DMODEL  256
#define DFFN    1024
#define NVT     8
#define NALLVT  600
#define TTOK    (N_BATCH * LQ)   // 21792

// -------------------- scratch --------------------
__device__ uint32_t g_q_pk    [(size_t)TTOK * 128];
__device__ float    g_vin     [(size_t)TTOK * DMODEL];
__device__ uint32_t g_vin_pk  [(size_t)TTOK * 128];
__device__ uint32_t g_value_pk[(size_t)TTOK * 128];
__device__ float    g_off     [(size_t)TTOK * DMODEL];
__device__ float    g_attn    [(size_t)TTOK * 128];
__device__ uint32_t g_samp_pk [(size_t)TTOK * 128];
__device__ float    g_src2    [(size_t)TTOK * DMODEL];
__device__ float    g_x       [(size_t)TTOK * DMODEL];
__device__ uint32_t g_x_pk    [(size_t)TTOK * 128];
__device__ uint32_t g_h_pk    [(size_t)TTOK * 512];
__device__ float    g_y       [(size_t)TTOK * DMODEL];
// packed weights: single fp16 plane
__device__ uint32_t g_Wv_pk [256 * 128];
__device__ uint32_t g_Woa_pk[384 * 128];
__device__ uint32_t g_Wp_pk [256 * 128];
__device__ uint32_t g_W1_pk [1024 * 128];
__device__ uint32_t g_W2_pk [256 * 512];
__device__ float    g_bias_oa[384];

// ==================== helpers ====================
__device__ __forceinline__ uint32_t smem_u32(const void* p) {
    return (uint32_t)__cvta_generic_to_shared(p);
}
__device__ __forceinline__ void cp_async16(uint32_t dst, const void* src, int src_size) {
    asm volatile("cp.async.cg.shared.global [%0], [%1], 16, %2;\n"
                 :: "r"(dst), "l"(src), "r"(src_size));
}
__device__ __forceinline__ void cp_async_commit() {
    asm volatile("cp.async.commit_group;" ::: "memory");
}
template<int N> __device__ __forceinline__ void cp_async_wait() {
    asm volatile("cp.async.wait_group %0;" :: "n"(N) : "memory");
}
__device__ __forceinline__ void ldm_x4(uint32_t addr, uint32_t& r0, uint32_t& r1,
                                       uint32_t& r2, uint32_t& r3) {
    asm volatile("ldmatrix.sync.aligned.m8n8.x4.shared.b16 {%0,%1,%2,%3}, [%4];"
                 : "=r"(r0), "=r"(r1), "=r"(r2), "=r"(r3) : "r"(addr));
}
__device__ __forceinline__ void mma16(float* d, const uint32_t* a, const uint32_t* b) {
    asm volatile(
        "mma.sync.aligned.m16n8k16.row.col.f32.f16.f16.f32 "
        "{%0,%1,%2,%3}, {%4,%5,%6,%7}, {%8,%9}, {%0,%1,%2,%3};"
        : "+f"(d[0]), "+f"(d[1]), "+f"(d[2]), "+f"(d[3])
        : "r"(a[0]), "r"(a[1]), "r"(a[2]), "r"(a[3]), "r"(b[0]), "r"(b[1]));
}
__device__ __forceinline__ uint32_t pack2h(float vx, float vy) {
    __half2 h = __floats2half2_rn(vx, vy);
    return *reinterpret_cast<uint32_t*>(&h);
}

// ==================== fp16 GEMM body: CTA 128x128, 8 warps, warp 32x64 ====================
#define BM 128
#define BN 128
#define STR 20
#define APL 2560
#define BUFW 5120
#define STAGES 4
#define SMEM_BYTES (STAGES * BUFW * 4)

__device__ __forceinline__ void gemm_body(
    const uint32_t* __restrict__ A, const uint32_t* __restrict__ Wt,
    const float* __restrict__ bias, int T, int KW, int Nout, int bm, int bn,
    float* __restrict__ outA, int split, float* __restrict__ outB,
    uint32_t* __restrict__ outPk, int relu, const unsigned char* __restrict__ mask,
    uint32_t sm)
{
    const int tid  = threadIdx.x;
    const int wid  = tid >> 5;
    const int lane = tid & 31;
    const int mbase = (wid & 3) * 32;
    const int nbase = (wid >> 2) * 64;
    const int gq = lane >> 2;
    const int tg = lane & 3;

    float acc[2][8][4];
#pragma unroll
    for (int mi = 0; mi < 2; mi++)
#pragma unroll
        for (int ni = 0; ni < 8; ni++)
#pragma unroll
            for (int r = 0; r < 4; r++) acc[mi][ni][r] = 0.f;

    auto load = [&](int kw0, int buf) {
        const uint32_t base = sm + buf * (BUFW * 4);
#pragma unroll
        for (int j = 0; j < 4; j++) {
            int o = tid + 256 * j;
            if (o < 512) {
                int row = o >> 2, ch = o & 3;
                int gr = bm + row;
                const uint32_t* srcp = A + (size_t)(gr < T ? gr : 0) * KW + kw0 + ch * 4;
                cp_async16(base + (row * STR + ch * 4) * 4, srcp, gr < T ? 16 : 0);
            } else {
                int oo = o - 512;
                int row = oo >> 2, ch = oo & 3;
                const uint32_t* srcp = Wt + (size_t)(bn + row) * KW + kw0 + ch * 4;
                cp_async16(base + (APL + row * STR + ch * 4) * 4, srcp, 16);
            }
        }
        cp_async_commit();
    };

    const int nch = KW >> 4;
    load(0, 0);
    load(16, 1);
    load(32, 2);

    const int arow = lane & 15;
    const int acol = (lane >> 4) * 4;
    const int brow = (lane & 7) + ((lane >> 4) & 1) * 8;
    const int bcol = ((lane >> 3) & 1) * 4;

    for (int i = 0; i < nch; i++) {
        cp_async_wait<2>();
        __syncthreads();
        if (i + 3 < nch) load((i + 3) << 4, (i + 3) & 3);
        else cp_async_commit();

        const uint32_t base = sm + (i & 3) * (BUFW * 4);
        const uint32_t Aw = base;
        const uint32_t Bw = base + APL * 4;

#pragma unroll
        for (int k16 = 0; k16 < 2; k16++) {
            const int kw = k16 * 8;
            uint32_t ah[2][4];
#pragma unroll
            for (int mi = 0; mi < 2; mi++) {
                uint32_t off = ((mbase + mi * 16 + arow) * STR + kw + acol) * 4;
                ldm_x4(Aw + off, ah[mi][0], ah[mi][1], ah[mi][2], ah[mi][3]);
            }
            uint32_t bh[8][2];
#pragma unroll
            for (int hb = 0; hb < 4; hb++) {
                uint32_t off = ((nbase + hb * 16 + brow) * STR + kw + bcol) * 4;
                ldm_x4(Bw + off, bh[hb*2][0], bh[hb*2][1], bh[hb*2+1][0], bh[hb*2+1][1]);
            }
#pragma unroll
            for (int mi = 0; mi < 2; mi++)
#pragma unroll
                for (int ng = 0; ng < 8; ng++)
                    mma16(acc[mi][ng], ah[mi], bh[ng]);
        }
        __syncthreads();
    }

    const int wB = Nout - split;
    const int KWout = Nout >> 1;
#pragma unroll
    for (int mi = 0; mi < 2; mi++) {
#pragma unroll
        for (int half = 0; half < 2; half++) {
            int row = bm + mbase + mi * 16 + gq + half * 8;
            if (row >= T) continue;
            bool zero = (mask != nullptr) && (mask[row] != 0);
#pragma unroll
            for (int ni = 0; ni < 8; ni++) {
                int gc = bn + nbase + ni * 8 + tg * 2;
                float vx = acc[mi][ni][half * 2 + 0] + bias[gc];
                float vy = acc[mi][ni][half * 2 + 1] + bias[gc + 1];
                if (relu) { vx = fmaxf(vx, 0.f); vy = fmaxf(vy, 0.f); }
                if (zero) { vx = 0.f; vy = 0.f; }
                if (outPk)
                    outPk[(size_t)row * KWout + (gc >> 1)] = pack2h(vx, vy);
                if (outA) {
                    if (gc < split) {
                        float2 v; v.x = vx; v.y = vy;
                        *reinterpret_cast<float2*>(outA + (size_t)row * split + gc) = v;
                    } else if (outB) {
                        float2 v; v.x = vx; v.y = vy;
                        *reinterpret_cast<float2*>(outB + (size_t)row * wB + (gc - split)) = v;
                    }
                }
            }
        }
    }
}

__global__ void __launch_bounds__(256, 2)
gemm_pl(const uint32_t* __restrict__ A, const uint32_t* __restrict__ Wt,
        const float* __restrict__ bias, int T, int KW, int Nout,
        float* __restrict__ outA, int split, float* __restrict__ outB,
        uint32_t* __restrict__ outPk, int relu, const unsigned char* __restrict__ mask)
{
    extern __shared__ __align__(16) uint32_t smem[];
    gemm_body(A, Wt, bias, T, KW, Nout, blockIdx.x * BM, blockIdx.y * BN,
              outA, split, outB, outPk, relu, mask, smem_u32(smem));
}

__global__ void __launch_bounds__(256, 2)
gemm_voa(const uint32_t* __restrict__ vin_pk, const uint32_t* __restrict__ Wv,
         const float* __restrict__ bv, uint32_t* __restrict__ value_pk,
         const unsigned char* __restrict__ mask,
         const uint32_t* __restrict__ q_pk, const uint32_t* __restrict__ Woa,
         const float* __restrict__ bias_oa, float* __restrict__ off,
         float* __restrict__ attn, int T)
{
    extern __shared__ __align__(16) uint32_t smem[];
    const int y = blockIdx.y;
    const bool isv = (y < 2);
    gemm_body(isv ? vin_pk : q_pk,
              isv ? Wv : Woa,
              isv ? bv : bias_oa,
              T, 128,
              isv ? 256 : 384,
              blockIdx.x * BM,
              (isv ? y : (y - 2)) * BN,
              isv ? nullptr : off, 256,
              isv ? nullptr : attn,
              isv ? value_pk : nullptr,
              0,
              isv ? mask : nullptr,
              smem_u32(smem));
}

// -------------------- weight packing --------------------
#define WV_W  32768
#define WO_W  32768
#define WA_W  16384
#define WP_W  32768
#define W1_W  131072
#define W2_W  131072
#define TOT_W (WV_W + WO_W + WA_W + WP_W + W1_W + W2_W)

__global__ void pack_weights(const float* __restrict__ Wv, const float* __restrict__ Wo,
                             const float* __restrict__ Wa, const float* __restrict__ Wp,
                             const float* __restrict__ W1, const float* __restrict__ W2,
                             const float* __restrict__ bo, const float* __restrict__ ba)
{
    int i = blockIdx.x * 256 + threadIdx.x;
    if (i < TOT_W) {
        const float* srcm; uint32_t* dst; int w;
        if (i < WV_W)                      { srcm = Wv; dst = g_Wv_pk;  w = i; }
        else if (i < WV_W + WO_W)          { srcm = Wo; dst = g_Woa_pk; w = i - WV_W; }
        else if (i < WV_W + WO_W + WA_W)   { srcm = Wa; dst = g_Woa_pk + WO_W; w = i - WV_W - WO_W; }
        else if (i < WV_W + WO_W + WA_W + WP_W)
                                           { srcm = Wp; dst = g_Wp_pk;  w = i - WV_W - WO_W - WA_W; }
        else if (i < TOT_W - W2_W)         { srcm = W1; dst = g_W1_pk;  w = i - (WV_W+WO_W+WA_W+WP_W); }
        else                               { srcm = W2; dst = g_W2_pk;  w = i - (TOT_W - W2_W); }
        float2 v = *reinterpret_cast<const float2*>(srcm + 2 * (size_t)w);
        dst[w] = pack2h(v.x, v.y);
    } else if (i < TOT_W + 256) {
        g_bias_oa[i - TOT_W] = bo[i - TOT_W];
    } else if (i < TOT_W + 384) {
        g_bias_oa[i - TOT_W] = ba[i - TOT_W - 256];
    }
}

// -------------------- build q / v_in --------------------
__global__ void build_qv_kernel(const float* __restrict__ src, const float* __restrict__ pos,
                                const float* __restrict__ sel,
                                uint32_t* __restrict__ q_pk,
                                float* __restrict__ vin, uint32_t* __restrict__ vin_pk)
{
    size_t gid = (size_t)blockIdx.x * 256 + threadIdx.x;
    if (gid >= (size_t)TTOK * 128) return;
    int dw = (int)(gid & 127);
    size_t t = gid >> 7;
    int n = (int)(t / LQ);
    int i = (int)(t % LQ);
    float2 sv, pv;
    if (i < LSP) {
        size_t si = ((size_t)n * LSP + i) * DMODEL + dw * 2;
        sv = *reinterpret_cast<const float2*>(src + si);
        pv = *reinterpret_cast<const float2*>(pos + si);
    } else {
        size_t si = ((size_t)n * NVT + (i - LSP)) * DMODEL + dw * 2;
        sv = *reinterpret_cast<const float2*>(sel + si);
        pv.x = 0.f; pv.y = 0.f;
    }
    q_pk[gid]   = pack2h(sv.x + pv.x, sv.y + pv.y);
    vin_pk[gid] = pack2h(sv.x, sv.y);
    *reinterpret_cast<float2*>(vin + 2 * gid) = sv;
}

// -------------------- deformable sampling: 2-phase, quarter-warp gathers --------------------
__global__ void msdeform_sample_kernel(const uint32_t* __restrict__ value_pk,
                                       const float* __restrict__ logits,
                                       const float* __restrict__ off,
                                       const float* __restrict__ ref,
                                       uint32_t* __restrict__ out_pk)
{
    const int nq   = blockIdx.x;
    const int n    = nq / LQ;
    const int m    = threadIdx.x >> 5;
    const int lane = threadIdx.x & 31;
    const int ql   = lane & 7;     // channel group (4 channels)
    const int qf   = lane >> 3;    // quarter id 0..3

    // softmax over 16 logits (lane s < 16 holds weight for sample s)
    const float* lg = logits + (size_t)nq * 128 + m * 16;
    float v = (lane < 16) ? lg[lane] : -1e30f;
    float mx = v;
#pragma unroll
    for (int o = 16; o > 0; o >>= 1) mx = fmaxf(mx, __shfl_xor_sync(0xffffffffu, mx, o));
    float e = (lane < 16) ? __expf(v - mx) : 0.f;
    float sm = e;
#pragma unroll
    for (int o = 16; o > 0; o >>= 1) sm += __shfl_xor_sync(0xffffffffu, sm, o);
    float wgt = e / sm;

    float offv = off[(size_t)nq * DMODEL + m * 32 + lane];
    float refv = (lane < 8) ? ref[(size_t)nq * 8 + lane] : 0.f;

    const int HH[4] = {64, 32, 16, 8};
    const int ST[4] = {0, 4096, 5120, 5376};

    // ---- phase 1: lane s computes indices + ws-premultiplied weights for sample s ----
    const int l_  = (lane >> 2) & 3;
    float dx = __shfl_sync(0xffffffffu, offv, (2 * lane) & 31);
    float dy = __shfl_sync(0xffffffffu, offv, (2 * lane + 1) & 31);
    float rx = __shfl_sync(0xffffffffu, refv, 2 * l_);
    float ry = __shfl_sync(0xffffffffu, refv, 2 * l_ + 1);
    const int Wd = HH[l_], st_ = ST[l_];

    float x = rx * (float)Wd + dx - 0.5f;
    float y = ry * (float)Wd + dy - 0.5f;
    float xf = floorf(x), yf = floorf(y);
    int x0 = (int)xf, y0 = (int)yf;
    float wx = x - xf, wy = y - yf;

    bool vx0 = (x0 >= 0) && (x0 < Wd);
    bool vx1 = (x0 + 1 >= 0) && (x0 + 1 < Wd);
    bool vy0 = (y0 >= 0) && (y0 < Wd);
    bool vy1 = (y0 + 1 >= 0) && (y0 + 1 < Wd);

    float w00 = (vx0 && vy0) ? wgt * (1.f - wx) * (1.f - wy) : 0.f;
    float w10 = (vx1 && vy0) ? wgt * wx * (1.f - wy) : 0.f;
    float w01 = (vx0 && vy1) ? wgt * (1.f - wx) * wy : 0.f;
    float w11 = (vx1 && vy1) ? wgt * wx * wy : 0.f;

    int base = st_ + y0 * Wd + x0;
    uint32_t c00 = (vx0 && vy0) ? (uint32_t)base : 0u;
    uint32_t c10 = (vx1 && vy0) ? (uint32_t)(base + 1) : 0u;
    uint32_t c01 = (vx0 && vy1) ? (uint32_t)(base + Wd) : 0u;
    uint32_t c11 = (vx1 && vy1) ? (uint32_t)(base + Wd + 1) : 0u;

    uint32_t idxA = c00 | (c10 << 16);
    uint32_t idxB = c01 | (c11 << 16);
    uint32_t wpkA = pack2h(w00, w10);
    uint32_t wpkB = pack2h(w01, w11);

    // ---- phase 2: quarter-warp qf handles sample 4*it+qf; 8 lanes x 4 channels ----
    const uint32_t* vb = value_pk + (size_t)n * LQ * 128 + m * 16 + ql * 2;

    float a0 = 0.f, a1 = 0.f, a2 = 0.f, a3 = 0.f;
#pragma unroll
    for (int it = 0; it < 4; it++) {
        int srcl = 4 * it + qf;
        uint32_t uA = __shfl_sync(0xffffffffu, idxA, srcl);
        uint32_t uB = __shfl_sync(0xffffffffu, idxB, srcl);
        uint32_t pA = __shfl_sync(0xffffffffu, wpkA, srcl);
        uint32_t pB = __shfl_sync(0xffffffffu, wpkB, srcl);
        float2 wA = __half22float2(*reinterpret_cast<__half2*>(&pA));
        float2 wB = __half22float2(*reinterpret_cast<__half2*>(&pB));

        uint2 f;
        float2 f0, f1;
        f = *reinterpret_cast<const uint2*>(vb + (size_t)(uA & 0xffffu) * 128);
        f0 = __half22float2(*reinterpret_cast<__half2*>(&f.x));
        f1 = __half22float2(*reinterpret_cast<__half2*>(&f.y));
        a0 += wA.x * f0.x; a1 += wA.x * f0.y; a2 += wA.x * f1.x; a3 += wA.x * f1.y;

        f = *reinterpret_cast<const uint2*>(vb + (size_t)(uA >> 16) * 128);
        f0 = __half22float2(*reinterpret_cast<__half2*>(&f.x));
        f1 = __half22float2(*reinterpret_cast<__half2*>(&f.y));
        a0 += wA.y * f0.x; a1 += wA.y * f0.y; a2 += wA.y * f1.x; a3 += wA.y * f1.y;

        f = *reinterpret_cast<const uint2*>(vb + (size_t)(uB & 0xffffu) * 128);
        f0 = __half22float2(*reinterpret_cast<__half2*>(&f.x));
        f1 = __half22float2(*reinterpret_cast<__half2*>(&f.y));
        a0 += wB.x * f0.x; a1 += wB.x * f0.y; a2 += wB.x * f1.x; a3 += wB.x * f1.y;

        f = *reinterpret_cast<const uint2*>(vb + (size_t)(uB >> 16) * 128);
        f0 = __half22float2(*reinterpret_cast<__half2*>(&f.x));
        f1 = __half22float2(*reinterpret_cast<__half2*>(&f.y));
        a0 += wB.y * f0.x; a1 += wB.y * f0.y; a2 += wB.y * f1.x; a3 += wB.y * f1.y;
    }
    // reduce across the 4 quarter-warps
#pragma unroll
    for (int o = 8; o <= 16; o <<= 1) {
        a0 += __shfl_xor_sync(0xffffffffu, a0, o);
        a1 += __shfl_xor_sync(0xffffffffu, a1, o);
        a2 += __shfl_xor_sync(0xffffffffu, a2, o);
        a3 += __shfl_xor_sync(0xffffffffu, a3, o);
    }
    if (lane < 8) {
        uint2 p;
        p.x = pack2h(a0, a1);
        p.y = pack2h(a2, a3);
        *reinterpret_cast<uint2*>(out_pk + (size_t)nq * 128 + m * 16 + ql * 2) = p;
    }
}

// -------------------- add + LayerNorm: warp per token --------------------
__global__ void add_ln_kernel(const float* __restrict__ a, const float* __restrict__ b,
                              const float* __restrict__ g, const float* __restrict__ beta,
                              float* __restrict__ out, uint32_t* __restrict__ out_pk, int scatter)
{
    const int wid  = threadIdx.x >> 5;
    const int lane = threadIdx.x & 31;
    const int t = blockIdx.x * 8 + wid;

    const float4* ap = reinterpret_cast<const float4*>(a + (size_t)t * DMODEL);
    const float4* bp = reinterpret_cast<const float4*>(b + (size_t)t * DMODEL);
    float4 v0, v1;
    {
        float4 x0 = ap[lane * 2],     y0 = bp[lane * 2];
        float4 x1 = ap[lane * 2 + 1], y1 = bp[lane * 2 + 1];
        v0.x = x0.x + y0.x; v0.y = x0.y + y0.y; v0.z = x0.z + y0.z; v0.w = x0.w + y0.w;
        v1.x = x1.x + y1.x; v1.y = x1.y + y1.y; v1.z = x1.z + y1.z; v1.w = x1.w + y1.w;
    }

    float s = v0.x + v0.y + v0.z + v0.w + v1.x + v1.y + v1.z + v1.w;
#pragma unroll
    for (int o = 16; o > 0; o >>= 1) s += __shfl_xor_sync(0xffffffffu, s, o);
    const float mean = s * (1.f / 256.f);

    float c0x = v0.x - mean, c0y = v0.y - mean, c0z = v0.z - mean, c0w = v0.w - mean;
    float c1x = v1.x - mean, c1y = v1.y - mean, c1z = v1.z - mean, c1w = v1.w - mean;
    float q = c0x*c0x + c0y*c0y + c0z*c0z + c0w*c0w + c1x*c1x + c1y*c1y + c1z*c1z + c1w*c1w;
#pragma unroll
    for (int o = 16; o > 0; o >>= 1) q += __shfl_xor_sync(0xffffffffu, q, o);
    const float rstd = rsqrtf(q * (1.f / 256.f) + 1e-5f);

    const float4* gp = reinterpret_cast<const float4*>(g);
    const float4* ep = reinterpret_cast<const float4*>(beta);
    float4 g0 = gp[lane * 2], g1 = gp[lane * 2 + 1];
    float4 e0 = ep[lane * 2], e1 = ep[lane * 2 + 1];

    float4 r0, r1;
    r0.x = g0.x * c0x * rstd + e0.x; r0.y = g0.y * c0y * rstd + e0.y;
    r0.z = g0.z * c0z * rstd + e0.z; r0.w = g0.w * c0w * rstd + e0.w;
    r1.x = g1.x * c1x * rstd + e1.x; r1.y = g1.y * c1y * rstd + e1.y;
    r1.z = g1.z * c1z * rstd + e1.z; r1.w = g1.w * c1w * rstd + e1.w;

    if (out_pk) {
        uint4 p;
        p.x = pack2h(r0.x, r0.y); p.y = pack2h(r0.z, r0.w);
        p.z = pack2h(r1.x, r1.y); p.w = pack2h(r1.z, r1.w);
        *reinterpret_cast<uint4*>(out_pk + (size_t)t * 128 + lane * 4) = p;
    }

    float* dst;
    if (!scatter) {
        dst = out + (size_t)t * DMODEL;
    } else {
        int n = t / LQ, i = t % LQ;
        if (i < LSP)
            dst = out + ((size_t)n * LSP + i) * DMODEL;
        else
            dst = out + ((size_t)N_BATCH * LSP + (size_t)N_BATCH * NALLVT) * DMODEL
                      + ((size_t)n * NVT + (i - LSP)) * DMODEL;
    }
    float4* dp = reinterpret_cast<float4*>(dst);
    dp[lane * 2]     = r0;
    dp[lane * 2 + 1] = r1;
}

// -------------------- launch --------------------
extern "C" void kernel_launch(void* const* d_in, const int* in_sizes, int n_in,
                              void* d_out, int out_size)
{
    const float* src  = (const float*)d_in[0];
    const float* pos  = (const float*)d_in[1];
    const float* ref  = (const float*)d_in[2];
    const unsigned char* mask = (const unsigned char*)d_in[5];
    const float* all_vt = (const float*)d_in[6];
    const float* sel_vt = (const float*)d_in[7];
    const float* Wv = (const float*)d_in[8];   const float* bv  = (const float*)d_in[9];
    const float* Wo = (const float*)d_in[10];  const float* bo  = (const float*)d_in[11];
    const float* Wa = (const float*)d_in[12];  const float* ba  = (const float*)d_in[13];
    const float* Wp = (const float*)d_in[14];  const float* bp  = (const float*)d_in[15];
    const float* g1 = (const float*)d_in[16];  const float* be1 = (const float*)d_in[17];
    const float* W1 = (const float*)d_in[18];  const float* bf1 = (const float*)d_in[19];
    const float* W2 = (const float*)d_in[20];  const float* bf2 = (const float*)d_in[21];
    const float* g2 = (const float*)d_in[22];  const float* be2 = (const float*)d_in[23];
    float* out = (float*)d_out;

    uint32_t *q_pk, *vin_pk, *value_pk, *samp_pk, *x_pk, *h_pk;
    uint32_t *Wv_pk, *Woa_pk, *Wp_pk, *W1_pk, *W2_pk;
    float *vin, *off, *attn, *src2, *x, *y, *bias_oa;
    cudaGetSymbolAddress((void**)&q_pk,    g_q_pk);
    cudaGetSymbolAddress((void**)&vin,     g_vin);
    cudaGetSymbolAddress((void**)&vin_pk,  g_vin_pk);
    cudaGetSymbolAddress((void**)&value_pk,g_value_pk);
    cudaGetSymbolAddress((void**)&off,     g_off);
    cudaGetSymbolAddress((void**)&attn,    g_attn);
    cudaGetSymbolAddress((void**)&samp_pk, g_samp_pk);
    cudaGetSymbolAddress((void**)&src2,    g_src2);
    cudaGetSymbolAddress((void**)&x,       g_x);
    cudaGetSymbolAddress((void**)&x_pk,    g_x_pk);
    cudaGetSymbolAddress((void**)&h_pk,    g_h_pk);
    cudaGetSymbolAddress((void**)&y,       g_y);
    cudaGetSymbolAddress((void**)&Wv_pk,   g_Wv_pk);
    cudaGetSymbolAddress((void**)&Woa_pk,  g_Woa_pk);
    cudaGetSymbolAddress((void**)&Wp_pk,   g_Wp_pk);
    cudaGetSymbolAddress((void**)&W1_pk,   g_W1_pk);
    cudaGetSymbolAddress((void**)&W2_pk,   g_W2_pk);
    cudaGetSymbolAddress((void**)&bias_oa, g_bias_oa);

    cudaFuncSetAttribute(gemm_pl,  cudaFuncAttributeMaxDynamicSharedMemorySize, SMEM_BYTES);
    cudaFuncSetAttribute(gemm_voa, cudaFuncAttributeMaxDynamicSharedMemorySize, SMEM_BYTES);

    const int T = TTOK;
    const int TM = (T + BM - 1) / BM;   // 171

    // 0) pack weights (+ concat bias_oa)
    pack_weights<<<(TOT_W + 384 + 255) / 256, 256>>>(Wv, Wo, Wa, Wp, W1, W2, bo, ba);

    // 1) build q / v_in
    build_qv_kernel<<<(TTOK * 128 + 255) / 256, 256>>>(src, pos, sel_vt, q_pk, vin, vin_pk);

    // 2+3) fused: value = vin@Wv^T+bv (masked, fp16) ; [off|attn] = q@[Wo;Wa]^T+[bo;ba]
    gemm_voa<<<dim3(TM, 5), 256, SMEM_BYTES>>>(vin_pk, Wv_pk, bv, value_pk, mask,
                                               q_pk, Woa_pk, bias_oa, off, attn, T);

    // 4) deformable sampling (softmax fused) -> fp16 packed samp
    msdeform_sample_kernel<<<TTOK, 256>>>(value_pk, attn, off, ref, samp_pk);

    // 5) src2 = samp @ Wp^T + bp
    gemm_pl<<<dim3(TM, 2), 256, SMEM_BYTES>>>(samp_pk, Wp_pk, bp, T, 128, 256,
                                              src2, 256, nullptr, nullptr, 0, nullptr);

    // 6) x = LN(vin + src2), also fp16 packed
    add_ln_kernel<<<TTOK / 8, 256>>>(vin, src2, g1, be1, x, x_pk, 0);

    // 7) h = relu(x @ W1^T + bf1) -> fp16 packed only
    gemm_pl<<<dim3(TM, 8), 256, SMEM_BYTES>>>(x_pk, W1_pk, bf1, T, 128, 1024,
                                              nullptr, 1024, nullptr, h_pk, 1, nullptr);
    // 8) y = h @ W2^T + bf2
    gemm_pl<<<dim3(TM, 2), 256, SMEM_BYTES>>>(h_pk, W2_pk, bf2, T, 512, 256,
                                              y, 256, nullptr, nullptr, 0, nullptr);

    // 9) out = LN(x + y) scattered into [spatial | all_vt | vt] layout
    add_ln_kernel<<<TTOK / 8, 256>>>(x, y, g2, be2, out, nullptr, 1);

    // 10) all_vt passthrough
    cudaMemcpyAsync(out + (size_t)N_BATCH * LSP * DMODEL, all_vt,
                    (size_t)N_BATCH * NALLVT * DMODEL * sizeof(float),
                    cudaMemcpyDeviceToDevice, 0);
}